// round 1
// baseline (speedup 1.0000x reference)
#include <cuda_runtime.h>
#include <math.h>
#include <stdint.h>

#define BB 8
#define CC 192
#define HH 64
#define WW 64
#define NN 4096
#define C4 48
#define CD 194
#define C8 24
#define NKEEP 2048

// ---------------- scratch (device globals; no allocation) ----------------
__device__ float g_f[BB*C4*NN];
__device__ float g_off[BB*2*NN];
__device__ float g_score[BB*NN];
__device__ int   g_keep[BB*NKEEP];
__device__ int   g_pos[BB*NN];
__device__ float g_fmean[BB*C4];
__device__ float g_ca[BB*CC];
__device__ float g_sa[BB*NN];
__device__ int   g_widx[BB*NN*4];
__device__ float g_wwt[BB*NN*4];
__device__ float g_v[BB*CC*NN];
__device__ float g_kimg[BB*CC*NN];
__device__ float g_q1[BB*CC*NKEEP];
__device__ float g_k1[BB*CC*NKEEP];
__device__ float g_v1[BB*NKEEP*CC];
__device__ float g_P[(size_t)BB*NKEEP*NKEEP];
__device__ float g_fattn[BB*CC*NKEEP];
__device__ float g_otok[BB*CC*NN];
__device__ float g_out2[BB*CC*NN];

// ---------------- front end: f = lrelu(LN(conv1x1(cond))), offsets, score --
__global__ void k_front(const float* __restrict__ x,
    const float* __restrict__ in_w, const float* __restrict__ in_b,
    const float* __restrict__ ln_w, const float* __restrict__ ln_b,
    const float* __restrict__ ow1, const float* __restrict__ ob1,
    const float* __restrict__ ow2, const float* __restrict__ ob2,
    const float* __restrict__ mw1, const float* __restrict__ mb1,
    const float* __restrict__ mw2, const float* __restrict__ mb2)
{
    __shared__ float cond[CD][33];
    __shared__ float fb[C4][33];
    __shared__ float mu_s[32], rs_s[32];
    __shared__ float hb[C8][33];
    int b = blockIdx.y;
    int n0 = blockIdx.x * 32;
    int tid = threadIdx.x;

    for (int l = tid; l < CC*32; l += 256) {
        int c = l >> 5, px = l & 31;
        cond[c][px] = x[((b*CC + c) << 12) + n0 + px];
    }
    if (tid < 32) {
        int n = n0 + tid;
        int h = n >> 6, w = n & 63;
        cond[192][tid] = -1.0f + 2.0f * (float)w / 63.0f;  // gx
        cond[193][tid] = -1.0f + 2.0f * (float)h / 63.0f;  // gy
    }
    __syncthreads();

    int px = tid & 31;
    for (int pass = 0; pass < 6; pass++) {
        int c = pass*8 + (tid >> 5);
        float acc = in_b[c];
        const float* wr = in_w + c*CD;
        #pragma unroll 2
        for (int k = 0; k < CD; k++) acc += wr[k] * cond[k][px];
        fb[c][px] = acc;
    }
    __syncthreads();

    if (tid < 32) {
        float s = 0.f, s2 = 0.f;
        for (int c = 0; c < C4; c++) { float v = fb[c][tid]; s += v; s2 += v*v; }
        float mu = s / (float)C4;
        float var = s2 / (float)C4 - mu*mu;
        mu_s[tid] = mu;
        rs_s[tid] = rsqrtf(var + 1e-6f);
    }
    __syncthreads();

    for (int l = tid; l < C4*32; l += 256) {
        int c = l >> 5, p = l & 31;
        float v = (fb[c][p] - mu_s[p]) * rs_s[p] * ln_w[c] + ln_b[c];
        v = v > 0.f ? v : 0.1f*v;
        fb[c][p] = v;
        g_f[(b*C4 + c)*NN + n0 + p] = v;
    }
    __syncthreads();

    for (int l = tid; l < C8*32; l += 256) {
        int j = l >> 5, p = l & 31;
        float acc = ob1[j];
        const float* wr = ow1 + j*C4;
        #pragma unroll 4
        for (int c = 0; c < C4; c++) acc += wr[c] * fb[c][p];
        hb[j][p] = acc > 0.f ? acc : 0.1f*acc;
    }
    __syncthreads();

    if (tid < 64) {
        int d = tid >> 5, p = tid & 31;
        float acc = ob2[d];
        const float* wr = ow2 + d*C8;
        #pragma unroll
        for (int j = 0; j < C8; j++) acc += wr[j] * hb[j][p];
        g_off[(b*2 + d)*NN + n0 + p] = tanhf(acc) * 8.0f;
    }
    if (tid >= 64 && tid < 96) {
        int p = tid - 64;
        float s = 0.f;
        for (int c = 0; c < C4; c++) s += fb[c][p];
        float t = s / (float)C4;
        float s1 = t * mw1[0] + mb1[0];
        s1 = s1 > 0.f ? s1 : 0.1f*s1;
        float l0 = s1 * mw2[0] + mb2[0];
        float l1 = s1 * mw2[1] + mb2[1];
        g_score[b*NN + n0 + p] = 1.0f / (1.0f + expf(l1 - l0));
    }
}

// ---------------- f mean over (H,W) per (b,c) ----------------
__global__ void k_fmean() {
    int bc = blockIdx.x;
    const float* p = g_f + bc*NN;
    float s = 0.f;
    for (int i = threadIdx.x; i < NN; i += 256) s += p[i];
    __shared__ float red[256];
    red[threadIdx.x] = s; __syncthreads();
    for (int o = 128; o > 0; o >>= 1) {
        if (threadIdx.x < o) red[threadIdx.x] += red[threadIdx.x + o];
        __syncthreads();
    }
    if (threadIdx.x == 0) g_fmean[bc] = red[0] / (float)NN;
}

// ---------------- ca = sigmoid(p_ca_w @ fmean + b) ----------------
__global__ void k_ca(const float* __restrict__ caw, const float* __restrict__ cab) {
    int l = blockIdx.x*256 + threadIdx.x;
    if (l >= BB*CC) return;
    int b = l / CC, co = l % CC;
    float acc = cab[co];
    #pragma unroll 4
    for (int c = 0; c < C4; c++) acc += caw[co*C4 + c] * g_fmean[b*C4 + c];
    g_ca[l] = 1.0f / (1.0f + expf(-acc));
}

// ---------------- sa = sigmoid(conv3x3(f)) ----------------
__global__ void k_sa(const float* __restrict__ saw, const float* __restrict__ sab) {
    __shared__ float wsh[C4*9];
    int tid = threadIdx.x;
    for (int l = tid; l < C4*9; l += 256) wsh[l] = saw[l];
    __syncthreads();
    int b = blockIdx.y;
    int n = blockIdx.x*256 + tid;
    int h = n >> 6, w = n & 63;
    float acc = sab[0];
    const float* fb_ = g_f + b*C4*NN;
    for (int c = 0; c < C4; c++) {
        const float* fr = fb_ + c*NN;
        #pragma unroll
        for (int dh = 0; dh < 3; dh++) {
            int hh = h + dh - 1;
            if (hh < 0 || hh >= HH) continue;
            #pragma unroll
            for (int dw = 0; dw < 3; dw++) {
                int ww = w + dw - 1;
                if (ww < 0 || ww >= WW) continue;
                acc += wsh[c*9 + dh*3 + dw] * fr[hh*WW + ww];
            }
        }
    }
    g_sa[b*NN + n] = 1.0f / (1.0f + expf(-acc));
}

// ---------------- top-k by bitonic sort (set semantics) ----------------
__device__ __forceinline__ unsigned int ford(float f) {
    unsigned int u = __float_as_uint(f);
    return (u & 0x80000000u) ? ~u : (u | 0x80000000u);
}
__global__ void k_topk() {
    __shared__ unsigned long long keys[NN];
    int b = blockIdx.x, tid = threadIdx.x;
    for (int l = tid; l < NN; l += 1024) {
        unsigned int o = ford(g_score[b*NN + l]) ^ 0xFFFFFFFFu;  // descending score
        keys[l] = ((unsigned long long)o << 32) | (unsigned int)l;
    }
    __syncthreads();
    for (int kk = 2; kk <= NN; kk <<= 1) {
        for (int j = kk >> 1; j > 0; j >>= 1) {
            for (int t = tid; t < NN/2; t += 1024) {
                int i = 2*t - (t & (j-1));
                int l = i + j;
                bool up = ((i & kk) == 0);
                unsigned long long a = keys[i], c = keys[l];
                if ((a > c) == up) { keys[i] = c; keys[l] = a; }
            }
            __syncthreads();
        }
    }
    for (int l = tid; l < NN; l += 1024) {
        int tok = (int)(keys[l] & 0xFFFFFFFFu);
        if (l < NKEEP) { g_keep[b*NKEEP + l] = tok; g_pos[b*NN + tok] = l; }
        else g_pos[b*NN + tok] = -1;
    }
}

// ---------------- flow-warp precompute (corners + weights) ----------------
__global__ void k_wprep() {
    int l = blockIdx.x*256 + threadIdx.x;  // b*NN + n
    if (l >= BB*NN) return;
    int n = l & (NN - 1);
    int b = l >> 12;
    int h = n >> 6, w = n & 63;
    float sx = (float)w + g_off[(b*2 + 0)*NN + n];
    float sy = (float)h + g_off[(b*2 + 1)*NN + n];
    float x0 = floorf(sx), y0 = floorf(sy);
    float wx = sx - x0, wy = sy - y0;
    #pragma unroll
    for (int r = 0; r < 4; r++) {
        float xi = x0 + (float)(r & 1);
        float yi = y0 + (float)(r >> 1);
        bool valid = (xi >= 0.f) && (xi <= (float)(WW-1)) && (yi >= 0.f) && (yi <= (float)(HH-1));
        int xc = (int)fminf(fmaxf(xi, 0.f), (float)(WW-1));
        int yc = (int)fminf(fmaxf(yi, 0.f), (float)(HH-1));
        float wt = ((r & 1) ? wx : 1.f - wx) * ((r >> 1) ? wy : 1.f - wy);
        g_widx[l*4 + r] = yc*WW + xc;
        g_wwt[l*4 + r]  = valid ? wt : 0.f;
    }
}

// ---------------- k_img = x + warp(x) ----------------
__global__ void k_kimg(const float* __restrict__ x) {
    int b = blockIdx.z, c = blockIdx.y;
    int n = blockIdx.x*256 + threadIdx.x;
    int4   wi = *(const int4*)&g_widx[(b*NN + n)*4];
    float4 wt = *(const float4*)&g_wwt[(b*NN + n)*4];
    const float* xb = x + (size_t)(b*CC + c)*NN;
    float v = xb[n] + wt.x*xb[wi.x] + wt.y*xb[wi.y] + wt.z*xb[wi.z] + wt.w*xb[wi.w];
    g_kimg[(size_t)(b*CC + c)*NN + n] = v;
}

// ---------------- generic channel-major conv1x1 GEMM (opt. token gather) ----
template<bool GATHER>
__global__ void k_conv1x1(const float* __restrict__ W, const float* __restrict__ bias,
                          const float* __restrict__ In, const int* __restrict__ gidx,
                          float* __restrict__ Out, int Nin, int Nout)
{
    __shared__ float As[16][65];
    __shared__ float Bs[16][65];
    __shared__ int gcol[64];
    int b = blockIdx.z;
    int n0 = blockIdx.x*64, co0 = blockIdx.y*64;
    int tid = threadIdx.x;
    int tx = tid & 15, ty = tid >> 4;
    if (GATHER) {
        if (tid < 64) gcol[tid] = gidx[b*Nout + n0 + tid];
        __syncthreads();
    }
    const float* Inb = In + (size_t)b*CC*Nin;
    float acc[4][4] = {};
    for (int k0 = 0; k0 < CC; k0 += 16) {
        __syncthreads();
        for (int l = tid; l < 1024; l += 256) {
            int co = l & 63, k = l >> 6;
            As[k][co] = W[(co0 + co)*CC + k0 + k];
        }
        for (int l = tid; l < 1024; l += 256) {
            int n = l & 63, k = l >> 6;
            int col = GATHER ? gcol[n] : (n0 + n);
            Bs[k][n] = Inb[(size_t)(k0 + k)*Nin + col];
        }
        __syncthreads();
        #pragma unroll
        for (int k = 0; k < 16; k++) {
            float a[4], bb[4];
            #pragma unroll
            for (int i = 0; i < 4; i++) a[i] = As[k][ty*4 + i];
            #pragma unroll
            for (int j = 0; j < 4; j++) bb[j] = Bs[k][tx*4 + j];
            #pragma unroll
            for (int i = 0; i < 4; i++)
                #pragma unroll
                for (int j = 0; j < 4; j++)
                    acc[i][j] += a[i]*bb[j];
        }
    }
    #pragma unroll
    for (int i = 0; i < 4; i++) {
        int co = co0 + ty*4 + i;
        float bv = bias[co];
        float4 o = make_float4(acc[i][0]+bv, acc[i][1]+bv, acc[i][2]+bv, acc[i][3]+bv);
        *(float4*)&Out[((size_t)b*CC + co)*Nout + n0 + tx*4] = o;
    }
}

// ---------------- S = scale * q1^T k1 ----------------
__global__ void k_qk(float scale) {
    __shared__ float As[16][65];
    __shared__ float Bs[16][65];
    int b = blockIdx.z;
    int m0 = blockIdx.y*64, n0 = blockIdx.x*64;
    int tid = threadIdx.x, tx = tid & 15, ty = tid >> 4;
    const float* q  = g_q1 + (size_t)b*CC*NKEEP;
    const float* kk = g_k1 + (size_t)b*CC*NKEEP;
    float acc[4][4] = {};
    for (int c0 = 0; c0 < CC; c0 += 16) {
        __syncthreads();
        for (int l = tid; l < 1024; l += 256) {
            int m = l & 63, k = l >> 6;
            As[k][m] = q [(c0 + k)*NKEEP + m0 + m];
            Bs[k][m] = kk[(c0 + k)*NKEEP + n0 + m];
        }
        __syncthreads();
        #pragma unroll
        for (int k = 0; k < 16; k++) {
            float a[4], bb[4];
            #pragma unroll
            for (int i = 0; i < 4; i++) a[i] = As[k][ty*4 + i];
            #pragma unroll
            for (int j = 0; j < 4; j++) bb[j] = Bs[k][tx*4 + j];
            #pragma unroll
            for (int i = 0; i < 4; i++)
                #pragma unroll
                for (int j = 0; j < 4; j++)
                    acc[i][j] += a[i]*bb[j];
        }
    }
    float* P = g_P + (size_t)b*NKEEP*NKEEP;
    #pragma unroll
    for (int i = 0; i < 4; i++) {
        float4 o = make_float4(acc[i][0]*scale, acc[i][1]*scale, acc[i][2]*scale, acc[i][3]*scale);
        *(float4*)&P[(size_t)(m0 + ty*4 + i)*NKEEP + n0 + tx*4] = o;
    }
}

// ---------------- row softmax over P ----------------
__global__ void k_softmax() {
    size_t row = blockIdx.x;
    float* p = g_P + row*NKEEP;
    int tid = threadIdx.x;
    __shared__ float red[256];
    float mx = -1e30f;
    for (int i = tid; i < NKEEP; i += 256) mx = fmaxf(mx, p[i]);
    red[tid] = mx; __syncthreads();
    for (int o = 128; o > 0; o >>= 1) { if (tid < o) red[tid] = fmaxf(red[tid], red[tid+o]); __syncthreads(); }
    mx = red[0];
    __syncthreads();
    float s = 0.f;
    for (int i = tid; i < NKEEP; i += 256) { float e = expf(p[i] - mx); p[i] = e; s += e; }
    red[tid] = s; __syncthreads();
    for (int o = 128; o > 0; o >>= 1) { if (tid < o) red[tid] += red[tid+o]; __syncthreads(); }
    float inv = 1.0f / red[0];
    for (int i = tid; i < NKEEP; i += 256) p[i] *= inv;
}

// ---------------- gather v1 (token-major) ----------------
__global__ void k_gatherv1() {
    int l = blockIdx.x*256 + threadIdx.x;
    int c = l % CC;
    int rest = l / CC;
    int m = rest % NKEEP;
    int b = rest / NKEEP;
    int tok = g_keep[b*NKEEP + m];
    g_v1[l] = g_v[(size_t)(b*CC + c)*NN + tok];
}

// ---------------- f_attn = P @ v1 (output channel-major) ----------------
__global__ void k_pv() {
    __shared__ float As[16][65];  // [n-chunk][c]
    __shared__ float Bs[16][65];  // [n-chunk][m]
    int b = blockIdx.z;
    int m0 = blockIdx.x*64, c0 = blockIdx.y*64;
    int tid = threadIdx.x, tx = tid & 15, ty = tid >> 4;
    const float* V = g_v1 + (size_t)b*NKEEP*CC;
    const float* P = g_P  + (size_t)b*NKEEP*NKEEP;
    float acc[4][4] = {};
    for (int nk = 0; nk < NKEEP; nk += 16) {
        __syncthreads();
        for (int l = tid; l < 1024; l += 256) {
            int cc = l & 63, k = l >> 6;
            As[k][cc] = V[(size_t)(nk + k)*CC + c0 + cc];
        }
        for (int l = tid; l < 1024; l += 256) {
            int k = l & 15, m = l >> 4;
            Bs[k][m] = P[(size_t)(m0 + m)*NKEEP + nk + k];
        }
        __syncthreads();
        #pragma unroll
        for (int k = 0; k < 16; k++) {
            float a[4], bb[4];
            #pragma unroll
            for (int i = 0; i < 4; i++) a[i] = As[k][ty*4 + i];
            #pragma unroll
            for (int j = 0; j < 4; j++) bb[j] = Bs[k][tx*4 + j];
            #pragma unroll
            for (int i = 0; i < 4; i++)
                #pragma unroll
                for (int j = 0; j < 4; j++)
                    acc[i][j] += a[i]*bb[j];
        }
    }
    #pragma unroll
    for (int i = 0; i < 4; i++) {
        int c = c0 + ty*4 + i;
        float4 o = make_float4(acc[i][0], acc[i][1], acc[i][2], acc[i][3]);
        *(float4*)&g_fattn[((size_t)b*CC + c)*NKEEP + m0 + tx*4] = o;
    }
}

// ---------------- assemble out tokens ----------------
__global__ void k_assemble() {
    int b = blockIdx.z, c = blockIdx.y;
    int n = blockIdx.x*256 + threadIdx.x;
    int p = g_pos[b*NN + n];
    float v;
    if (p >= 0) v = g_fattn[((size_t)b*CC + c)*NKEEP + p];
    else        v = g_v[((size_t)b*CC + c)*NN + n] * g_sa[b*NN + n];
    g_otok[((size_t)b*CC + c)*NN + n] = v;
}

// ---------------- depthwise 3x3 + gelu*ca + residual ----------------
__global__ void k_dw(const float* __restrict__ csw, const float* __restrict__ csb) {
    int b = blockIdx.z, c = blockIdx.y;
    int n = blockIdx.x*256 + threadIdx.x;
    int h = n >> 6, w = n & 63;
    const float* inb = g_otok + ((size_t)b*CC + c)*NN;
    float acc = csb[c];
    #pragma unroll
    for (int dh = 0; dh < 3; dh++) {
        int hh = h + dh - 1;
        if (hh < 0 || hh >= HH) continue;
        #pragma unroll
        for (int dw = 0; dw < 3; dw++) {
            int ww = w + dw - 1;
            if (ww < 0 || ww >= WW) continue;
            acc += csw[c*9 + dh*3 + dw] * inb[hh*64 + ww];
        }
    }
    float x3 = acc*acc*acc;
    float g = 0.5f*acc*(1.0f + tanhf(0.7978845608028654f*(acc + 0.044715f*x3)));
    g_out2[((size_t)b*CC + c)*NN + n] = g * g_ca[b*CC + c] + inb[n];
}

// ---------------- host launch ----------------
extern "C" void kernel_launch(void* const* d_in, const int* in_sizes, int n_in,
                              void* d_out, int out_size) {
    const float* x     = (const float*)d_in[0];
    const float* in_w  = (const float*)d_in[1];
    const float* in_b  = (const float*)d_in[2];
    const float* ln_w  = (const float*)d_in[3];
    const float* ln_b  = (const float*)d_in[4];
    const float* ow1   = (const float*)d_in[5];
    const float* ob1   = (const float*)d_in[6];
    const float* ow2   = (const float*)d_in[7];
    const float* ob2   = (const float*)d_in[8];
    const float* caw   = (const float*)d_in[9];
    const float* cab   = (const float*)d_in[10];
    const float* saw   = (const float*)d_in[11];
    const float* sab   = (const float*)d_in[12];
    const float* mw1   = (const float*)d_in[13];
    const float* mb1   = (const float*)d_in[14];
    const float* mw2   = (const float*)d_in[15];
    const float* mb2   = (const float*)d_in[16];
    const float* v_w   = (const float*)d_in[17];
    const float* v_b   = (const float*)d_in[18];
    const float* q_w   = (const float*)d_in[19];
    const float* q_b   = (const float*)d_in[20];
    const float* k_w   = (const float*)d_in[21];
    const float* k_b   = (const float*)d_in[22];
    const float* cs_w  = (const float*)d_in[23];
    const float* cs_b  = (const float*)d_in[24];
    const float* out_w = (const float*)d_in[25];
    const float* out_b = (const float*)d_in[26];
    float* out = (float*)d_out;

    // symbol addresses for generic GEMM kernels
    float *p_v, *p_kimg, *p_q1, *p_k1, *p_out2;
    int *p_keep;
    cudaGetSymbolAddress((void**)&p_v,    g_v);
    cudaGetSymbolAddress((void**)&p_kimg, g_kimg);
    cudaGetSymbolAddress((void**)&p_q1,   g_q1);
    cudaGetSymbolAddress((void**)&p_k1,   g_k1);
    cudaGetSymbolAddress((void**)&p_out2, g_out2);
    cudaGetSymbolAddress((void**)&p_keep, g_keep);

    k_front<<<dim3(NN/32, BB), 256>>>(x, in_w, in_b, ln_w, ln_b,
                                      ow1, ob1, ow2, ob2, mw1, mb1, mw2, mb2);
    k_fmean<<<BB*C4, 256>>>();
    k_ca<<<(BB*CC + 255)/256, 256>>>(caw, cab);
    k_sa<<<dim3(NN/256, BB), 256>>>(saw, sab);
    k_topk<<<BB, 1024>>>();
    k_wprep<<<BB*NN/256, 256>>>();
    k_kimg<<<dim3(NN/256, CC, BB), 256>>>(x);

    // v = conv1x1(x)
    k_conv1x1<false><<<dim3(NN/64, CC/64, BB), 256>>>(v_w, v_b, x, nullptr, p_v, NN, NN);
    // q1 = gather(x) @ q_w^T ; k1 = gather(k_img) @ k_w^T    (channel-major [B,192,2048])
    k_conv1x1<true><<<dim3(NKEEP/64, CC/64, BB), 256>>>(q_w, q_b, x,      p_keep, p_q1, NN, NKEEP);
    k_conv1x1<true><<<dim3(NKEEP/64, CC/64, BB), 256>>>(k_w, k_b, p_kimg, p_keep, p_k1, NN, NKEEP);

    float scale = 1.0f / sqrtf((float)CC);
    k_qk<<<dim3(NKEEP/64, NKEEP/64, BB), 256>>>(scale);
    k_softmax<<<BB*NKEEP, 256>>>();
    k_gatherv1<<<BB*NKEEP*CC/256, 256>>>();
    k_pv<<<dim3(NKEEP/64, CC/64, BB), 256>>>();
    k_assemble<<<dim3(NN/256, CC, BB), 256>>>();
    k_dw<<<dim3(NN/256, CC, BB), 256>>>(cs_w, cs_b);
    // final conv1x1 -> output
    k_conv1x1<false><<<dim3(NN/64, CC/64, BB), 256>>>(out_w, out_b, p_out2, nullptr, out, NN, NN);
}

// round 3
// speedup vs baseline: 2.8587x; 2.8587x over previous
#include <cuda_runtime.h>
#include <math.h>
#include <stdint.h>

#define BB 8
#define CC 192
#define HH 64
#define WW 64
#define NN 4096
#define C4 48
#define CD 194
#define C8 24
#define NKEEP 2048

// ================= scratch (device globals; no allocation) =================
__device__ float g_f[BB*C4*NN];
__device__ float g_off[BB*2*NN];
__device__ float g_score[BB*NN];
__device__ int   g_keep[BB*NKEEP];
__device__ int   g_pos[BB*NN];
__device__ float g_fmean[BB*C4];
__device__ float g_ca[BB*CC];
__device__ float g_sa[BB*NN];
__device__ int   g_widx[BB*NN*4];
__device__ float g_wwt[BB*NN*4];
__device__ float g_xt[(size_t)BB*NN*CC];
__device__ float g_kimgt[(size_t)BB*NN*CC];
__device__ float g_vt[(size_t)BB*NN*CC];
__device__ float g_q1[(size_t)BB*NKEEP*CC];
__device__ float g_k1[(size_t)BB*NKEEP*CC];
__device__ float g_v1t[(size_t)BB*CC*NKEEP];
__device__ float g_P[(size_t)BB*NKEEP*NKEEP];
__device__ float g_fattnT[(size_t)BB*NKEEP*CC];
__device__ float g_otokT[(size_t)BB*NN*CC];
__device__ float g_otok[(size_t)BB*NN*CC];
__device__ float g_out2[(size_t)BB*NN*CC];
__device__ float g_out2T[(size_t)BB*NN*CC];
__device__ float g_outT[(size_t)BB*NN*CC];

// ================= tf32 mma.sync helpers =================
__device__ __forceinline__ uint32_t to_tf32(float f) {
    uint32_t u;
    asm("cvt.rna.tf32.f32 %0, %1;" : "=r"(u) : "f"(f));
    return u;
}
__device__ __forceinline__ void mma_tf32(float* d, const uint32_t* a, uint32_t b0, uint32_t b1) {
    asm volatile("mma.sync.aligned.m16n8k8.row.col.f32.tf32.tf32.f32 "
        "{%0,%1,%2,%3}, {%4,%5,%6,%7}, {%8,%9}, {%0,%1,%2,%3};"
        : "+f"(d[0]), "+f"(d[1]), "+f"(d[2]), "+f"(d[3])
        : "r"(a[0]), "r"(a[1]), "r"(a[2]), "r"(a[3]), "r"(b0), "r"(b1));
}

// ================= GEMM: Out[m,n] = (sum_k A[m,k]*B[n,k] + bias[n]) * scale ====
// Block 128x64, BK=32, 256 threads. smem [row][k] with k-stride 36 (conflict-free).
#define KS 36
#define AS_SZ (128*KS)   // per buffer (floats)
#define BS_SZ (64*KS)
template<bool GATHER>
__global__ void __launch_bounds__(256, 2) k_gemm(
    const float* __restrict__ A, size_t bsA,
    const float* __restrict__ Bm, size_t bsB,
    const float* __restrict__ bias,
    const int* __restrict__ gidx,
    float* __restrict__ Out, size_t bsOut, int Ntot, int K, float scale)
{
    extern __shared__ uint32_t sm[];
    uint32_t* As = sm;                 // [2][AS_SZ]
    uint32_t* Bs = sm + 2*AS_SZ;       // [2][BS_SZ]
    int tid = threadIdx.x;
    int lane = tid & 31, wid = tid >> 5;
    int wm = wid & 3, wn = wid >> 2;
    int g = lane >> 2, t4 = lane & 3;
    int b = blockIdx.z;
    int m0 = blockIdx.x * 128, n0 = blockIdx.y * 64;

    const float* Ab = A + (size_t)b * bsA;
    const float* Bb = Bm + (size_t)b * bsB;

    // global pointers for the 4 A-float4 loads and 2 B-float4 loads per tile
    const float* aptr[4];
    int ar[4], ac[4];
    #pragma unroll
    for (int i = 0; i < 4; i++) {
        int idx = tid + i*256;
        ar[i] = idx >> 3; ac[i] = (idx & 7) << 2;
        int grow = GATHER ? gidx[b*NKEEP + m0 + ar[i]] : (m0 + ar[i]);
        aptr[i] = Ab + (size_t)grow * K + ac[i];
    }
    const float* bptr[2];
    int br[2], bc[2];
    #pragma unroll
    for (int i = 0; i < 2; i++) {
        int idx = tid + i*256;
        br[i] = idx >> 3; bc[i] = (idx & 7) << 2;
        bptr[i] = Bb + (size_t)(n0 + br[i]) * K + bc[i];
    }

    float acc[2][4][4];
    #pragma unroll
    for (int mt = 0; mt < 2; mt++)
        #pragma unroll
        for (int nt = 0; nt < 4; nt++)
            #pragma unroll
            for (int e = 0; e < 4; e++) acc[mt][nt][e] = 0.f;

    float4 pa[4], pb[2];
    #pragma unroll
    for (int i = 0; i < 4; i++) pa[i] = *(const float4*)(aptr[i]);
    #pragma unroll
    for (int i = 0; i < 2; i++) pb[i] = *(const float4*)(bptr[i]);

    // store tile into buffer 0
    #pragma unroll
    for (int i = 0; i < 4; i++) {
        uint32_t* dst = As + ar[i]*KS + ac[i];
        *(uint4*)dst = make_uint4(to_tf32(pa[i].x), to_tf32(pa[i].y), to_tf32(pa[i].z), to_tf32(pa[i].w));
    }
    #pragma unroll
    for (int i = 0; i < 2; i++) {
        uint32_t* dst = Bs + br[i]*KS + bc[i];
        *(uint4*)dst = make_uint4(to_tf32(pb[i].x), to_tf32(pb[i].y), to_tf32(pb[i].z), to_tf32(pb[i].w));
    }
    __syncthreads();

    int nkt = K >> 5;
    for (int kt = 0; kt < nkt; kt++) {
        int buf = kt & 1;
        if (kt + 1 < nkt) {
            int off = (kt + 1) << 5;
            #pragma unroll
            for (int i = 0; i < 4; i++) pa[i] = *(const float4*)(aptr[i] + off);
            #pragma unroll
            for (int i = 0; i < 2; i++) pb[i] = *(const float4*)(bptr[i] + off);
        }
        const uint32_t* Asb = As + buf*AS_SZ;
        const uint32_t* Bsb = Bs + buf*BS_SZ;
        #pragma unroll
        for (int ks = 0; ks < 4; ks++) {
            int k0 = ks*8;
            uint32_t af[2][4];
            #pragma unroll
            for (int mt = 0; mt < 2; mt++) {
                int m = wm*32 + mt*16;
                af[mt][0] = Asb[(m+g)*KS   + k0 + t4];
                af[mt][1] = Asb[(m+g+8)*KS + k0 + t4];
                af[mt][2] = Asb[(m+g)*KS   + k0 + t4 + 4];
                af[mt][3] = Asb[(m+g+8)*KS + k0 + t4 + 4];
            }
            #pragma unroll
            for (int nt = 0; nt < 4; nt++) {
                int n = wn*32 + nt*8;
                uint32_t b0 = Bsb[(n+g)*KS + k0 + t4];
                uint32_t b1 = Bsb[(n+g)*KS + k0 + t4 + 4];
                mma_tf32(acc[0][nt], af[0], b0, b1);
                mma_tf32(acc[1][nt], af[1], b0, b1);
            }
        }
        if (kt + 1 < nkt) {
            uint32_t* Asn = As + (buf^1)*AS_SZ;
            uint32_t* Bsn = Bs + (buf^1)*BS_SZ;
            #pragma unroll
            for (int i = 0; i < 4; i++) {
                uint32_t* dst = Asn + ar[i]*KS + ac[i];
                *(uint4*)dst = make_uint4(to_tf32(pa[i].x), to_tf32(pa[i].y), to_tf32(pa[i].z), to_tf32(pa[i].w));
            }
            #pragma unroll
            for (int i = 0; i < 2; i++) {
                uint32_t* dst = Bsn + br[i]*KS + bc[i];
                *(uint4*)dst = make_uint4(to_tf32(pb[i].x), to_tf32(pb[i].y), to_tf32(pb[i].z), to_tf32(pb[i].w));
            }
        }
        __syncthreads();
    }

    // epilogue
    float* Ob = Out + (size_t)b * bsOut;
    #pragma unroll
    for (int nt = 0; nt < 4; nt++) {
        int ncol = n0 + wn*32 + nt*8 + 2*t4;
        float b0v = bias ? bias[ncol]     : 0.f;
        float b1v = bias ? bias[ncol + 1] : 0.f;
        #pragma unroll
        for (int mt = 0; mt < 2; mt++) {
            int row0 = m0 + wm*32 + mt*16 + g;
            float2 o0 = make_float2((acc[mt][nt][0] + b0v) * scale, (acc[mt][nt][1] + b1v) * scale);
            float2 o1 = make_float2((acc[mt][nt][2] + b0v) * scale, (acc[mt][nt][3] + b1v) * scale);
            *(float2*)&Ob[(size_t)row0 * Ntot + ncol]       = o0;
            *(float2*)&Ob[(size_t)(row0+8) * Ntot + ncol]   = o1;
        }
    }
}

// ================= transpose: src[R][C] -> dst[C][R] per batch =================
__global__ void k_T(const float* __restrict__ src, float* __restrict__ dst, int R, int C) {
    __shared__ float t[32][33];
    int b = blockIdx.z;
    int r0 = blockIdx.y * 32, c0 = blockIdx.x * 32;
    const float* s = src + (size_t)b * R * C;
    float* d = dst + (size_t)b * R * C;
    int tx = threadIdx.x, ty = threadIdx.y;
    #pragma unroll
    for (int j = ty; j < 32; j += 8)
        t[j][tx] = s[(size_t)(r0 + j) * C + c0 + tx];
    __syncthreads();
    #pragma unroll
    for (int j = ty; j < 32; j += 8)
        d[(size_t)(c0 + j) * R + r0 + tx] = t[tx][j];
}

// ================= gather-transpose v1t[c][m] = vt[keep[m]][c] =================
__global__ void k_gT() {
    __shared__ float t[32][33];
    int b = blockIdx.z;
    int m0 = blockIdx.x * 32, c0 = blockIdx.y * 32;
    int tx = threadIdx.x, ty = threadIdx.y;
    #pragma unroll
    for (int j = ty; j < 32; j += 8) {
        int tok = g_keep[b*NKEEP + m0 + j];
        t[j][tx] = g_vt[((size_t)b*NN + tok)*CC + c0 + tx];
    }
    __syncthreads();
    #pragma unroll
    for (int j = ty; j < 32; j += 8)
        g_v1t[((size_t)b*CC + c0 + j)*NKEEP + m0 + tx] = t[tx][j];
}

// ================= front end =================
__global__ void k_front(const float* __restrict__ x,
    const float* __restrict__ in_w, const float* __restrict__ in_b,
    const float* __restrict__ ln_w, const float* __restrict__ ln_b,
    const float* __restrict__ ow1, const float* __restrict__ ob1,
    const float* __restrict__ ow2, const float* __restrict__ ob2,
    const float* __restrict__ mw1, const float* __restrict__ mb1,
    const float* __restrict__ mw2, const float* __restrict__ mb2)
{
    __shared__ float cond[CD][33];
    __shared__ float fb[C4][33];
    __shared__ float mu_s[32], rs_s[32];
    __shared__ float hb[C8][33];
    int b = blockIdx.y;
    int n0 = blockIdx.x * 32;
    int tid = threadIdx.x;

    for (int l = tid; l < CC*32; l += 256) {
        int c = l >> 5, px = l & 31;
        cond[c][px] = x[((b*CC + c) << 12) + n0 + px];
    }
    if (tid < 32) {
        int n = n0 + tid;
        int h = n >> 6, w = n & 63;
        cond[192][tid] = -1.0f + 2.0f * (float)w / 63.0f;
        cond[193][tid] = -1.0f + 2.0f * (float)h / 63.0f;
    }
    __syncthreads();

    int px = tid & 31;
    for (int pass = 0; pass < 6; pass++) {
        int c = pass*8 + (tid >> 5);
        float acc = in_b[c];
        const float* wr = in_w + c*CD;
        #pragma unroll 2
        for (int k = 0; k < CD; k++) acc += wr[k] * cond[k][px];
        fb[c][px] = acc;
    }
    __syncthreads();

    if (tid < 32) {
        float s = 0.f, s2 = 0.f;
        for (int c = 0; c < C4; c++) { float v = fb[c][tid]; s += v; s2 += v*v; }
        float mu = s / (float)C4;
        float var = s2 / (float)C4 - mu*mu;
        mu_s[tid] = mu;
        rs_s[tid] = rsqrtf(var + 1e-6f);
    }
    __syncthreads();

    for (int l = tid; l < C4*32; l += 256) {
        int c = l >> 5, p = l & 31;
        float v = (fb[c][p] - mu_s[p]) * rs_s[p] * ln_w[c] + ln_b[c];
        v = v > 0.f ? v : 0.1f*v;
        fb[c][p] = v;
        g_f[(b*C4 + c)*NN + n0 + p] = v;
    }
    __syncthreads();

    for (int l = tid; l < C8*32; l += 256) {
        int j = l >> 5, p = l & 31;
        float acc = ob1[j];
        const float* wr = ow1 + j*C4;
        #pragma unroll 4
        for (int c = 0; c < C4; c++) acc += wr[c] * fb[c][p];
        hb[j][p] = acc > 0.f ? acc : 0.1f*acc;
    }
    __syncthreads();

    if (tid < 64) {
        int d = tid >> 5, p = tid & 31;
        float acc = ob2[d];
        const float* wr = ow2 + d*C8;
        #pragma unroll
        for (int j = 0; j < C8; j++) acc += wr[j] * hb[j][p];
        g_off[(b*2 + d)*NN + n0 + p] = tanhf(acc) * 8.0f;
    }
    if (tid >= 64 && tid < 96) {
        int p = tid - 64;
        float s = 0.f;
        for (int c = 0; c < C4; c++) s += fb[c][p];
        float t = s / (float)C4;
        float s1 = t * mw1[0] + mb1[0];
        s1 = s1 > 0.f ? s1 : 0.1f*s1;
        float l0 = s1 * mw2[0] + mb2[0];
        float l1 = s1 * mw2[1] + mb2[1];
        g_score[b*NN + n0 + p] = 1.0f / (1.0f + expf(l1 - l0));
    }
}

__global__ void k_fmean() {
    int bc = blockIdx.x;
    const float* p = g_f + bc*NN;
    float s = 0.f;
    for (int i = threadIdx.x; i < NN; i += 256) s += p[i];
    __shared__ float red[256];
    red[threadIdx.x] = s; __syncthreads();
    for (int o = 128; o > 0; o >>= 1) {
        if (threadIdx.x < o) red[threadIdx.x] += red[threadIdx.x + o];
        __syncthreads();
    }
    if (threadIdx.x == 0) g_fmean[bc] = red[0] / (float)NN;
}

__global__ void k_ca(const float* __restrict__ caw, const float* __restrict__ cab) {
    int l = blockIdx.x*256 + threadIdx.x;
    if (l >= BB*CC) return;
    int b = l / CC, co = l % CC;
    float acc = cab[co];
    #pragma unroll 4
    for (int c = 0; c < C4; c++) acc += caw[co*C4 + c] * g_fmean[b*C4 + c];
    g_ca[l] = 1.0f / (1.0f + expf(-acc));
}

__global__ void k_sa(const float* __restrict__ saw, const float* __restrict__ sab) {
    __shared__ float wsh[C4*9];
    int tid = threadIdx.x;
    for (int l = tid; l < C4*9; l += 256) wsh[l] = saw[l];
    __syncthreads();
    int b = blockIdx.y;
    int n = blockIdx.x*256 + tid;
    int h = n >> 6, w = n & 63;
    float acc = sab[0];
    const float* fb_ = g_f + b*C4*NN;
    for (int c = 0; c < C4; c++) {
        const float* fr = fb_ + c*NN;
        #pragma unroll
        for (int dh = 0; dh < 3; dh++) {
            int hh = h + dh - 1;
            if (hh < 0 || hh >= HH) continue;
            #pragma unroll
            for (int dw = 0; dw < 3; dw++) {
                int ww = w + dw - 1;
                if (ww < 0 || ww >= WW) continue;
                acc += wsh[c*9 + dh*3 + dw] * fr[hh*WW + ww];
            }
        }
    }
    g_sa[b*NN + n] = 1.0f / (1.0f + expf(-acc));
}

__device__ __forceinline__ unsigned int ford(float f) {
    unsigned int u = __float_as_uint(f);
    return (u & 0x80000000u) ? ~u : (u | 0x80000000u);
}
__global__ void k_topk() {
    __shared__ unsigned long long keys[NN];
    int b = blockIdx.x, tid = threadIdx.x;
    for (int l = tid; l < NN; l += 1024) {
        unsigned int o = ford(g_score[b*NN + l]) ^ 0xFFFFFFFFu;
        keys[l] = ((unsigned long long)o << 32) | (unsigned int)l;
    }
    __syncthreads();
    for (int kk = 2; kk <= NN; kk <<= 1) {
        for (int j = kk >> 1; j > 0; j >>= 1) {
            for (int t = tid; t < NN/2; t += 1024) {
                int i = 2*t - (t & (j-1));
                int l = i + j;
                bool up = ((i & kk) == 0);
                unsigned long long a = keys[i], c = keys[l];
                if ((a > c) == up) { keys[i] = c; keys[l] = a; }
            }
            __syncthreads();
        }
    }
    for (int l = tid; l < NN; l += 1024) {
        int tok = (int)(keys[l] & 0xFFFFFFFFu);
        if (l < NKEEP) { g_keep[b*NKEEP + l] = tok; g_pos[b*NN + tok] = l; }
        else g_pos[b*NN + tok] = -1;
    }
}

__global__ void k_wprep() {
    int l = blockIdx.x*256 + threadIdx.x;
    if (l >= BB*NN) return;
    int n = l & (NN - 1);
    int b = l >> 12;
    int h = n >> 6, w = n & 63;
    float sx = (float)w + g_off[(b*2 + 0)*NN + n];
    float sy = (float)h + g_off[(b*2 + 1)*NN + n];
    float x0 = floorf(sx), y0 = floorf(sy);
    float wx = sx - x0, wy = sy - y0;
    #pragma unroll
    for (int r = 0; r < 4; r++) {
        float xi = x0 + (float)(r & 1);
        float yi = y0 + (float)(r >> 1);
        bool valid = (xi >= 0.f) && (xi <= (float)(WW-1)) && (yi >= 0.f) && (yi <= (float)(HH-1));
        int xc = (int)fminf(fmaxf(xi, 0.f), (float)(WW-1));
        int yc = (int)fminf(fmaxf(yi, 0.f), (float)(HH-1));
        float wt = ((r & 1) ? wx : 1.f - wx) * ((r >> 1) ? wy : 1.f - wy);
        g_widx[l*4 + r] = yc*WW + xc;
        g_wwt[l*4 + r]  = valid ? wt : 0.f;
    }
}

// kimg token-major
__global__ void k_kimgt() {
    int b = blockIdx.y;
    int n = blockIdx.x*2 + threadIdx.x/192;
    int c = threadIdx.x % 192;
    int4   wi = *(const int4*)&g_widx[(b*NN + n)*4];
    float4 wt = *(const float4*)&g_wwt[(b*NN + n)*4];
    const float* xt = g_xt + (size_t)b*NN*CC;
    float v = xt[(size_t)n*CC + c]
            + wt.x*xt[(size_t)wi.x*CC + c] + wt.y*xt[(size_t)wi.y*CC + c]
            + wt.z*xt[(size_t)wi.z*CC + c] + wt.w*xt[(size_t)wi.w*CC + c];
    g_kimgt[((size_t)b*NN + n)*CC + c] = v;
}

// one-pass softmax
__global__ void k_softmax1() {
    size_t row = blockIdx.x;
    float* p = g_P + row*NKEEP;
    int tid = threadIdx.x;
    float4 a = *(float4*)(p + tid*8);
    float4 c = *(float4*)(p + tid*8 + 4);
    float m = fmaxf(fmaxf(fmaxf(a.x, a.y), fmaxf(a.z, a.w)),
                    fmaxf(fmaxf(c.x, c.y), fmaxf(c.z, c.w)));
    #pragma unroll
    for (int o = 16; o; o >>= 1) m = fmaxf(m, __shfl_xor_sync(~0u, m, o));
    __shared__ float sm[8];
    if ((tid & 31) == 0) sm[tid >> 5] = m;
    __syncthreads();
    m = sm[0];
    #pragma unroll
    for (int i = 1; i < 8; i++) m = fmaxf(m, sm[i]);
    float e[8];
    e[0] = __expf(a.x - m); e[1] = __expf(a.y - m); e[2] = __expf(a.z - m); e[3] = __expf(a.w - m);
    e[4] = __expf(c.x - m); e[5] = __expf(c.y - m); e[6] = __expf(c.z - m); e[7] = __expf(c.w - m);
    float s = e[0]+e[1]+e[2]+e[3]+e[4]+e[5]+e[6]+e[7];
    #pragma unroll
    for (int o = 16; o; o >>= 1) s += __shfl_xor_sync(~0u, s, o);
    __syncthreads();
    if ((tid & 31) == 0) sm[tid >> 5] = s;
    __syncthreads();
    s = sm[0];
    #pragma unroll
    for (int i = 1; i < 8; i++) s += sm[i];
    float inv = 1.0f / s;
    float4 o0 = make_float4(e[0]*inv, e[1]*inv, e[2]*inv, e[3]*inv);
    float4 o1 = make_float4(e[4]*inv, e[5]*inv, e[6]*inv, e[7]*inv);
    *(float4*)(p + tid*8) = o0;
    *(float4*)(p + tid*8 + 4) = o1;
}

// assemble token-major
__global__ void k_assembleT() {
    int b = blockIdx.y;
    int n = blockIdx.x*2 + threadIdx.x/192;
    int c = threadIdx.x % 192;
    int p = g_pos[b*NN + n];
    float v;
    if (p >= 0) v = g_fattnT[((size_t)b*NKEEP + p)*CC + c];
    else        v = g_vt[((size_t)b*NN + n)*CC + c] * g_sa[b*NN + n];
    g_otokT[((size_t)b*NN + n)*CC + c] = v;
}

// depthwise 3x3 + gelu*ca + residual (channel-major)
__global__ void k_dw(const float* __restrict__ csw, const float* __restrict__ csb) {
    int b = blockIdx.z, c = blockIdx.y;
    int n = blockIdx.x*256 + threadIdx.x;
    int h = n >> 6, w = n & 63;
    const float* inb = g_otok + ((size_t)b*CC + c)*NN;
    float acc = csb[c];
    #pragma unroll
    for (int dh = 0; dh < 3; dh++) {
        int hh = h + dh - 1;
        if (hh < 0 || hh >= HH) continue;
        #pragma unroll
        for (int dw = 0; dw < 3; dw++) {
            int ww = w + dw - 1;
            if (ww < 0 || ww >= WW) continue;
            acc += csw[c*9 + dh*3 + dw] * inb[hh*64 + ww];
        }
    }
    float x3 = acc*acc*acc;
    float g = 0.5f*acc*(1.0f + tanhf(0.7978845608028654f*(acc + 0.044715f*x3)));
    g_out2[((size_t)b*CC + c)*NN + n] = g * g_ca[b*CC + c] + inb[n];
}

// ================= host =================
extern "C" void kernel_launch(void* const* d_in, const int* in_sizes, int n_in,
                              void* d_out, int out_size) {
    const float* x     = (const float*)d_in[0];
    const float* in_w  = (const float*)d_in[1];
    const float* in_b  = (const float*)d_in[2];
    const float* ln_w  = (const float*)d_in[3];
    const float* ln_b  = (const float*)d_in[4];
    const float* ow1   = (const float*)d_in[5];
    const float* ob1   = (const float*)d_in[6];
    const float* ow2   = (const float*)d_in[7];
    const float* ob2   = (const float*)d_in[8];
    const float* caw   = (const float*)d_in[9];
    const float* cab   = (const float*)d_in[10];
    const float* saw   = (const float*)d_in[11];
    const float* sab   = (const float*)d_in[12];
    const float* mw1   = (const float*)d_in[13];
    const float* mb1   = (const float*)d_in[14];
    const float* mw2   = (const float*)d_in[15];
    const float* mb2   = (const float*)d_in[16];
    const float* v_w   = (const float*)d_in[17];
    const float* v_b   = (const float*)d_in[18];
    const float* q_w   = (const float*)d_in[19];
    const float* q_b   = (const float*)d_in[20];
    const float* k_w   = (const float*)d_in[21];
    const float* k_b   = (const float*)d_in[22];
    const float* cs_w  = (const float*)d_in[23];
    const float* cs_b  = (const float*)d_in[24];
    const float* out_w = (const float*)d_in[25];
    const float* out_b = (const float*)d_in[26];
    float* out = (float*)d_out;

    float *p_xt, *p_kimgt, *p_vt, *p_q1, *p_k1, *p_v1t, *p_P, *p_fattnT;
    float *p_otokT, *p_otok, *p_out2, *p_out2T, *p_outT;
    int *p_keep;
    cudaGetSymbolAddress((void**)&p_xt, g_xt);
    cudaGetSymbolAddress((void**)&p_kimgt, g_kimgt);
    cudaGetSymbolAddress((void**)&p_vt, g_vt);
    cudaGetSymbolAddress((void**)&p_q1, g_q1);
    cudaGetSymbolAddress((void**)&p_k1, g_k1);
    cudaGetSymbolAddress((void**)&p_v1t, g_v1t);
    cudaGetSymbolAddress((void**)&p_P, g_P);
    cudaGetSymbolAddress((void**)&p_fattnT, g_fattnT);
    cudaGetSymbolAddress((void**)&p_otokT, g_otokT);
    cudaGetSymbolAddress((void**)&p_otok, g_otok);
    cudaGetSymbolAddress((void**)&p_out2, g_out2);
    cudaGetSymbolAddress((void**)&p_out2T, g_out2T);
    cudaGetSymbolAddress((void**)&p_outT, g_outT);
    cudaGetSymbolAddress((void**)&p_keep, g_keep);

    const int SMEM = (2*AS_SZ + 2*BS_SZ) * 4;  // 55296 bytes
    cudaFuncSetAttribute(k_gemm<false>, cudaFuncAttributeMaxDynamicSharedMemorySize, SMEM);
    cudaFuncSetAttribute(k_gemm<true>,  cudaFuncAttributeMaxDynamicSharedMemorySize, SMEM);

    dim3 tb(32, 8);
    // x -> x_t
    k_T<<<dim3(NN/32, CC/32, BB), tb>>>(x, p_xt, CC, NN);
    k_front<<<dim3(NN/32, BB), 256>>>(x, in_w, in_b, ln_w, ln_b,
                                      ow1, ob1, ow2, ob2, mw1, mb1, mw2, mb2);
    k_fmean<<<BB*C4, 256>>>();
    k_ca<<<(BB*CC + 255)/256, 256>>>(caw, cab);
    k_sa<<<dim3(NN/256, BB), 256>>>(saw, sab);
    k_topk<<<BB, 1024>>>();
    k_wprep<<<BB*NN/256, 256>>>();
    k_kimgt<<<dim3(NN/2, BB), 384>>>();

    float scale = rsqrtf((float)CC);
    // v = x_t @ v_w^T + v_b          [4096 x 192]
    k_gemm<false><<<dim3(NN/128, 3, BB), 256, SMEM>>>(
        p_xt, (size_t)NN*CC, v_w, 0, v_b, nullptr, p_vt, (size_t)NN*CC, CC, CC, 1.0f);
    // q1 = (gather(x_t) @ q_w^T + q_b) * C^-0.5   [2048 x 192]
    k_gemm<true><<<dim3(NKEEP/128, 3, BB), 256, SMEM>>>(
        p_xt, (size_t)NN*CC, q_w, 0, q_b, p_keep, p_q1, (size_t)NKEEP*CC, CC, CC, scale);
    // k1 = gather(kimg_t) @ k_w^T + k_b           [2048 x 192]
    k_gemm<true><<<dim3(NKEEP/128, 3, BB), 256, SMEM>>>(
        p_kimgt, (size_t)NN*CC, k_w, 0, k_b, p_keep, p_k1, (size_t)NKEEP*CC, CC, CC, 1.0f);
    // P = q1 @ k1^T                                [2048 x 2048]
    k_gemm<false><<<dim3(NKEEP/128, NKEEP/64, BB), 256, SMEM>>>(
        p_q1, (size_t)NKEEP*CC, p_k1, (size_t)NKEEP*CC, nullptr, nullptr,
        p_P, (size_t)NKEEP*NKEEP, NKEEP, CC, 1.0f);
    k_softmax1<<<BB*NKEEP, 256>>>();
    k_gT<<<dim3(NKEEP/32, CC/32, BB), tb>>>();
    // f_attn = P @ v1t^T                           [2048 x 192], K=2048
    k_gemm<false><<<dim3(NKEEP/128, 3, BB), 256, SMEM>>>(
        p_P, (size_t)NKEEP*NKEEP, p_v1t, (size_t)CC*NKEEP, nullptr, nullptr,
        p_fattnT, (size_t)NKEEP*CC, CC, NKEEP, 1.0f);
    k_assembleT<<<dim3(NN/2, BB), 384>>>();
    // otokT [N][C] -> otok [C][N]
    k_T<<<dim3(CC/32, NN/32, BB), tb>>>(p_otokT, p_otok, NN, CC);
    k_dw<<<dim3(NN/256, CC, BB), 256>>>(cs_w, cs_b);
    // out2 [C][N] -> out2T [N][C]
    k_T<<<dim3(NN/32, CC/32, BB), tb>>>(p_out2, p_out2T, CC, NN);
    // final conv: outT = out2T @ out_w^T + out_b   [4096 x 192]
    k_gemm<false><<<dim3(NN/128, 3, BB), 256, SMEM>>>(
        p_out2T, (size_t)NN*CC, out_w, 0, out_b, nullptr, p_outT, (size_t)NN*CC, CC, CC, 1.0f);
    // outT [N][C] -> out [C][N]
    k_T<<<dim3(CC/32, NN/32, BB), tb>>>(p_outT, out, NN, CC);
}

// round 4
// speedup vs baseline: 3.1051x; 1.0862x over previous
#include <cuda_runtime.h>
#include <math.h>
#include <stdint.h>

#define BB 8
#define CC 192
#define HH 64
#define WW 64
#define NN 4096
#define C4 48
#define CD 194
#define C8 24
#define NKEEP 2048

// ================= scratch =================
__device__ float g_f[BB*C4*NN];
__device__ float g_off[BB*2*NN];
__device__ float g_score[BB*NN];
__device__ int   g_keep[BB*NKEEP];
__device__ int   g_pos[BB*NN];
__device__ float g_fmean[BB*C4];
__device__ float g_ca[BB*CC];
__device__ float g_sa[BB*NN];
__device__ int   g_widx[BB*NN*4];
__device__ float g_wwt[BB*NN*4];
__device__ float g_xt[(size_t)BB*NN*CC];
__device__ float g_kimgt[(size_t)BB*NN*CC];
__device__ float g_vt[(size_t)BB*NN*CC];
__device__ float g_q1[(size_t)BB*NKEEP*CC];
__device__ float g_k1[(size_t)BB*NKEEP*CC];
__device__ float g_v1t[(size_t)BB*CC*NKEEP];
__device__ float g_otokT[(size_t)BB*NN*CC];
__device__ float g_out2T[(size_t)BB*NN*CC];
__device__ float g_outT[(size_t)BB*NN*CC];

// ================= tf32 mma helpers =================
__device__ __forceinline__ uint32_t to_tf32(float f) {
    uint32_t u;
    asm("cvt.rna.tf32.f32 %0, %1;" : "=r"(u) : "f"(f));
    return u;
}
__device__ __forceinline__ uint4 cvt4(float4 v) {
    return make_uint4(to_tf32(v.x), to_tf32(v.y), to_tf32(v.z), to_tf32(v.w));
}
__device__ __forceinline__ void mma_tf32(float* d, const uint32_t* a, uint32_t b0, uint32_t b1) {
    asm volatile("mma.sync.aligned.m16n8k8.row.col.f32.tf32.tf32.f32 "
        "{%0,%1,%2,%3}, {%4,%5,%6,%7}, {%8,%9}, {%0,%1,%2,%3};"
        : "+f"(d[0]), "+f"(d[1]), "+f"(d[2]), "+f"(d[3])
        : "r"(a[0]), "r"(a[1]), "r"(a[2]), "r"(a[3]), "r"(b0), "r"(b1));
}

// ================= generic GEMM (kept from R3): Out[m,n]=(A[m,:]·B[n,:]+bias[n])*scale ===
#define KS 36
#define AS_SZ (128*KS)
#define BS_SZ (64*KS)
template<bool GATHER>
__global__ void __launch_bounds__(256, 2) k_gemm(
    const float* __restrict__ A, size_t bsA,
    const float* __restrict__ Bm, size_t bsB,
    const float* __restrict__ bias,
    const int* __restrict__ gidx,
    float* __restrict__ Out, size_t bsOut, int Ntot, int K, float scale)
{
    extern __shared__ uint32_t sm[];
    uint32_t* As = sm;
    uint32_t* Bs = sm + 2*AS_SZ;
    int tid = threadIdx.x;
    int lane = tid & 31, wid = tid >> 5;
    int wm = wid & 3, wn = wid >> 2;
    int g = lane >> 2, t4 = lane & 3;
    int b = blockIdx.z;
    int m0 = blockIdx.x * 128, n0 = blockIdx.y * 64;

    const float* Ab = A + (size_t)b * bsA;
    const float* Bb = Bm + (size_t)b * bsB;

    const float* aptr[4];
    int ar[4], ac[4];
    #pragma unroll
    for (int i = 0; i < 4; i++) {
        int idx = tid + i*256;
        ar[i] = idx >> 3; ac[i] = (idx & 7) << 2;
        int grow = GATHER ? gidx[b*NKEEP + m0 + ar[i]] : (m0 + ar[i]);
        aptr[i] = Ab + (size_t)grow * K + ac[i];
    }
    const float* bptr[2];
    int br[2], bc[2];
    #pragma unroll
    for (int i = 0; i < 2; i++) {
        int idx = tid + i*256;
        br[i] = idx >> 3; bc[i] = (idx & 7) << 2;
        bptr[i] = Bb + (size_t)(n0 + br[i]) * K + bc[i];
    }

    float acc[2][4][4];
    #pragma unroll
    for (int mt = 0; mt < 2; mt++)
        #pragma unroll
        for (int nt = 0; nt < 4; nt++)
            #pragma unroll
            for (int e = 0; e < 4; e++) acc[mt][nt][e] = 0.f;

    float4 pa[4], pb[2];
    #pragma unroll
    for (int i = 0; i < 4; i++) pa[i] = *(const float4*)(aptr[i]);
    #pragma unroll
    for (int i = 0; i < 2; i++) pb[i] = *(const float4*)(bptr[i]);

    #pragma unroll
    for (int i = 0; i < 4; i++) *(uint4*)(As + ar[i]*KS + ac[i]) = cvt4(pa[i]);
    #pragma unroll
    for (int i = 0; i < 2; i++) *(uint4*)(Bs + br[i]*KS + bc[i]) = cvt4(pb[i]);
    __syncthreads();

    int nkt = K >> 5;
    for (int kt = 0; kt < nkt; kt++) {
        int buf = kt & 1;
        if (kt + 1 < nkt) {
            int off = (kt + 1) << 5;
            #pragma unroll
            for (int i = 0; i < 4; i++) pa[i] = *(const float4*)(aptr[i] + off);
            #pragma unroll
            for (int i = 0; i < 2; i++) pb[i] = *(const float4*)(bptr[i] + off);
        }
        const uint32_t* Asb = As + buf*AS_SZ;
        const uint32_t* Bsb = Bs + buf*BS_SZ;
        #pragma unroll
        for (int ks = 0; ks < 4; ks++) {
            int k0 = ks*8;
            uint32_t af[2][4];
            #pragma unroll
            for (int mt = 0; mt < 2; mt++) {
                int m = wm*32 + mt*16;
                af[mt][0] = Asb[(m+g)*KS   + k0 + t4];
                af[mt][1] = Asb[(m+g+8)*KS + k0 + t4];
                af[mt][2] = Asb[(m+g)*KS   + k0 + t4 + 4];
                af[mt][3] = Asb[(m+g+8)*KS + k0 + t4 + 4];
            }
            #pragma unroll
            for (int nt = 0; nt < 4; nt++) {
                int n = wn*32 + nt*8;
                uint32_t b0 = Bsb[(n+g)*KS + k0 + t4];
                uint32_t b1 = Bsb[(n+g)*KS + k0 + t4 + 4];
                mma_tf32(acc[0][nt], af[0], b0, b1);
                mma_tf32(acc[1][nt], af[1], b0, b1);
            }
        }
        if (kt + 1 < nkt) {
            uint32_t* Asn = As + (buf^1)*AS_SZ;
            uint32_t* Bsn = Bs + (buf^1)*BS_SZ;
            #pragma unroll
            for (int i = 0; i < 4; i++) *(uint4*)(Asn + ar[i]*KS + ac[i]) = cvt4(pa[i]);
            #pragma unroll
            for (int i = 0; i < 2; i++) *(uint4*)(Bsn + br[i]*KS + bc[i]) = cvt4(pb[i]);
        }
        __syncthreads();
    }

    float* Ob = Out + (size_t)b * bsOut;
    #pragma unroll
    for (int nt = 0; nt < 4; nt++) {
        int ncol = n0 + wn*32 + nt*8 + 2*t4;
        float b0v = bias ? bias[ncol]     : 0.f;
        float b1v = bias ? bias[ncol + 1] : 0.f;
        #pragma unroll
        for (int mt = 0; mt < 2; mt++) {
            int row0 = m0 + wm*32 + mt*16 + g;
            float2 o0 = make_float2((acc[mt][nt][0] + b0v) * scale, (acc[mt][nt][1] + b1v) * scale);
            float2 o1 = make_float2((acc[mt][nt][2] + b0v) * scale, (acc[mt][nt][3] + b1v) * scale);
            *(float2*)&Ob[(size_t)row0 * Ntot + ncol]     = o0;
            *(float2*)&Ob[(size_t)(row0+8) * Ntot + ncol] = o1;
        }
    }
}

// ================= flash attention =================
// smem float offsets
#define F_QS 0
#define F_KS 25088            // Qs 128x196
#define F_VS 31360            // Ks 32x196
#define F_PS 45184            // Vs 2 x (192x36)
#define F_SC 49792            // Ps 128x36
#define F_LB 49920
#define F_TOT 50048
#define NTILES (NKEEP/32)

__global__ void __launch_bounds__(256, 1) k_flash() {
    extern __shared__ uint32_t sm[];
    uint32_t* Qs = sm + F_QS;
    uint32_t* Ksm = sm + F_KS;
    uint32_t* Vsm = sm + F_VS;
    uint32_t* Ps = sm + F_PS;
    float* scaleb = (float*)(sm + F_SC);
    float* lb = (float*)(sm + F_LB);

    int tid = threadIdx.x, lane = tid & 31, w = tid >> 5;
    int g = lane >> 2, t4 = lane & 3;
    int b = blockIdx.y, m0 = blockIdx.x * 128;

    const float* Qg = g_q1 + ((size_t)b*NKEEP + m0)*CC;
    const float* Kg = g_k1 + (size_t)b*NKEEP*CC;
    const float* Vg = g_v1t + (size_t)b*CC*NKEEP;

    // load Q tile once
    #pragma unroll
    for (int j = 0; j < 24; j++) {
        int idx = tid + j*256;
        int r = idx/48, c4v = (idx%48)*4;
        float4 v = *(const float4*)(Qg + (size_t)r*CC + c4v);
        *(uint4*)&Qs[r*196 + c4v] = cvt4(v);
    }

    // per-thread load indices
    int rK[6], cK[6], cV[6], kV[6];
    #pragma unroll
    for (int j = 0; j < 6; j++) {
        int idx = tid + j*256;
        rK[j] = idx/48; cK[j] = (idx%48)*4;
        cV[j] = idx>>3; kV[j] = (idx&7)*4;
    }

    float4 pk[6], pv[6];
    #pragma unroll
    for (int j = 0; j < 6; j++) {
        pk[j] = *(const float4*)(Kg + (size_t)rK[j]*CC + cK[j]);
        pv[j] = *(const float4*)(Vg + (size_t)cV[j]*NKEEP + kV[j]);
    }
    #pragma unroll
    for (int j = 0; j < 6; j++) {
        *(uint4*)&Ksm[rK[j]*196 + cK[j]] = cvt4(pk[j]);
        *(uint4*)&Vsm[cV[j]*36 + kV[j]] = cvt4(pv[j]);
    }
    __syncthreads();

    int wm = w >> 1, wn = w & 1;
    float oat[3][8][4];
    #pragma unroll
    for (int mt = 0; mt < 3; mt++)
        #pragma unroll
        for (int nt = 0; nt < 8; nt++)
            #pragma unroll
            for (int e = 0; e < 4; e++) oat[mt][nt][e] = 0.f;
    float m_r0 = -1e30f, m_r1 = -1e30f, l_r0 = 0.f, l_r1 = 0.f;

    int qr0 = w * 16;
    #pragma unroll 1
    for (int kt = 0; kt < NTILES; kt++) {
        int buf = kt & 1;
        // prefetch next K/V tile
        if (kt + 1 < NTILES) {
            int k0 = (kt + 1) * 32;
            #pragma unroll
            for (int j = 0; j < 6; j++) {
                pk[j] = *(const float4*)(Kg + (size_t)(k0 + rK[j])*CC + cK[j]);
                pv[j] = *(const float4*)(Vg + (size_t)cV[j]*NKEEP + k0 + kV[j]);
            }
        }
        // ---- S = Q K^T  (warp: 16 q-rows x 32 keys) ----
        float sacc[4][4];
        #pragma unroll
        for (int nt = 0; nt < 4; nt++)
            #pragma unroll
            for (int e = 0; e < 4; e++) sacc[nt][e] = 0.f;
        #pragma unroll
        for (int ks = 0; ks < 24; ks++) {
            int k0 = ks*8;
            uint32_t a[4];
            a[0] = Qs[(qr0+g)*196   + k0 + t4];
            a[1] = Qs[(qr0+g+8)*196 + k0 + t4];
            a[2] = Qs[(qr0+g)*196   + k0 + t4 + 4];
            a[3] = Qs[(qr0+g+8)*196 + k0 + t4 + 4];
            #pragma unroll
            for (int nt = 0; nt < 4; nt++) {
                uint32_t b0 = Ksm[(nt*8+g)*196 + k0 + t4];
                uint32_t b1 = Ksm[(nt*8+g)*196 + k0 + t4 + 4];
                mma_tf32(sacc[nt], a, b0, b1);
            }
        }
        // ---- online softmax ----
        float mx0 = -1e30f, mx1 = -1e30f;
        #pragma unroll
        for (int nt = 0; nt < 4; nt++) {
            mx0 = fmaxf(mx0, fmaxf(sacc[nt][0], sacc[nt][1]));
            mx1 = fmaxf(mx1, fmaxf(sacc[nt][2], sacc[nt][3]));
        }
        mx0 = fmaxf(mx0, __shfl_xor_sync(~0u, mx0, 1));
        mx0 = fmaxf(mx0, __shfl_xor_sync(~0u, mx0, 2));
        mx1 = fmaxf(mx1, __shfl_xor_sync(~0u, mx1, 1));
        mx1 = fmaxf(mx1, __shfl_xor_sync(~0u, mx1, 2));
        float mn0 = fmaxf(m_r0, mx0), mn1 = fmaxf(m_r1, mx1);
        float al0 = __expf(m_r0 - mn0), al1 = __expf(m_r1 - mn1);
        float s0 = 0.f, s1 = 0.f;
        #pragma unroll
        for (int nt = 0; nt < 4; nt++) {
            float e00 = __expf(sacc[nt][0] - mn0);
            float e01 = __expf(sacc[nt][1] - mn0);
            float e10 = __expf(sacc[nt][2] - mn1);
            float e11 = __expf(sacc[nt][3] - mn1);
            s0 += e00 + e01; s1 += e10 + e11;
            uint2 p0 = make_uint2(to_tf32(e00), to_tf32(e01));
            uint2 p1 = make_uint2(to_tf32(e10), to_tf32(e11));
            *(uint2*)&Ps[(qr0+g)*36   + nt*8 + 2*t4] = p0;
            *(uint2*)&Ps[(qr0+g+8)*36 + nt*8 + 2*t4] = p1;
        }
        s0 += __shfl_xor_sync(~0u, s0, 1); s0 += __shfl_xor_sync(~0u, s0, 2);
        s1 += __shfl_xor_sync(~0u, s1, 1); s1 += __shfl_xor_sync(~0u, s1, 2);
        l_r0 = l_r0 * al0 + s0;
        l_r1 = l_r1 * al1 + s1;
        m_r0 = mn0; m_r1 = mn1;
        if (t4 == 0) {
            scaleb[qr0+g]   = al0;
            scaleb[qr0+g+8] = al1;
            if (kt == NTILES-1) { lb[qr0+g] = l_r0; lb[qr0+g+8] = l_r1; }
        }
        __syncthreads();   // Ps/scale visible; Ks reads done
        // store prefetched K (next tile)
        if (kt + 1 < NTILES) {
            #pragma unroll
            for (int j = 0; j < 6; j++)
                *(uint4*)&Ksm[rK[j]*196 + cK[j]] = cvt4(pk[j]);
        }
        // ---- rescale O^T and accumulate O^T += V^T P^T ----
        #pragma unroll
        for (int nt = 0; nt < 8; nt++) {
            int qc = wn*64 + nt*8 + 2*t4;
            float a0 = scaleb[qc], a1 = scaleb[qc+1];
            #pragma unroll
            for (int mt = 0; mt < 3; mt++) {
                oat[mt][nt][0] *= a0; oat[mt][nt][1] *= a1;
                oat[mt][nt][2] *= a0; oat[mt][nt][3] *= a1;
            }
        }
        const uint32_t* Vb = Vsm + buf*6912;
        #pragma unroll
        for (int ks = 0; ks < 4; ks++) {
            int k0 = ks*8;
            uint32_t bfr[8][2];
            #pragma unroll
            for (int nt = 0; nt < 8; nt++) {
                bfr[nt][0] = Ps[(wn*64 + nt*8 + g)*36 + k0 + t4];
                bfr[nt][1] = Ps[(wn*64 + nt*8 + g)*36 + k0 + t4 + 4];
            }
            #pragma unroll
            for (int mt = 0; mt < 3; mt++) {
                int cr = wm*48 + mt*16;
                uint32_t a[4];
                a[0] = Vb[(cr+g)*36   + k0 + t4];
                a[1] = Vb[(cr+g+8)*36 + k0 + t4];
                a[2] = Vb[(cr+g)*36   + k0 + t4 + 4];
                a[3] = Vb[(cr+g+8)*36 + k0 + t4 + 4];
                #pragma unroll
                for (int nt = 0; nt < 8; nt++)
                    mma_tf32(oat[mt][nt], a, bfr[nt][0], bfr[nt][1]);
            }
        }
        // store prefetched V into other buffer
        if (kt + 1 < NTILES) {
            uint32_t* Vn = Vsm + (buf^1)*6912;
            #pragma unroll
            for (int j = 0; j < 6; j++)
                *(uint4*)&Vn[cV[j]*36 + kV[j]] = cvt4(pv[j]);
        }
        __syncthreads();
    }

    // ---- epilogue: normalize, transpose via smem (reuse Qs), scatter to g_otokT ----
    float* Ot = (float*)Qs;
    #pragma unroll
    for (int nt = 0; nt < 8; nt++) {
        int qc = wn*64 + nt*8 + 2*t4;
        float li0 = 1.f / lb[qc], li1 = 1.f / lb[qc+1];
        #pragma unroll
        for (int mt = 0; mt < 3; mt++) {
            int cr = wm*48 + mt*16;
            Ot[qc*196 + cr+g]       = oat[mt][nt][0] * li0;
            Ot[(qc+1)*196 + cr+g]   = oat[mt][nt][1] * li1;
            Ot[qc*196 + cr+g+8]     = oat[mt][nt][2] * li0;
            Ot[(qc+1)*196 + cr+g+8] = oat[mt][nt][3] * li1;
        }
    }
    __syncthreads();
    #pragma unroll
    for (int j = 0; j < 24; j++) {
        int idx = tid + j*256;
        int r = idx/48, c4v = (idx%48)*4;
        int tok = g_keep[b*NKEEP + m0 + r];
        float4 v = *(float4*)&Ot[r*196 + c4v];
        *(float4*)&g_otokT[((size_t)b*NN + tok)*CC + c4v] = v;
    }
}

// ================= transpose src[R][C] -> dst[C][R] =================
__global__ void k_T(const float* __restrict__ src, float* __restrict__ dst, int R, int C) {
    __shared__ float t[32][33];
    int b = blockIdx.z;
    int r0 = blockIdx.y * 32, c0 = blockIdx.x * 32;
    const float* s = src + (size_t)b * R * C;
    float* d = dst + (size_t)b * R * C;
    int tx = threadIdx.x, ty = threadIdx.y;
    #pragma unroll
    for (int j = ty; j < 32; j += 8)
        t[j][tx] = s[(size_t)(r0 + j) * C + c0 + tx];
    __syncthreads();
    #pragma unroll
    for (int j = ty; j < 32; j += 8)
        d[(size_t)(c0 + j) * R + r0 + tx] = t[tx][j];
}

// ================= gather-transpose v1t[c][m] = vt[keep[m]][c] =================
__global__ void k_gT() {
    __shared__ float t[32][33];
    int b = blockIdx.z;
    int m0 = blockIdx.x * 32, c0 = blockIdx.y * 32;
    int tx = threadIdx.x, ty = threadIdx.y;
    #pragma unroll
    for (int j = ty; j < 32; j += 8) {
        int tok = g_keep[b*NKEEP + m0 + j];
        t[j][tx] = g_vt[((size_t)b*NN + tok)*CC + c0 + tx];
    }
    __syncthreads();
    #pragma unroll
    for (int j = ty; j < 32; j += 8)
        g_v1t[((size_t)b*CC + c0 + j)*NKEEP + m0 + tx] = t[tx][j];
}

// ================= front end =================
__global__ void k_front(const float* __restrict__ x,
    const float* __restrict__ in_w, const float* __restrict__ in_b,
    const float* __restrict__ ln_w, const float* __restrict__ ln_b,
    const float* __restrict__ ow1, const float* __restrict__ ob1,
    const float* __restrict__ ow2, const float* __restrict__ ob2,
    const float* __restrict__ mw1, const float* __restrict__ mb1,
    const float* __restrict__ mw2, const float* __restrict__ mb2)
{
    __shared__ float cond[CD][33];
    __shared__ float fb[C4][33];
    __shared__ float mu_s[32], rs_s[32];
    __shared__ float hb[C8][33];
    int b = blockIdx.y;
    int n0 = blockIdx.x * 32;
    int tid = threadIdx.x;

    for (int l = tid; l < CC*32; l += 256) {
        int c = l >> 5, px = l & 31;
        cond[c][px] = x[((b*CC + c) << 12) + n0 + px];
    }
    if (tid < 32) {
        int n = n0 + tid;
        int h = n >> 6, w = n & 63;
        cond[192][tid] = -1.0f + 2.0f * (float)w / 63.0f;
        cond[193][tid] = -1.0f + 2.0f * (float)h / 63.0f;
    }
    __syncthreads();

    int px = tid & 31;
    for (int pass = 0; pass < 6; pass++) {
        int c = pass*8 + (tid >> 5);
        float acc = in_b[c];
        const float* wr = in_w + c*CD;
        #pragma unroll 2
        for (int k = 0; k < CD; k++) acc += wr[k] * cond[k][px];
        fb[c][px] = acc;
    }
    __syncthreads();

    if (tid < 32) {
        float s = 0.f, s2 = 0.f;
        for (int c = 0; c < C4; c++) { float v = fb[c][tid]; s += v; s2 += v*v; }
        float mu = s / (float)C4;
        float var = s2 / (float)C4 - mu*mu;
        mu_s[tid] = mu;
        rs_s[tid] = rsqrtf(var + 1e-6f);
    }
    __syncthreads();

    for (int l = tid; l < C4*32; l += 256) {
        int c = l >> 5, p = l & 31;
        float v = (fb[c][p] - mu_s[p]) * rs_s[p] * ln_w[c] + ln_b[c];
        v = v > 0.f ? v : 0.1f*v;
        fb[c][p] = v;
        g_f[(b*C4 + c)*NN + n0 + p] = v;
    }
    __syncthreads();

    for (int l = tid; l < C8*32; l += 256) {
        int j = l >> 5, p = l & 31;
        float acc = ob1[j];
        const float* wr = ow1 + j*C4;
        #pragma unroll 4
        for (int c = 0; c < C4; c++) acc += wr[c] * fb[c][p];
        hb[j][p] = acc > 0.f ? acc : 0.1f*acc;
    }
    __syncthreads();

    if (tid < 64) {
        int d = tid >> 5, p = tid & 31;
        float acc = ob2[d];
        const float* wr = ow2 + d*C8;
        #pragma unroll
        for (int j = 0; j < C8; j++) acc += wr[j] * hb[j][p];
        g_off[(b*2 + d)*NN + n0 + p] = tanhf(acc) * 8.0f;
    }
    if (tid >= 64 && tid < 96) {
        int p = tid - 64;
        float s = 0.f;
        for (int c = 0; c < C4; c++) s += fb[c][p];
        float t = s / (float)C4;
        float s1 = t * mw1[0] + mb1[0];
        s1 = s1 > 0.f ? s1 : 0.1f*s1;
        float l0 = s1 * mw2[0] + mb2[0];
        float l1 = s1 * mw2[1] + mb2[1];
        g_score[b*NN + n0 + p] = 1.0f / (1.0f + expf(l1 - l0));
    }
}

__global__ void k_fmean() {
    int bc = blockIdx.x;
    const float* p = g_f + bc*NN;
    float s = 0.f;
    for (int i = threadIdx.x; i < NN; i += 256) s += p[i];
    __shared__ float red[256];
    red[threadIdx.x] = s; __syncthreads();
    for (int o = 128; o > 0; o >>= 1) {
        if (threadIdx.x < o) red[threadIdx.x] += red[threadIdx.x + o];
        __syncthreads();
    }
    if (threadIdx.x == 0) g_fmean[bc] = red[0] / (float)NN;
}

__global__ void k_ca(const float* __restrict__ caw, const float* __restrict__ cab) {
    int l = blockIdx.x*256 + threadIdx.x;
    if (l >= BB*CC) return;
    int b = l / CC, co = l % CC;
    float acc = cab[co];
    #pragma unroll 4
    for (int c = 0; c < C4; c++) acc += caw[co*C4 + c] * g_fmean[b*C4 + c];
    g_ca[l] = 1.0f / (1.0f + expf(-acc));
}

// ================= sa: tiled 3x3 conv + sigmoid =================
__global__ void k_sa2(const float* __restrict__ saw, const float* __restrict__ sab) {
    __shared__ float wsh[C4*9];
    __shared__ float smf[6][64];
    int b = blockIdx.y, h0 = blockIdx.x*4;
    int tid = threadIdx.x;
    for (int l = tid; l < C4*9; l += 256) wsh[l] = saw[l];
    int lw = tid & 63, lh = tid >> 6;
    float acc = sab[0];
    const float* fb = g_f + b*C4*NN;
    for (int c = 0; c < C4; c++) {
        __syncthreads();
        for (int l = tid; l < 384; l += 256) {
            int r = l >> 6, ww = l & 63;
            int hh = h0 - 1 + r;
            smf[r][ww] = (hh >= 0 && hh < HH) ? fb[c*NN + hh*64 + ww] : 0.f;
        }
        __syncthreads();
        #pragma unroll
        for (int dh = 0; dh < 3; dh++) {
            float w0 = wsh[c*9+dh*3+0], w1 = wsh[c*9+dh*3+1], w2 = wsh[c*9+dh*3+2];
            const float* row = smf[lh + dh];
            float vm = (lw > 0)  ? row[lw-1] : 0.f;
            float vc = row[lw];
            float vp = (lw < 63) ? row[lw+1] : 0.f;
            acc += w0*vm + w1*vc + w2*vp;
        }
    }
    g_sa[b*NN + (h0+lh)*64 + lw] = 1.f/(1.f + __expf(-acc));
}

// ================= top-k (set semantics) =================
__device__ __forceinline__ unsigned int ford(float f) {
    unsigned int u = __float_as_uint(f);
    return (u & 0x80000000u) ? ~u : (u | 0x80000000u);
}
__global__ void k_topk() {
    __shared__ unsigned long long keys[NN];
    int b = blockIdx.x, tid = threadIdx.x;
    for (int l = tid; l < NN; l += 1024) {
        unsigned int o = ford(g_score[b*NN + l]) ^ 0xFFFFFFFFu;
        keys[l] = ((unsigned long long)o << 32) | (unsigned int)l;
    }
    __syncthreads();
    for (int kk = 2; kk <= NN; kk <<= 1) {
        for (int j = kk >> 1; j > 0; j >>= 1) {
            for (int t = tid; t < NN/2; t += 1024) {
                int i = 2*t - (t & (j-1));
                int l = i + j;
                bool up = ((i & kk) == 0);
                unsigned long long a = keys[i], c = keys[l];
                if ((a > c) == up) { keys[i] = c; keys[l] = a; }
            }
            __syncthreads();
        }
    }
    for (int l = tid; l < NN; l += 1024) {
        int tok = (int)(keys[l] & 0xFFFFFFFFu);
        if (l < NKEEP) { g_keep[b*NKEEP + l] = tok; g_pos[b*NN + tok] = l; }
        else g_pos[b*NN + tok] = -1;
    }
}

__global__ void k_wprep() {
    int l = blockIdx.x*256 + threadIdx.x;
    if (l >= BB*NN) return;
    int n = l & (NN - 1);
    int b = l >> 12;
    int h = n >> 6, w = n & 63;
    float sx = (float)w + g_off[(b*2 + 0)*NN + n];
    float sy = (float)h + g_off[(b*2 + 1)*NN + n];
    float x0 = floorf(sx), y0 = floorf(sy);
    float wx = sx - x0, wy = sy - y0;
    #pragma unroll
    for (int r = 0; r < 4; r++) {
        float xi = x0 + (float)(r & 1);
        float yi = y0 + (float)(r >> 1);
        bool valid = (xi >= 0.f) && (xi <= (float)(WW-1)) && (yi >= 0.f) && (yi <= (float)(HH-1));
        int xc = (int)fminf(fmaxf(xi, 0.f), (float)(WW-1));
        int yc = (int)fminf(fmaxf(yi, 0.f), (float)(HH-1));
        float wt = ((r & 1) ? wx : 1.f - wx) * ((r >> 1) ? wy : 1.f - wy);
        g_widx[l*4 + r] = yc*WW + xc;
        g_wwt[l*4 + r]  = valid ? wt : 0.f;
    }
}

__global__ void k_kimgt() {
    int b = blockIdx.y;
    int n = blockIdx.x*2 + threadIdx.x/192;
    int c = threadIdx.x % 192;
    int4   wi = *(const int4*)&g_widx[(b*NN + n)*4];
    float4 wt = *(const float4*)&g_wwt[(b*NN + n)*4];
    const float* xt = g_xt + (size_t)b*NN*CC;
    float v = xt[(size_t)n*CC + c]
            + wt.x*xt[(size_t)wi.x*CC + c] + wt.y*xt[(size_t)wi.y*CC + c]
            + wt.z*xt[(size_t)wi.z*CC + c] + wt.w*xt[(size_t)wi.w*CC + c];
    g_kimgt[((size_t)b*NN + n)*CC + c] = v;
}

// ================= fill non-kept tokens: otokT = vt * sa =================
__global__ void k_fill() {
    int b = blockIdx.y;
    int n = blockIdx.x*2 + threadIdx.x/192;
    int c = threadIdx.x % 192;
    if (g_pos[b*NN + n] >= 0) return;
    g_otokT[((size_t)b*NN + n)*CC + c] =
        g_vt[((size_t)b*NN + n)*CC + c] * g_sa[b*NN + n];
}

// ================= token-major depthwise 3x3 + gelu*ca + residual =================
__global__ void __launch_bounds__(192) k_dwT(const float* __restrict__ csw, const float* __restrict__ csb) {
    extern __shared__ float sdw[];
    float* tile = sdw;            // [100][192]
    float* wsm = sdw + 100*192;   // [192*9]
    int b = blockIdx.y;
    int t = blockIdx.x;
    int th0 = (t >> 3) * 8, tw0 = (t & 7) * 8;
    int tid = threadIdx.x;
    for (int l = tid; l < 192*9; l += 192) wsm[l] = csw[l];
    const float* inb = g_otokT + (size_t)b*NN*CC;
    for (int l = tid; l < 100*48; l += 192) {
        int pos = l / 48, c4v = (l % 48)*4;
        int hh = th0 - 1 + pos/10, ww = tw0 - 1 + pos%10;
        float4 v = (hh >= 0 && hh < 64 && ww >= 0 && ww < 64)
            ? *(const float4*)(inb + ((size_t)(hh*64+ww))*CC + c4v)
            : make_float4(0.f,0.f,0.f,0.f);
        *(float4*)&tile[pos*192 + c4v] = v;
    }
    __syncthreads();

    int c4 = (tid % 48) * 4;
    int pxb = tid / 48;           // 0..3
    // cache weights, bias, ca for this channel group
    float wreg[9][4];
    #pragma unroll
    for (int tap = 0; tap < 9; tap++)
        #pragma unroll
        for (int e = 0; e < 4; e++)
            wreg[tap][e] = wsm[(c4+e)*9 + tap];
    float bv[4], cav[4];
    #pragma unroll
    for (int e = 0; e < 4; e++) { bv[e] = csb[c4+e]; cav[e] = g_ca[b*CC + c4 + e]; }

    float* outb = g_out2T + (size_t)b*NN*CC;
    for (int j = 0; j < 16; j++) {
        int px = pxb*16 + j;
        int lh = px >> 3, lw2 = px & 7;
        float acc[4] = {bv[0], bv[1], bv[2], bv[3]};
        #pragma unroll
        for (int dh = 0; dh < 3; dh++)
            #pragma unroll
            for (int dw_ = 0; dw_ < 3; dw_++) {
                int pos = (lh+dh)*10 + (lw2+dw_);
                float4 v = *(const float4*)&tile[pos*192 + c4];
                int tap = dh*3 + dw_;
                acc[0] += wreg[tap][0]*v.x; acc[1] += wreg[tap][1]*v.y;
                acc[2] += wreg[tap][2]*v.z; acc[3] += wreg[tap][3]*v.w;
            }
        float4 cen = *(const float4*)&tile[((lh+1)*10 + (lw2+1))*192 + c4];
        float* cenp = (float*)&cen;
        float4 o;
        float* op = (float*)&o;
        #pragma unroll
        for (int e = 0; e < 4; e++) {
            float a = acc[e];
            float x3 = a*a*a;
            float gg = 0.5f*a*(1.0f + tanhf(0.7978845608028654f*(a + 0.044715f*x3)));
            op[e] = gg * cav[e] + cenp[e];
        }
        int n = (th0+lh)*64 + (tw0+lw2);
        *(float4*)(outb + (size_t)n*CC + c4) = o;
    }
}

// ================= host =================
extern "C" void kernel_launch(void* const* d_in, const int* in_sizes, int n_in,
                              void* d_out, int out_size) {
    const float* x     = (const float*)d_in[0];
    const float* in_w  = (const float*)d_in[1];
    const float* in_b  = (const float*)d_in[2];
    const float* ln_w  = (const float*)d_in[3];
    const float* ln_b  = (const float*)d_in[4];
    const float* ow1   = (const float*)d_in[5];
    const float* ob1   = (const float*)d_in[6];
    const float* ow2   = (const float*)d_in[7];
    const float* ob2   = (const float*)d_in[8];
    const float* caw   = (const float*)d_in[9];
    const float* cab   = (const float*)d_in[10];
    const float* saw   = (const float*)d_in[11];
    const float* sab   = (const float*)d_in[12];
    const float* mw1   = (const float*)d_in[13];
    const float* mb1   = (const float*)d_in[14];
    const float* mw2   = (const float*)d_in[15];
    const float* mb2   = (const float*)d_in[16];
    const float* v_w   = (const float*)d_in[17];
    const float* v_b   = (const float*)d_in[18];
    const float* q_w   = (const float*)d_in[19];
    const float* q_b   = (const float*)d_in[20];
    const float* k_w   = (const float*)d_in[21];
    const float* k_b   = (const float*)d_in[22];
    const float* cs_w  = (const float*)d_in[23];
    const float* cs_b  = (const float*)d_in[24];
    const float* out_w = (const float*)d_in[25];
    const float* out_b = (const float*)d_in[26];
    float* out = (float*)d_out;

    float *p_xt, *p_kimgt, *p_vt, *p_q1, *p_k1, *p_out2T, *p_outT;
    int *p_keep;
    cudaGetSymbolAddress((void**)&p_xt, g_xt);
    cudaGetSymbolAddress((void**)&p_kimgt, g_kimgt);
    cudaGetSymbolAddress((void**)&p_vt, g_vt);
    cudaGetSymbolAddress((void**)&p_q1, g_q1);
    cudaGetSymbolAddress((void**)&p_k1, g_k1);
    cudaGetSymbolAddress((void**)&p_out2T, g_out2T);
    cudaGetSymbolAddress((void**)&p_outT, g_outT);
    cudaGetSymbolAddress((void**)&p_keep, g_keep);

    const int SMEM_G = (2*AS_SZ + 2*BS_SZ) * 4;
    cudaFuncSetAttribute(k_gemm<false>, cudaFuncAttributeMaxDynamicSharedMemorySize, SMEM_G);
    cudaFuncSetAttribute(k_gemm<true>,  cudaFuncAttributeMaxDynamicSharedMemorySize, SMEM_G);
    const int SMEM_F = F_TOT * 4;  // 200192
    cudaFuncSetAttribute(k_flash, cudaFuncAttributeMaxDynamicSharedMemorySize, SMEM_F);
    const int SMEM_DW = (100*192 + 192*9) * 4;  // 83712
    cudaFuncSetAttribute(k_dwT, cudaFuncAttributeMaxDynamicSharedMemorySize, SMEM_DW);

    dim3 tb(32, 8);
    k_T<<<dim3(NN/32, CC/32, BB), tb>>>(x, p_xt, CC, NN);
    k_front<<<dim3(NN/32, BB), 256>>>(x, in_w, in_b, ln_w, ln_b,
                                      ow1, ob1, ow2, ob2, mw1, mb1, mw2, mb2);
    k_fmean<<<BB*C4, 256>>>();
    k_ca<<<(BB*CC + 255)/256, 256>>>(caw, cab);
    k_sa2<<<dim3(HH/4, BB), 256>>>(saw, sab);
    k_topk<<<BB, 1024>>>();
    k_wprep<<<BB*NN/256, 256>>>();
    k_kimgt<<<dim3(NN/2, BB), 384>>>();

    float scale = rsqrtf((float)CC);
    k_gemm<false><<<dim3(NN/128, 3, BB), 256, SMEM_G>>>(
        p_xt, (size_t)NN*CC, v_w, 0, v_b, nullptr, p_vt, (size_t)NN*CC, CC, CC, 1.0f);
    k_gemm<true><<<dim3(NKEEP/128, 3, BB), 256, SMEM_G>>>(
        p_xt, (size_t)NN*CC, q_w, 0, q_b, p_keep, p_q1, (size_t)NKEEP*CC, CC, CC, scale);
    k_gemm<true><<<dim3(NKEEP/128, 3, BB), 256, SMEM_G>>>(
        p_kimgt, (size_t)NN*CC, k_w, 0, k_b, p_keep, p_k1, (size_t)NKEEP*CC, CC, CC, 1.0f);
    k_gT<<<dim3(NKEEP/32, CC/32, BB), tb>>>();
    k_fill<<<dim3(NN/2, BB), 384>>>();
    k_flash<<<dim3(NKEEP/128, BB), 256, SMEM_F>>>();
    k_dwT<<<dim3(64, BB), 192, SMEM_DW>>>(cs_w, cs_b);
    k_gemm<false><<<dim3(NN/128, 3, BB), 256, SMEM_G>>>(
        p_out2T, (size_t)NN*CC, out_w, 0, out_b, nullptr, p_outT, (size_t)NN*CC, CC, CC, 1.0f);
    k_T<<<dim3(CC/32, NN/32, BB), tb>>>(p_outT, out, NN, CC);
}

// round 5
// speedup vs baseline: 3.2102x; 1.0338x over previous
#include <cuda_runtime.h>
#include <math.h>
#include <stdint.h>

#define BB 8
#define CC 192
#define HH 64
#define WW 64
#define NN 4096
#define C4 48
#define CD 194
#define C8 24
#define NKEEP 2048

// ================= scratch =================
__device__ float g_f[BB*C4*NN];
__device__ float g_off[BB*2*NN];
__device__ float g_score[BB*NN];
__device__ int   g_keep[BB*NKEEP];
__device__ int   g_pos[BB*NN];
__device__ float g_ca[BB*CC];
__device__ float g_sa[BB*NN];
__device__ int   g_widx[BB*NN*4];
__device__ float g_wwt[BB*NN*4];
__device__ float g_xt[(size_t)BB*NN*CC];
__device__ float g_vt[(size_t)BB*NN*CC];
__device__ float g_q1[(size_t)BB*NKEEP*CC];
__device__ float g_k1[(size_t)BB*NKEEP*CC];
__device__ float g_v1t[(size_t)BB*CC*NKEEP];
__device__ float g_otokT[(size_t)BB*NN*CC];
__device__ float g_out2T[(size_t)BB*NN*CC];

// ================= tf32 mma helpers =================
__device__ __forceinline__ uint32_t to_tf32(float f) {
    uint32_t u;
    asm("cvt.rna.tf32.f32 %0, %1;" : "=r"(u) : "f"(f));
    return u;
}
__device__ __forceinline__ uint4 cvt4(float4 v) {
    return make_uint4(to_tf32(v.x), to_tf32(v.y), to_tf32(v.z), to_tf32(v.w));
}
__device__ __forceinline__ void mma_tf32(float* d, const uint32_t* a, uint32_t b0, uint32_t b1) {
    asm volatile("mma.sync.aligned.m16n8k8.row.col.f32.tf32.tf32.f32 "
        "{%0,%1,%2,%3}, {%4,%5,%6,%7}, {%8,%9}, {%0,%1,%2,%3};"
        : "+f"(d[0]), "+f"(d[1]), "+f"(d[2]), "+f"(d[3])
        : "r"(a[0]), "r"(a[1]), "r"(a[2]), "r"(a[3]), "r"(b0), "r"(b1));
}

// ================= GEMM: Out[m,n]=(A[m,:]·B[n,:]+bias[n])*scale =================
// AMODE: 0 plain, 1 gather rows by gidx, 2 gather + flow-warp A
// TO: transposed output epilogue (writes Out[(b*CC+n)*NN+m])
#define KS 36
#define AS_SZ (128*KS)
#define BS_SZ (64*KS)
template<int AMODE, bool TO>
__global__ void __launch_bounds__(256, 2) k_gemm(
    const float* __restrict__ A, size_t bsA,
    const float* __restrict__ Bm, size_t bsB,
    const float* __restrict__ bias,
    const int* __restrict__ gidx,
    float* __restrict__ Out, size_t bsOut, int Ntot, int K, float scale)
{
    extern __shared__ uint32_t sm[];
    uint32_t* As = sm;
    uint32_t* Bs = sm + 2*AS_SZ;
    int tid = threadIdx.x;
    int lane = tid & 31, wid = tid >> 5;
    int wm = wid & 3, wn = wid >> 2;
    int g = lane >> 2, t4 = lane & 3;
    int b = blockIdx.z;
    int m0 = blockIdx.x * 128, n0 = blockIdx.y * 64;

    const float* Ab = A + (size_t)b * bsA;
    const float* Bb = Bm + (size_t)b * bsB;

    const float* aptr[4];
    const float* np[4][4];
    float4 wt4[4];
    int ar[4], ac[4];
    #pragma unroll
    for (int i = 0; i < 4; i++) {
        int idx = tid + i*256;
        ar[i] = idx >> 3; ac[i] = (idx & 7) << 2;
        int grow = (AMODE >= 1) ? gidx[b*NKEEP + m0 + ar[i]] : (m0 + ar[i]);
        aptr[i] = Ab + (size_t)grow * K + ac[i];
        if (AMODE == 2) {
            int4 wi = *(const int4*)&g_widx[((size_t)b*NN + grow)*4];
            wt4[i]  = *(const float4*)&g_wwt[((size_t)b*NN + grow)*4];
            np[i][0] = Ab + (size_t)wi.x * K + ac[i];
            np[i][1] = Ab + (size_t)wi.y * K + ac[i];
            np[i][2] = Ab + (size_t)wi.z * K + ac[i];
            np[i][3] = Ab + (size_t)wi.w * K + ac[i];
        }
    }
    const float* bptr[2];
    int br[2], bc[2];
    #pragma unroll
    for (int i = 0; i < 2; i++) {
        int idx = tid + i*256;
        br[i] = idx >> 3; bc[i] = (idx & 7) << 2;
        bptr[i] = Bb + (size_t)(n0 + br[i]) * K + bc[i];
    }

    float acc[2][4][4];
    #pragma unroll
    for (int mt = 0; mt < 2; mt++)
        #pragma unroll
        for (int nt = 0; nt < 4; nt++)
            #pragma unroll
            for (int e = 0; e < 4; e++) acc[mt][nt][e] = 0.f;

    float4 pa[4], pb[2];
    #pragma unroll
    for (int i = 0; i < 4; i++) pa[i] = *(const float4*)(aptr[i]);
    #pragma unroll
    for (int i = 0; i < 2; i++) pb[i] = *(const float4*)(bptr[i]);

    #pragma unroll
    for (int i = 0; i < 4; i++) {
        float4 v = pa[i];
        if (AMODE == 2) {
            const float* wtp = (const float*)&wt4[i];
            #pragma unroll
            for (int j = 0; j < 4; j++) {
                float4 nv = *(const float4*)(np[i][j]);
                v.x += wtp[j]*nv.x; v.y += wtp[j]*nv.y;
                v.z += wtp[j]*nv.z; v.w += wtp[j]*nv.w;
            }
        }
        *(uint4*)(As + ar[i]*KS + ac[i]) = cvt4(v);
    }
    #pragma unroll
    for (int i = 0; i < 2; i++) *(uint4*)(Bs + br[i]*KS + bc[i]) = cvt4(pb[i]);
    __syncthreads();

    int nkt = K >> 5;
    for (int kt = 0; kt < nkt; kt++) {
        int buf = kt & 1;
        int off = (kt + 1) << 5;
        if (kt + 1 < nkt) {
            #pragma unroll
            for (int i = 0; i < 4; i++) pa[i] = *(const float4*)(aptr[i] + off);
            #pragma unroll
            for (int i = 0; i < 2; i++) pb[i] = *(const float4*)(bptr[i] + off);
        }
        const uint32_t* Asb = As + buf*AS_SZ;
        const uint32_t* Bsb = Bs + buf*BS_SZ;
        #pragma unroll
        for (int ks = 0; ks < 4; ks++) {
            int k0 = ks*8;
            uint32_t af[2][4];
            #pragma unroll
            for (int mt = 0; mt < 2; mt++) {
                int m = wm*32 + mt*16;
                af[mt][0] = Asb[(m+g)*KS   + k0 + t4];
                af[mt][1] = Asb[(m+g+8)*KS + k0 + t4];
                af[mt][2] = Asb[(m+g)*KS   + k0 + t4 + 4];
                af[mt][3] = Asb[(m+g+8)*KS + k0 + t4 + 4];
            }
            #pragma unroll
            for (int nt = 0; nt < 4; nt++) {
                int n = wn*32 + nt*8;
                uint32_t b0 = Bsb[(n+g)*KS + k0 + t4];
                uint32_t b1 = Bsb[(n+g)*KS + k0 + t4 + 4];
                mma_tf32(acc[0][nt], af[0], b0, b1);
                mma_tf32(acc[1][nt], af[1], b0, b1);
            }
        }
        if (kt + 1 < nkt) {
            uint32_t* Asn = As + (buf^1)*AS_SZ;
            uint32_t* Bsn = Bs + (buf^1)*BS_SZ;
            #pragma unroll
            for (int i = 0; i < 4; i++) {
                float4 v = pa[i];
                if (AMODE == 2) {
                    const float* wtp = (const float*)&wt4[i];
                    #pragma unroll
                    for (int j = 0; j < 4; j++) {
                        float4 nv = *(const float4*)(np[i][j] + off);
                        v.x += wtp[j]*nv.x; v.y += wtp[j]*nv.y;
                        v.z += wtp[j]*nv.z; v.w += wtp[j]*nv.w;
                    }
                }
                *(uint4*)(Asn + ar[i]*KS + ac[i]) = cvt4(v);
            }
            #pragma unroll
            for (int i = 0; i < 2; i++) *(uint4*)(Bsn + br[i]*KS + bc[i]) = cvt4(pb[i]);
        }
        __syncthreads();
    }

    if (!TO) {
        float* Ob = Out + (size_t)b * bsOut;
        #pragma unroll
        for (int nt = 0; nt < 4; nt++) {
            int ncol = n0 + wn*32 + nt*8 + 2*t4;
            float b0v = bias ? bias[ncol]     : 0.f;
            float b1v = bias ? bias[ncol + 1] : 0.f;
            #pragma unroll
            for (int mt = 0; mt < 2; mt++) {
                int row0 = m0 + wm*32 + mt*16 + g;
                float2 o0 = make_float2((acc[mt][nt][0] + b0v) * scale, (acc[mt][nt][1] + b1v) * scale);
                float2 o1 = make_float2((acc[mt][nt][2] + b0v) * scale, (acc[mt][nt][3] + b1v) * scale);
                *(float2*)&Ob[(size_t)row0 * Ntot + ncol]     = o0;
                *(float2*)&Ob[(size_t)(row0+8) * Ntot + ncol] = o1;
            }
        }
    } else {
        // stage [n(64) x m(128)] in smem, then coalesced channel-major writes
        float* st = (float*)sm;   // 64 x 132
        #pragma unroll
        for (int nt = 0; nt < 4; nt++) {
            int nl = wn*32 + nt*8 + 2*t4;
            float b0v = bias ? bias[n0 + nl]     : 0.f;
            float b1v = bias ? bias[n0 + nl + 1] : 0.f;
            #pragma unroll
            for (int mt = 0; mt < 2; mt++) {
                int ml = wm*32 + mt*16 + g;
                st[nl*132 + ml]         = (acc[mt][nt][0] + b0v) * scale;
                st[(nl+1)*132 + ml]     = (acc[mt][nt][1] + b1v) * scale;
                st[nl*132 + ml + 8]     = (acc[mt][nt][2] + b0v) * scale;
                st[(nl+1)*132 + ml + 8] = (acc[mt][nt][3] + b1v) * scale;
            }
        }
        __syncthreads();
        for (int l = tid; l < 64*32; l += 256) {
            int r = l >> 5, c4v = (l & 31) << 2;
            float4 v = *(float4*)&st[r*132 + c4v];
            *(float4*)&Out[((size_t)b*CC + n0 + r)*NN + m0 + c4v] = v;
        }
    }
}

// ================= flash attention (validated R4) =================
#define F_QS 0
#define F_KS 25088
#define F_VS 31360
#define F_PS 45184
#define F_SC 49792
#define F_LB 49920
#define F_TOT 50048
#define NTILES (NKEEP/32)

__global__ void __launch_bounds__(256, 1) k_flash() {
    extern __shared__ uint32_t sm[];
    uint32_t* Qs = sm + F_QS;
    uint32_t* Ksm = sm + F_KS;
    uint32_t* Vsm = sm + F_VS;
    uint32_t* Ps = sm + F_PS;
    float* scaleb = (float*)(sm + F_SC);
    float* lb = (float*)(sm + F_LB);

    int tid = threadIdx.x, lane = tid & 31, w = tid >> 5;
    int g = lane >> 2, t4 = lane & 3;
    int b = blockIdx.y, m0 = blockIdx.x * 128;

    const float* Qg = g_q1 + ((size_t)b*NKEEP + m0)*CC;
    const float* Kg = g_k1 + (size_t)b*NKEEP*CC;
    const float* Vg = g_v1t + (size_t)b*CC*NKEEP;

    #pragma unroll
    for (int j = 0; j < 24; j++) {
        int idx = tid + j*256;
        int r = idx/48, c4v = (idx%48)*4;
        float4 v = *(const float4*)(Qg + (size_t)r*CC + c4v);
        *(uint4*)&Qs[r*196 + c4v] = cvt4(v);
    }

    int rK[6], cK[6], cV[6], kV[6];
    #pragma unroll
    for (int j = 0; j < 6; j++) {
        int idx = tid + j*256;
        rK[j] = idx/48; cK[j] = (idx%48)*4;
        cV[j] = idx>>3; kV[j] = (idx&7)*4;
    }

    float4 pk[6], pv[6];
    #pragma unroll
    for (int j = 0; j < 6; j++) {
        pk[j] = *(const float4*)(Kg + (size_t)rK[j]*CC + cK[j]);
        pv[j] = *(const float4*)(Vg + (size_t)cV[j]*NKEEP + kV[j]);
    }
    #pragma unroll
    for (int j = 0; j < 6; j++) {
        *(uint4*)&Ksm[rK[j]*196 + cK[j]] = cvt4(pk[j]);
        *(uint4*)&Vsm[cV[j]*36 + kV[j]] = cvt4(pv[j]);
    }
    __syncthreads();

    int wm = w >> 1, wn = w & 1;
    float oat[3][8][4];
    #pragma unroll
    for (int mt = 0; mt < 3; mt++)
        #pragma unroll
        for (int nt = 0; nt < 8; nt++)
            #pragma unroll
            for (int e = 0; e < 4; e++) oat[mt][nt][e] = 0.f;
    float m_r0 = -1e30f, m_r1 = -1e30f, l_r0 = 0.f, l_r1 = 0.f;

    int qr0 = w * 16;
    #pragma unroll 1
    for (int kt = 0; kt < NTILES; kt++) {
        int buf = kt & 1;
        if (kt + 1 < NTILES) {
            int k0 = (kt + 1) * 32;
            #pragma unroll
            for (int j = 0; j < 6; j++) {
                pk[j] = *(const float4*)(Kg + (size_t)(k0 + rK[j])*CC + cK[j]);
                pv[j] = *(const float4*)(Vg + (size_t)cV[j]*NKEEP + k0 + kV[j]);
            }
        }
        float sacc[4][4];
        #pragma unroll
        for (int nt = 0; nt < 4; nt++)
            #pragma unroll
            for (int e = 0; e < 4; e++) sacc[nt][e] = 0.f;
        #pragma unroll
        for (int ks = 0; ks < 24; ks++) {
            int k0 = ks*8;
            uint32_t a[4];
            a[0] = Qs[(qr0+g)*196   + k0 + t4];
            a[1] = Qs[(qr0+g+8)*196 + k0 + t4];
            a[2] = Qs[(qr0+g)*196   + k0 + t4 + 4];
            a[3] = Qs[(qr0+g+8)*196 + k0 + t4 + 4];
            #pragma unroll
            for (int nt = 0; nt < 4; nt++) {
                uint32_t b0 = Ksm[(nt*8+g)*196 + k0 + t4];
                uint32_t b1 = Ksm[(nt*8+g)*196 + k0 + t4 + 4];
                mma_tf32(sacc[nt], a, b0, b1);
            }
        }
        float mx0 = -1e30f, mx1 = -1e30f;
        #pragma unroll
        for (int nt = 0; nt < 4; nt++) {
            mx0 = fmaxf(mx0, fmaxf(sacc[nt][0], sacc[nt][1]));
            mx1 = fmaxf(mx1, fmaxf(sacc[nt][2], sacc[nt][3]));
        }
        mx0 = fmaxf(mx0, __shfl_xor_sync(~0u, mx0, 1));
        mx0 = fmaxf(mx0, __shfl_xor_sync(~0u, mx0, 2));
        mx1 = fmaxf(mx1, __shfl_xor_sync(~0u, mx1, 1));
        mx1 = fmaxf(mx1, __shfl_xor_sync(~0u, mx1, 2));
        float mn0 = fmaxf(m_r0, mx0), mn1 = fmaxf(m_r1, mx1);
        float al0 = __expf(m_r0 - mn0), al1 = __expf(m_r1 - mn1);
        float s0 = 0.f, s1 = 0.f;
        #pragma unroll
        for (int nt = 0; nt < 4; nt++) {
            float e00 = __expf(sacc[nt][0] - mn0);
            float e01 = __expf(sacc[nt][1] - mn0);
            float e10 = __expf(sacc[nt][2] - mn1);
            float e11 = __expf(sacc[nt][3] - mn1);
            s0 += e00 + e01; s1 += e10 + e11;
            uint2 p0 = make_uint2(to_tf32(e00), to_tf32(e01));
            uint2 p1 = make_uint2(to_tf32(e10), to_tf32(e11));
            *(uint2*)&Ps[(qr0+g)*36   + nt*8 + 2*t4] = p0;
            *(uint2*)&Ps[(qr0+g+8)*36 + nt*8 + 2*t4] = p1;
        }
        s0 += __shfl_xor_sync(~0u, s0, 1); s0 += __shfl_xor_sync(~0u, s0, 2);
        s1 += __shfl_xor_sync(~0u, s1, 1); s1 += __shfl_xor_sync(~0u, s1, 2);
        l_r0 = l_r0 * al0 + s0;
        l_r1 = l_r1 * al1 + s1;
        m_r0 = mn0; m_r1 = mn1;
        if (t4 == 0) {
            scaleb[qr0+g]   = al0;
            scaleb[qr0+g+8] = al1;
            if (kt == NTILES-1) { lb[qr0+g] = l_r0; lb[qr0+g+8] = l_r1; }
        }
        __syncthreads();
        if (kt + 1 < NTILES) {
            #pragma unroll
            for (int j = 0; j < 6; j++)
                *(uint4*)&Ksm[rK[j]*196 + cK[j]] = cvt4(pk[j]);
        }
        #pragma unroll
        for (int nt = 0; nt < 8; nt++) {
            int qc = wn*64 + nt*8 + 2*t4;
            float a0 = scaleb[qc], a1 = scaleb[qc+1];
            #pragma unroll
            for (int mt = 0; mt < 3; mt++) {
                oat[mt][nt][0] *= a0; oat[mt][nt][1] *= a1;
                oat[mt][nt][2] *= a0; oat[mt][nt][3] *= a1;
            }
        }
        const uint32_t* Vb = Vsm + buf*6912;
        #pragma unroll
        for (int ks = 0; ks < 4; ks++) {
            int k0 = ks*8;
            uint32_t bfr[8][2];
            #pragma unroll
            for (int nt = 0; nt < 8; nt++) {
                bfr[nt][0] = Ps[(wn*64 + nt*8 + g)*36 + k0 + t4];
                bfr[nt][1] = Ps[(wn*64 + nt*8 + g)*36 + k0 + t4 + 4];
            }
            #pragma unroll
            for (int mt = 0; mt < 3; mt++) {
                int cr = wm*48 + mt*16;
                uint32_t a[4];
                a[0] = Vb[(cr+g)*36   + k0 + t4];
                a[1] = Vb[(cr+g+8)*36 + k0 + t4];
                a[2] = Vb[(cr+g)*36   + k0 + t4 + 4];
                a[3] = Vb[(cr+g+8)*36 + k0 + t4 + 4];
                #pragma unroll
                for (int nt = 0; nt < 8; nt++)
                    mma_tf32(oat[mt][nt], a, bfr[nt][0], bfr[nt][1]);
            }
        }
        if (kt + 1 < NTILES) {
            uint32_t* Vn = Vsm + (buf^1)*6912;
            #pragma unroll
            for (int j = 0; j < 6; j++)
                *(uint4*)&Vn[cV[j]*36 + kV[j]] = cvt4(pv[j]);
        }
        __syncthreads();
    }

    float* Ot = (float*)Qs;
    #pragma unroll
    for (int nt = 0; nt < 8; nt++) {
        int qc = wn*64 + nt*8 + 2*t4;
        float li0 = 1.f / lb[qc], li1 = 1.f / lb[qc+1];
        #pragma unroll
        for (int mt = 0; mt < 3; mt++) {
            int cr = wm*48 + mt*16;
            Ot[qc*196 + cr+g]       = oat[mt][nt][0] * li0;
            Ot[(qc+1)*196 + cr+g]   = oat[mt][nt][1] * li1;
            Ot[qc*196 + cr+g+8]     = oat[mt][nt][2] * li0;
            Ot[(qc+1)*196 + cr+g+8] = oat[mt][nt][3] * li1;
        }
    }
    __syncthreads();
    #pragma unroll
    for (int j = 0; j < 24; j++) {
        int idx = tid + j*256;
        int r = idx/48, c4v = (idx%48)*4;
        int tok = g_keep[b*NKEEP + m0 + r];
        float4 v = *(float4*)&Ot[r*196 + c4v];
        *(float4*)&g_otokT[((size_t)b*NN + tok)*CC + c4v] = v;
    }
}

// ================= gather-transpose v1t[c][m] = vt[keep[m]][c] =================
__global__ void k_gT() {
    __shared__ float t[32][33];
    int b = blockIdx.z;
    int m0 = blockIdx.x * 32, c0 = blockIdx.y * 32;
    int tx = threadIdx.x, ty = threadIdx.y;
    #pragma unroll
    for (int j = ty; j < 32; j += 8) {
        int tok = g_keep[b*NKEEP + m0 + j];
        t[j][tx] = g_vt[((size_t)b*NN + tok)*CC + c0 + tx];
    }
    __syncthreads();
    #pragma unroll
    for (int j = ty; j < 32; j += 8)
        g_v1t[((size_t)b*CC + c0 + j)*NKEEP + m0 + tx] = t[tx][j];
}

// ================= front end (+ fused x transpose) =================
__global__ void k_front(const float* __restrict__ x,
    const float* __restrict__ in_w, const float* __restrict__ in_b,
    const float* __restrict__ ln_w, const float* __restrict__ ln_b,
    const float* __restrict__ ow1, const float* __restrict__ ob1,
    const float* __restrict__ ow2, const float* __restrict__ ob2,
    const float* __restrict__ mw1, const float* __restrict__ mb1,
    const float* __restrict__ mw2, const float* __restrict__ mb2)
{
    __shared__ float cond[CD][33];
    __shared__ float fb[C4][33];
    __shared__ float mu_s[32], rs_s[32];
    __shared__ float hb[C8][33];
    int b = blockIdx.y;
    int n0 = blockIdx.x * 32;
    int tid = threadIdx.x;

    for (int l = tid; l < CC*32; l += 256) {
        int c = l >> 5, px = l & 31;
        cond[c][px] = x[((b*CC + c) << 12) + n0 + px];
    }
    if (tid < 32) {
        int n = n0 + tid;
        int h = n >> 6, w = n & 63;
        cond[192][tid] = -1.0f + 2.0f * (float)w / 63.0f;
        cond[193][tid] = -1.0f + 2.0f * (float)h / 63.0f;
    }
    __syncthreads();

    // fused transpose writeback: xt[n][c]
    for (int l = tid; l < 32*CC; l += 256) {
        int px = l / CC, c = l % CC;
        g_xt[((size_t)b*NN + n0 + px)*CC + c] = cond[c][px];
    }

    int px = tid & 31;
    for (int pass = 0; pass < 6; pass++) {
        int c = pass*8 + (tid >> 5);
        float acc = in_b[c];
        const float* wr = in_w + c*CD;
        #pragma unroll 2
        for (int k = 0; k < CD; k++) acc += wr[k] * cond[k][px];
        fb[c][px] = acc;
    }
    __syncthreads();

    if (tid < 32) {
        float s = 0.f, s2 = 0.f;
        for (int c = 0; c < C4; c++) { float v = fb[c][tid]; s += v; s2 += v*v; }
        float mu = s / (float)C4;
        float var = s2 / (float)C4 - mu*mu;
        mu_s[tid] = mu;
        rs_s[tid] = rsqrtf(var + 1e-6f);
    }
    __syncthreads();

    for (int l = tid; l < C4*32; l += 256) {
        int c = l >> 5, p = l & 31;
        float v = (fb[c][p] - mu_s[p]) * rs_s[p] * ln_w[c] + ln_b[c];
        v = v > 0.f ? v : 0.1f*v;
        fb[c][p] = v;
        g_f[(b*C4 + c)*NN + n0 + p] = v;
    }
    __syncthreads();

    for (int l = tid; l < C8*32; l += 256) {
        int j = l >> 5, p = l & 31;
        float acc = ob1[j];
        const float* wr = ow1 + j*C4;
        #pragma unroll 4
        for (int c = 0; c < C4; c++) acc += wr[c] * fb[c][p];
        hb[j][p] = acc > 0.f ? acc : 0.1f*acc;
    }
    __syncthreads();

    if (tid < 64) {
        int d = tid >> 5, p = tid & 31;
        float acc = ob2[d];
        const float* wr = ow2 + d*C8;
        #pragma unroll
        for (int j = 0; j < C8; j++) acc += wr[j] * hb[j][p];
        g_off[(b*2 + d)*NN + n0 + p] = tanhf(acc) * 8.0f;
    }
    if (tid >= 64 && tid < 96) {
        int p = tid - 64;
        float s = 0.f;
        for (int c = 0; c < C4; c++) s += fb[c][p];
        float t = s / (float)C4;
        float s1 = t * mw1[0] + mb1[0];
        s1 = s1 > 0.f ? s1 : 0.1f*s1;
        float l0 = s1 * mw2[0] + mb2[0];
        float l1 = s1 * mw2[1] + mb2[1];
        g_score[b*NN + n0 + p] = 1.0f / (1.0f + expf(l1 - l0));
    }
}

// ================= merged fmean + ca =================
__global__ void k_stats(const float* __restrict__ caw, const float* __restrict__ cab) {
    __shared__ float fm[C4];
    int b = blockIdx.x, tid = threadIdx.x;
    int w = tid >> 5, lane = tid & 31;
    for (int c = w; c < C4; c += 32) {
        const float* p = g_f + (b*C4 + c)*NN;
        float s = 0.f;
        for (int i = lane; i < NN; i += 32) s += p[i];
        #pragma unroll
        for (int o = 16; o; o >>= 1) s += __shfl_xor_sync(~0u, s, o);
        if (lane == 0) fm[c] = s / (float)NN;
    }
    __syncthreads();
    if (tid < CC) {
        float acc = cab[tid];
        #pragma unroll 4
        for (int c = 0; c < C4; c++) acc += caw[tid*C4 + c] * fm[c];
        g_ca[b*CC + tid] = 1.0f / (1.0f + __expf(-acc));
    }
}

// ================= sa: tiled 3x3 conv + sigmoid =================
__global__ void k_sa2(const float* __restrict__ saw, const float* __restrict__ sab) {
    __shared__ float wsh[C4*9];
    __shared__ float smf[6][64];
    int b = blockIdx.y, h0 = blockIdx.x*4;
    int tid = threadIdx.x;
    for (int l = tid; l < C4*9; l += 256) wsh[l] = saw[l];
    int lw = tid & 63, lh = tid >> 6;
    float acc = sab[0];
    const float* fb = g_f + b*C4*NN;
    for (int c = 0; c < C4; c++) {
        __syncthreads();
        for (int l = tid; l < 384; l += 256) {
            int r = l >> 6, ww = l & 63;
            int hh = h0 - 1 + r;
            smf[r][ww] = (hh >= 0 && hh < HH) ? fb[c*NN + hh*64 + ww] : 0.f;
        }
        __syncthreads();
        #pragma unroll
        for (int dh = 0; dh < 3; dh++) {
            float w0 = wsh[c*9+dh*3+0], w1 = wsh[c*9+dh*3+1], w2 = wsh[c*9+dh*3+2];
            const float* row = smf[lh + dh];
            float vm = (lw > 0)  ? row[lw-1] : 0.f;
            float vc = row[lw];
            float vp = (lw < 63) ? row[lw+1] : 0.f;
            acc += w0*vm + w1*vc + w2*vp;
        }
    }
    g_sa[b*NN + (h0+lh)*64 + lw] = 1.f/(1.f + __expf(-acc));
}

// ================= top-k (set semantics) =================
__device__ __forceinline__ unsigned int ford(float f) {
    unsigned int u = __float_as_uint(f);
    return (u & 0x80000000u) ? ~u : (u | 0x80000000u);
}
__global__ void k_topk() {
    __shared__ unsigned long long keys[NN];
    int b = blockIdx.x, tid = threadIdx.x;
    for (int l = tid; l < NN; l += 1024) {
        unsigned int o = ford(g_score[b*NN + l]) ^ 0xFFFFFFFFu;
        keys[l] = ((unsigned long long)o << 32) | (unsigned int)l;
    }
    __syncthreads();
    for (int kk = 2; kk <= NN; kk <<= 1) {
        for (int j = kk >> 1; j > 0; j >>= 1) {
            for (int t = tid; t < NN/2; t += 1024) {
                int i = 2*t - (t & (j-1));
                int l = i + j;
                bool up = ((i & kk) == 0);
                unsigned long long a = keys[i], c = keys[l];
                if ((a > c) == up) { keys[i] = c; keys[l] = a; }
            }
            __syncthreads();
        }
    }
    for (int l = tid; l < NN; l += 1024) {
        int tok = (int)(keys[l] & 0xFFFFFFFFu);
        if (l < NKEEP) { g_keep[b*NKEEP + l] = tok; g_pos[b*NN + tok] = l; }
        else g_pos[b*NN + tok] = -1;
    }
}

__global__ void k_wprep() {
    int l = blockIdx.x*256 + threadIdx.x;
    if (l >= BB*NN) return;
    int n = l & (NN - 1);
    int b = l >> 12;
    int h = n >> 6, w = n & 63;
    float sx = (float)w + g_off[(b*2 + 0)*NN + n];
    float sy = (float)h + g_off[(b*2 + 1)*NN + n];
    float x0 = floorf(sx), y0 = floorf(sy);
    float wx = sx - x0, wy = sy - y0;
    #pragma unroll
    for (int r = 0; r < 4; r++) {
        float xi = x0 + (float)(r & 1);
        float yi = y0 + (float)(r >> 1);
        bool valid = (xi >= 0.f) && (xi <= (float)(WW-1)) && (yi >= 0.f) && (yi <= (float)(HH-1));
        int xc = (int)fminf(fmaxf(xi, 0.f), (float)(WW-1));
        int yc = (int)fminf(fmaxf(yi, 0.f), (float)(HH-1));
        float wt = ((r & 1) ? wx : 1.f - wx) * ((r >> 1) ? wy : 1.f - wy);
        g_widx[l*4 + r] = yc*WW + xc;
        g_wwt[l*4 + r]  = valid ? wt : 0.f;
    }
}

// ================= token-major depthwise 3x3 + gelu*ca + residual (fused fill) =====
__global__ void __launch_bounds__(192) k_dwT(const float* __restrict__ csw, const float* __restrict__ csb) {
    extern __shared__ float sdw[];
    float* tile = sdw;            // [100][192]
    float* wsm = sdw + 100*192;   // [192*9]
    int b = blockIdx.y;
    int t = blockIdx.x;
    int th0 = (t >> 3) * 8, tw0 = (t & 7) * 8;
    int tid = threadIdx.x;
    for (int l = tid; l < 192*9; l += 192) wsm[l] = csw[l];
    const float* inb = g_otokT + (size_t)b*NN*CC;
    const float* vtb = g_vt + (size_t)b*NN*CC;
    for (int l = tid; l < 100*48; l += 192) {
        int pos = l / 48, c4v = (l % 48)*4;
        int hh = th0 - 1 + pos/10, ww = tw0 - 1 + pos%10;
        float4 v = make_float4(0.f, 0.f, 0.f, 0.f);
        if (hh >= 0 && hh < 64 && ww >= 0 && ww < 64) {
            int n = hh*64 + ww;
            if (g_pos[b*NN + n] >= 0) {
                v = *(const float4*)(inb + (size_t)n*CC + c4v);
            } else {
                v = *(const float4*)(vtb + (size_t)n*CC + c4v);
                float s = g_sa[b*NN + n];
                v.x *= s; v.y *= s; v.z *= s; v.w *= s;
            }
        }
        *(float4*)&tile[pos*192 + c4v] = v;
    }
    __syncthreads();

    int c4 = (tid % 48) * 4;
    int pxb = tid / 48;
    float wreg[9][4];
    #pragma unroll
    for (int tap = 0; tap < 9; tap++)
        #pragma unroll
        for (int e = 0; e < 4; e++)
            wreg[tap][e] = wsm[(c4+e)*9 + tap];
    float bv[4], cav[4];
    #pragma unroll
    for (int e = 0; e < 4; e++) { bv[e] = csb[c4+e]; cav[e] = g_ca[b*CC + c4 + e]; }

    float* outb = g_out2T + (size_t)b*NN*CC;
    for (int j = 0; j < 16; j++) {
        int px = pxb*16 + j;
        int lh = px >> 3, lw2 = px & 7;
        float acc[4] = {bv[0], bv[1], bv[2], bv[3]};
        #pragma unroll
        for (int dh = 0; dh < 3; dh++)
            #pragma unroll
            for (int dw_ = 0; dw_ < 3; dw_++) {
                int pos = (lh+dh)*10 + (lw2+dw_);
                float4 v = *(const float4*)&tile[pos*192 + c4];
                int tap = dh*3 + dw_;
                acc[0] += wreg[tap][0]*v.x; acc[1] += wreg[tap][1]*v.y;
                acc[2] += wreg[tap][2]*v.z; acc[3] += wreg[tap][3]*v.w;
            }
        float4 cen = *(const float4*)&tile[((lh+1)*10 + (lw2+1))*192 + c4];
        float* cenp = (float*)&cen;
        float4 o;
        float* op = (float*)&o;
        #pragma unroll
        for (int e = 0; e < 4; e++) {
            float a = acc[e];
            float x3 = a*a*a;
            float gg = 0.5f*a*(1.0f + tanhf(0.7978845608028654f*(a + 0.044715f*x3)));
            op[e] = gg * cav[e] + cenp[e];
        }
        int n = (th0+lh)*64 + (tw0+lw2);
        *(float4*)(outb + (size_t)n*CC + c4) = o;
    }
}

// ================= host =================
extern "C" void kernel_launch(void* const* d_in, const int* in_sizes, int n_in,
                              void* d_out, int out_size) {
    const float* x     = (const float*)d_in[0];
    const float* in_w  = (const float*)d_in[1];
    const float* in_b  = (const float*)d_in[2];
    const float* ln_w  = (const float*)d_in[3];
    const float* ln_b  = (const float*)d_in[4];
    const float* ow1   = (const float*)d_in[5];
    const float* ob1   = (const float*)d_in[6];
    const float* ow2   = (const float*)d_in[7];
    const float* ob2   = (const float*)d_in[8];
    const float* caw   = (const float*)d_in[9];
    const float* cab   = (const float*)d_in[10];
    const float* saw   = (const float*)d_in[11];
    const float* sab   = (const float*)d_in[12];
    const float* mw1   = (const float*)d_in[13];
    const float* mb1   = (const float*)d_in[14];
    const float* mw2   = (const float*)d_in[15];
    const float* mb2   = (const float*)d_in[16];
    const float* v_w   = (const float*)d_in[17];
    const float* v_b   = (const float*)d_in[18];
    const float* q_w   = (const float*)d_in[19];
    const float* q_b   = (const float*)d_in[20];
    const float* k_w   = (const float*)d_in[21];
    const float* k_b   = (const float*)d_in[22];
    const float* cs_w  = (const float*)d_in[23];
    const float* cs_b  = (const float*)d_in[24];
    const float* out_w = (const float*)d_in[25];
    const float* out_b = (const float*)d_in[26];
    float* out = (float*)d_out;

    float *p_xt, *p_vt, *p_q1, *p_k1, *p_out2T;
    int *p_keep;
    cudaGetSymbolAddress((void**)&p_xt, g_xt);
    cudaGetSymbolAddress((void**)&p_vt, g_vt);
    cudaGetSymbolAddress((void**)&p_q1, g_q1);
    cudaGetSymbolAddress((void**)&p_k1, g_k1);
    cudaGetSymbolAddress((void**)&p_out2T, g_out2T);
    cudaGetSymbolAddress((void**)&p_keep, g_keep);

    const int SMEM_G = (2*AS_SZ + 2*BS_SZ) * 4;
    cudaFuncSetAttribute((k_gemm<0,false>), cudaFuncAttributeMaxDynamicSharedMemorySize, SMEM_G);
    cudaFuncSetAttribute((k_gemm<1,false>), cudaFuncAttributeMaxDynamicSharedMemorySize, SMEM_G);
    cudaFuncSetAttribute((k_gemm<2,false>), cudaFuncAttributeMaxDynamicSharedMemorySize, SMEM_G);
    cudaFuncSetAttribute((k_gemm<0,true>),  cudaFuncAttributeMaxDynamicSharedMemorySize, SMEM_G);
    const int SMEM_F = F_TOT * 4;
    cudaFuncSetAttribute(k_flash, cudaFuncAttributeMaxDynamicSharedMemorySize, SMEM_F);
    const int SMEM_DW = (100*192 + 192*9) * 4;
    cudaFuncSetAttribute(k_dwT, cudaFuncAttributeMaxDynamicSharedMemorySize, SMEM_DW);

    dim3 tb(32, 8);
    k_front<<<dim3(NN/32, BB), 256>>>(x, in_w, in_b, ln_w, ln_b,
                                      ow1, ob1, ow2, ob2, mw1, mb1, mw2, mb2);
    k_stats<<<BB, 1024>>>(caw, cab);
    k_sa2<<<dim3(HH/4, BB), 256>>>(saw, sab);
    k_topk<<<BB, 1024>>>();
    k_wprep<<<BB*NN/256, 256>>>();

    float scale = rsqrtf((float)CC);
    k_gemm<0,false><<<dim3(NN/128, 3, BB), 256, SMEM_G>>>(
        p_xt, (size_t)NN*CC, v_w, 0, v_b, nullptr, p_vt, (size_t)NN*CC, CC, CC, 1.0f);
    k_gemm<1,false><<<dim3(NKEEP/128, 3, BB), 256, SMEM_G>>>(
        p_xt, (size_t)NN*CC, q_w, 0, q_b, p_keep, p_q1, (size_t)NKEEP*CC, CC, CC, scale);
    k_gemm<2,false><<<dim3(NKEEP/128, 3, BB), 256, SMEM_G>>>(
        p_xt, (size_t)NN*CC, k_w, 0, k_b, p_keep, p_k1, (size_t)NKEEP*CC, CC, CC, 1.0f);
    k_gT<<<dim3(NKEEP/32, CC/32, BB), tb>>>();
    k_flash<<<dim3(NKEEP/128, BB), 256, SMEM_F>>>();
    k_dwT<<<dim3(64, BB), 192, SMEM_DW>>>(cs_w, cs_b);
    k_gemm<0,true><<<dim3(NN/128, 3, BB), 256, SMEM_G>>>(
        p_out2T, (size_t)NN*CC, out_w, 0, out_b, nullptr, out, 0, CC, CC, 1.0f);
}

// round 6
// speedup vs baseline: 4.4215x; 1.3773x over previous
#include <cuda_runtime.h>
#include <cuda_fp16.h>
#include <math.h>
#include <stdint.h>

#define BB 8
#define CC 192
#define HH 64
#define WW 64
#define NN 4096
#define C4 48
#define CD 194
#define C8 24
#define NKEEP 2048

typedef unsigned long long ull;

// ================= scratch =================
__device__ float g_f[BB*C4*NN];
__device__ float g_off[BB*2*NN];
__device__ float g_score[BB*NN];
__device__ int   g_keep[BB*NKEEP];
__device__ int   g_pos[BB*NN];
__device__ float g_ca[BB*CC];
__device__ float g_sa[BB*NN];
__device__ float g_xt[(size_t)BB*NN*CC];
__device__ float g_vt[(size_t)BB*NN*CC];
__device__ float g_q1[(size_t)BB*NKEEP*CC];
__device__ float g_k1[(size_t)BB*NKEEP*CC];
__device__ float g_v1t[(size_t)BB*CC*NKEEP];
__device__ float g_otokT[(size_t)BB*NN*CC];
__device__ float g_out2T[(size_t)BB*NN*CC];

// ================= fp16 mma helpers =================
__device__ __forceinline__ uint32_t f22h2(float x, float y) {
    __half2 h = __floats2half2_rn(x, y);
    return *reinterpret_cast<uint32_t*>(&h);
}
__device__ __forceinline__ uint2 cvt4h(float4 v) {
    return make_uint2(f22h2(v.x, v.y), f22h2(v.z, v.w));
}
__device__ __forceinline__ void mma_f16(float* d, const uint32_t* a, uint32_t b0, uint32_t b1) {
    asm volatile("mma.sync.aligned.m16n8k16.row.col.f32.f16.f16.f32 "
        "{%0,%1,%2,%3}, {%4,%5,%6,%7}, {%8,%9}, {%0,%1,%2,%3};"
        : "+f"(d[0]), "+f"(d[1]), "+f"(d[2]), "+f"(d[3])
        : "r"(a[0]), "r"(a[1]), "r"(a[2]), "r"(a[3]), "r"(b0), "r"(b1));
}

// ================= GEMM fp16: Out[m,n]=(A[m,:]·B[n,:]+bias[n])*scale =================
// AMODE: 0 plain, 1 gather rows by gidx, 2 gather + inline flow-warp
// TO: transposed epilogue (writes Out[(b*CC+n)*NN+m])
// smem row = 16 kpairs (32 halves) + 4 pad words
#define KP 20
#define AS_SZ (128*KP)
#define BS_SZ (64*KP)
template<int AMODE, bool TO>
__global__ void __launch_bounds__(256, 2) k_gemm(
    const float* __restrict__ A, size_t bsA,
    const float* __restrict__ Bm, size_t bsB,
    const float* __restrict__ bias,
    const int* __restrict__ gidx,
    float* __restrict__ Out, size_t bsOut, int Ntot, int K, float scale)
{
    extern __shared__ uint32_t sm[];
    uint32_t* As = sm;
    uint32_t* Bs = sm + 2*AS_SZ;
    int tid = threadIdx.x;
    int lane = tid & 31, wid = tid >> 5;
    int wm = wid & 3, wn = wid >> 2;
    int g = lane >> 2, t4 = lane & 3;
    int b = blockIdx.z;
    int m0 = blockIdx.x * 128, n0 = blockIdx.y * 64;

    const float* Ab = A + (size_t)b * bsA;
    const float* Bb = Bm + (size_t)b * bsB;

    const float* aptr[4];
    const float* np[4][4];
    float4 wt4[4];
    int ar[4], ac[4];
    #pragma unroll
    for (int i = 0; i < 4; i++) {
        int idx = tid + i*256;
        ar[i] = idx >> 3; ac[i] = (idx & 7) << 2;
        int grow = (AMODE >= 1) ? gidx[b*NKEEP + m0 + ar[i]] : (m0 + ar[i]);
        aptr[i] = Ab + (size_t)grow * K + ac[i];
        if (AMODE == 2) {
            const float* offb = g_off + (size_t)(b*2)*NN;
            float sx = (float)(grow & 63) + offb[grow];
            float sy = (float)(grow >> 6) + offb[NN + grow];
            float x0f = floorf(sx), y0f = floorf(sy);
            float wx = sx - x0f, wy = sy - y0f;
            int x0 = (int)x0f, y0 = (int)y0f;
            float* wtp = (float*)&wt4[i];
            #pragma unroll
            for (int j = 0; j < 4; j++) {
                int xi = x0 + (j & 1), yi = y0 + (j >> 1);
                bool valid = (xi >= 0) && (xi <= 63) && (yi >= 0) && (yi <= 63);
                int xc = min(max(xi, 0), 63), yc = min(max(yi, 0), 63);
                float wt = ((j & 1) ? wx : 1.f - wx) * ((j >> 1) ? wy : 1.f - wy);
                wtp[j] = valid ? wt : 0.f;
                np[i][j] = Ab + (size_t)(yc*64 + xc) * K + ac[i];
            }
        }
    }
    const float* bptr[2];
    int br[2], bc[2];
    #pragma unroll
    for (int i = 0; i < 2; i++) {
        int idx = tid + i*256;
        br[i] = idx >> 3; bc[i] = (idx & 7) << 2;
        bptr[i] = Bb + (size_t)(n0 + br[i]) * K + bc[i];
    }

    float acc[2][4][4];
    #pragma unroll
    for (int mt = 0; mt < 2; mt++)
        #pragma unroll
        for (int nt = 0; nt < 4; nt++)
            #pragma unroll
            for (int e = 0; e < 4; e++) acc[mt][nt][e] = 0.f;

    float4 pa[4], pb[2];
    #pragma unroll
    for (int i = 0; i < 4; i++) pa[i] = *(const float4*)(aptr[i]);
    #pragma unroll
    for (int i = 0; i < 2; i++) pb[i] = *(const float4*)(bptr[i]);

    #pragma unroll
    for (int i = 0; i < 4; i++) {
        float4 v = pa[i];
        if (AMODE == 2) {
            const float* wtp = (const float*)&wt4[i];
            #pragma unroll
            for (int j = 0; j < 4; j++) {
                float4 nv = *(const float4*)(np[i][j]);
                v.x += wtp[j]*nv.x; v.y += wtp[j]*nv.y;
                v.z += wtp[j]*nv.z; v.w += wtp[j]*nv.w;
            }
        }
        *(uint2*)(As + ar[i]*KP + (ac[i] >> 1)) = cvt4h(v);
    }
    #pragma unroll
    for (int i = 0; i < 2; i++) *(uint2*)(Bs + br[i]*KP + (bc[i] >> 1)) = cvt4h(pb[i]);
    __syncthreads();

    int nkt = K >> 5;
    for (int kt = 0; kt < nkt; kt++) {
        int buf = kt & 1;
        int off = (kt + 1) << 5;
        if (kt + 1 < nkt) {
            #pragma unroll
            for (int i = 0; i < 4; i++) pa[i] = *(const float4*)(aptr[i] + off);
            #pragma unroll
            for (int i = 0; i < 2; i++) pb[i] = *(const float4*)(bptr[i] + off);
        }
        const uint32_t* Asb = As + buf*AS_SZ;
        const uint32_t* Bsb = Bs + buf*BS_SZ;
        #pragma unroll
        for (int ks = 0; ks < 2; ks++) {
            int k0 = ks*8;
            uint32_t af[2][4];
            #pragma unroll
            for (int mt = 0; mt < 2; mt++) {
                int m = wm*32 + mt*16;
                af[mt][0] = Asb[(m+g)*KP   + k0 + t4];
                af[mt][1] = Asb[(m+g+8)*KP + k0 + t4];
                af[mt][2] = Asb[(m+g)*KP   + k0 + t4 + 4];
                af[mt][3] = Asb[(m+g+8)*KP + k0 + t4 + 4];
            }
            #pragma unroll
            for (int nt = 0; nt < 4; nt++) {
                int n = wn*32 + nt*8;
                uint32_t b0 = Bsb[(n+g)*KP + k0 + t4];
                uint32_t b1 = Bsb[(n+g)*KP + k0 + t4 + 4];
                mma_f16(acc[0][nt], af[0], b0, b1);
                mma_f16(acc[1][nt], af[1], b0, b1);
            }
        }
        if (kt + 1 < nkt) {
            uint32_t* Asn = As + (buf^1)*AS_SZ;
            uint32_t* Bsn = Bs + (buf^1)*BS_SZ;
            #pragma unroll
            for (int i = 0; i < 4; i++) {
                float4 v = pa[i];
                if (AMODE == 2) {
                    const float* wtp = (const float*)&wt4[i];
                    #pragma unroll
                    for (int j = 0; j < 4; j++) {
                        float4 nv = *(const float4*)(np[i][j] + off);
                        v.x += wtp[j]*nv.x; v.y += wtp[j]*nv.y;
                        v.z += wtp[j]*nv.z; v.w += wtp[j]*nv.w;
                    }
                }
                *(uint2*)(Asn + ar[i]*KP + (ac[i] >> 1)) = cvt4h(v);
            }
            #pragma unroll
            for (int i = 0; i < 2; i++) *(uint2*)(Bsn + br[i]*KP + (bc[i] >> 1)) = cvt4h(pb[i]);
        }
        __syncthreads();
    }

    if (!TO) {
        float* Ob = Out + (size_t)b * bsOut;
        #pragma unroll
        for (int nt = 0; nt < 4; nt++) {
            int ncol = n0 + wn*32 + nt*8 + 2*t4;
            float b0v = bias ? bias[ncol]     : 0.f;
            float b1v = bias ? bias[ncol + 1] : 0.f;
            #pragma unroll
            for (int mt = 0; mt < 2; mt++) {
                int row0 = m0 + wm*32 + mt*16 + g;
                float2 o0 = make_float2((acc[mt][nt][0] + b0v) * scale, (acc[mt][nt][1] + b1v) * scale);
                float2 o1 = make_float2((acc[mt][nt][2] + b0v) * scale, (acc[mt][nt][3] + b1v) * scale);
                *(float2*)&Ob[(size_t)row0 * Ntot + ncol]     = o0;
                *(float2*)&Ob[(size_t)(row0+8) * Ntot + ncol] = o1;
            }
        }
    } else {
        float* st = (float*)sm;   // 64 x 132
        __syncthreads();
        #pragma unroll
        for (int nt = 0; nt < 4; nt++) {
            int nl = wn*32 + nt*8 + 2*t4;
            float b0v = bias ? bias[n0 + nl]     : 0.f;
            float b1v = bias ? bias[n0 + nl + 1] : 0.f;
            #pragma unroll
            for (int mt = 0; mt < 2; mt++) {
                int ml = wm*32 + mt*16 + g;
                st[nl*132 + ml]         = (acc[mt][nt][0] + b0v) * scale;
                st[(nl+1)*132 + ml]     = (acc[mt][nt][1] + b1v) * scale;
                st[nl*132 + ml + 8]     = (acc[mt][nt][2] + b0v) * scale;
                st[(nl+1)*132 + ml + 8] = (acc[mt][nt][3] + b1v) * scale;
            }
        }
        __syncthreads();
        for (int l = tid; l < 64*32; l += 256) {
            int r = l >> 5, c4v = (l & 31) << 2;
            float4 v = *(float4*)&st[r*132 + c4v];
            *(float4*)&Out[((size_t)b*CC + n0 + r)*NN + m0 + c4v] = v;
        }
    }
}

// ================= flash attention fp16 =================
// word offsets
#define F_QS 0
#define F_KS 12800            // Qs 128 x 100
#define F_VS 16000            // Ks 32 x 100
#define F_PS 23680            // Vs 2 x (192 x 20)
#define F_SC 26240            // Ps 128 x 20
#define F_LB 26368
#define F_TOT 26496
#define NTILES (NKEEP/32)

__global__ void __launch_bounds__(256, 1) k_flash() {
    extern __shared__ uint32_t sm[];
    uint32_t* Qs = sm + F_QS;
    uint32_t* Ksm = sm + F_KS;
    uint32_t* Vsm = sm + F_VS;
    uint32_t* Ps = sm + F_PS;
    float* scaleb = (float*)(sm + F_SC);
    float* lb = (float*)(sm + F_LB);

    int tid = threadIdx.x, lane = tid & 31, w = tid >> 5;
    int g = lane >> 2, t4 = lane & 3;
    int b = blockIdx.y, m0 = blockIdx.x * 128;

    const float* Qg = g_q1 + ((size_t)b*NKEEP + m0)*CC;
    const float* Kg = g_k1 + (size_t)b*NKEEP*CC;
    const float* Vg = g_v1t + (size_t)b*CC*NKEEP;

    #pragma unroll
    for (int j = 0; j < 24; j++) {
        int idx = tid + j*256;
        int r = idx/48, c4v = (idx%48)*4;
        float4 v = *(const float4*)(Qg + (size_t)r*CC + c4v);
        *(uint2*)&Qs[r*100 + (c4v >> 1)] = cvt4h(v);
    }

    int rK[6], cK[6], cV[6], kV[6];
    #pragma unroll
    for (int j = 0; j < 6; j++) {
        int idx = tid + j*256;
        rK[j] = idx/48; cK[j] = (idx%48)*4;
        cV[j] = idx>>3; kV[j] = (idx&7)*4;
    }

    float4 pk[6], pv[6];
    #pragma unroll
    for (int j = 0; j < 6; j++) {
        pk[j] = *(const float4*)(Kg + (size_t)rK[j]*CC + cK[j]);
        pv[j] = *(const float4*)(Vg + (size_t)cV[j]*NKEEP + kV[j]);
    }
    #pragma unroll
    for (int j = 0; j < 6; j++) {
        *(uint2*)&Ksm[rK[j]*100 + (cK[j] >> 1)] = cvt4h(pk[j]);
        *(uint2*)&Vsm[cV[j]*20 + (kV[j] >> 1)] = cvt4h(pv[j]);
    }
    __syncthreads();

    int wm = w >> 1, wn = w & 1;
    float oat[3][8][4];
    #pragma unroll
    for (int mt = 0; mt < 3; mt++)
        #pragma unroll
        for (int nt = 0; nt < 8; nt++)
            #pragma unroll
            for (int e = 0; e < 4; e++) oat[mt][nt][e] = 0.f;
    float m_r0 = -1e30f, m_r1 = -1e30f, l_r0 = 0.f, l_r1 = 0.f;

    int qr0 = w * 16;
    #pragma unroll 1
    for (int kt = 0; kt < NTILES; kt++) {
        int buf = kt & 1;
        if (kt + 1 < NTILES) {
            int k0 = (kt + 1) * 32;
            #pragma unroll
            for (int j = 0; j < 6; j++) {
                pk[j] = *(const float4*)(Kg + (size_t)(k0 + rK[j])*CC + cK[j]);
                pv[j] = *(const float4*)(Vg + (size_t)cV[j]*NKEEP + k0 + kV[j]);
            }
        }
        float sacc[4][4];
        #pragma unroll
        for (int nt = 0; nt < 4; nt++)
            #pragma unroll
            for (int e = 0; e < 4; e++) sacc[nt][e] = 0.f;
        #pragma unroll
        for (int ks = 0; ks < 12; ks++) {
            int k0 = ks*8;
            uint32_t a[4];
            a[0] = Qs[(qr0+g)*100   + k0 + t4];
            a[1] = Qs[(qr0+g+8)*100 + k0 + t4];
            a[2] = Qs[(qr0+g)*100   + k0 + t4 + 4];
            a[3] = Qs[(qr0+g+8)*100 + k0 + t4 + 4];
            #pragma unroll
            for (int nt = 0; nt < 4; nt++) {
                uint32_t b0 = Ksm[(nt*8+g)*100 + k0 + t4];
                uint32_t b1 = Ksm[(nt*8+g)*100 + k0 + t4 + 4];
                mma_f16(sacc[nt], a, b0, b1);
            }
        }
        float mx0 = -1e30f, mx1 = -1e30f;
        #pragma unroll
        for (int nt = 0; nt < 4; nt++) {
            mx0 = fmaxf(mx0, fmaxf(sacc[nt][0], sacc[nt][1]));
            mx1 = fmaxf(mx1, fmaxf(sacc[nt][2], sacc[nt][3]));
        }
        mx0 = fmaxf(mx0, __shfl_xor_sync(~0u, mx0, 1));
        mx0 = fmaxf(mx0, __shfl_xor_sync(~0u, mx0, 2));
        mx1 = fmaxf(mx1, __shfl_xor_sync(~0u, mx1, 1));
        mx1 = fmaxf(mx1, __shfl_xor_sync(~0u, mx1, 2));
        float mn0 = fmaxf(m_r0, mx0), mn1 = fmaxf(m_r1, mx1);
        float al0 = __expf(m_r0 - mn0), al1 = __expf(m_r1 - mn1);
        float s0 = 0.f, s1 = 0.f;
        #pragma unroll
        for (int nt = 0; nt < 4; nt++) {
            float e00 = __expf(sacc[nt][0] - mn0);
            float e01 = __expf(sacc[nt][1] - mn0);
            float e10 = __expf(sacc[nt][2] - mn1);
            float e11 = __expf(sacc[nt][3] - mn1);
            s0 += e00 + e01; s1 += e10 + e11;
            Ps[(qr0+g)*20   + nt*4 + t4] = f22h2(e00, e01);
            Ps[(qr0+g+8)*20 + nt*4 + t4] = f22h2(e10, e11);
        }
        s0 += __shfl_xor_sync(~0u, s0, 1); s0 += __shfl_xor_sync(~0u, s0, 2);
        s1 += __shfl_xor_sync(~0u, s1, 1); s1 += __shfl_xor_sync(~0u, s1, 2);
        l_r0 = l_r0 * al0 + s0;
        l_r1 = l_r1 * al1 + s1;
        m_r0 = mn0; m_r1 = mn1;
        if (t4 == 0) {
            scaleb[qr0+g]   = al0;
            scaleb[qr0+g+8] = al1;
            if (kt == NTILES-1) { lb[qr0+g] = l_r0; lb[qr0+g+8] = l_r1; }
        }
        __syncthreads();
        if (kt + 1 < NTILES) {
            #pragma unroll
            for (int j = 0; j < 6; j++)
                *(uint2*)&Ksm[rK[j]*100 + (cK[j] >> 1)] = cvt4h(pk[j]);
        }
        #pragma unroll
        for (int nt = 0; nt < 8; nt++) {
            int qc = wn*64 + nt*8 + 2*t4;
            float a0 = scaleb[qc], a1 = scaleb[qc+1];
            #pragma unroll
            for (int mt = 0; mt < 3; mt++) {
                oat[mt][nt][0] *= a0; oat[mt][nt][1] *= a1;
                oat[mt][nt][2] *= a0; oat[mt][nt][3] *= a1;
            }
        }
        const uint32_t* Vb = Vsm + buf*3840;
        #pragma unroll
        for (int ks = 0; ks < 2; ks++) {
            int k0 = ks*8;
            uint32_t bfr[8][2];
            #pragma unroll
            for (int nt = 0; nt < 8; nt++) {
                bfr[nt][0] = Ps[(wn*64 + nt*8 + g)*20 + k0 + t4];
                bfr[nt][1] = Ps[(wn*64 + nt*8 + g)*20 + k0 + t4 + 4];
            }
            #pragma unroll
            for (int mt = 0; mt < 3; mt++) {
                int cr = wm*48 + mt*16;
                uint32_t a[4];
                a[0] = Vb[(cr+g)*20   + k0 + t4];
                a[1] = Vb[(cr+g+8)*20 + k0 + t4];
                a[2] = Vb[(cr+g)*20   + k0 + t4 + 4];
                a[3] = Vb[(cr+g+8)*20 + k0 + t4 + 4];
                #pragma unroll
                for (int nt = 0; nt < 8; nt++)
                    mma_f16(oat[mt][nt], a, bfr[nt][0], bfr[nt][1]);
            }
        }
        if (kt + 1 < NTILES) {
            uint32_t* Vn = Vsm + (buf^1)*3840;
            #pragma unroll
            for (int j = 0; j < 6; j++)
                *(uint2*)&Vn[cV[j]*20 + (kV[j] >> 1)] = cvt4h(pv[j]);
        }
        __syncthreads();
    }

    // epilogue: normalize, transpose via smem (alias full smem as float [128][196])
    float* Ot = (float*)sm;
    #pragma unroll
    for (int nt = 0; nt < 8; nt++) {
        int qc = wn*64 + nt*8 + 2*t4;
        float li0 = 1.f / lb[qc], li1 = 1.f / lb[qc+1];
        #pragma unroll
        for (int mt = 0; mt < 3; mt++) {
            int cr = wm*48 + mt*16;
            Ot[qc*196 + cr+g]       = oat[mt][nt][0] * li0;
            Ot[(qc+1)*196 + cr+g]   = oat[mt][nt][1] * li1;
            Ot[qc*196 + cr+g+8]     = oat[mt][nt][2] * li0;
            Ot[(qc+1)*196 + cr+g+8] = oat[mt][nt][3] * li1;
        }
    }
    __syncthreads();
    #pragma unroll
    for (int j = 0; j < 24; j++) {
        int idx = tid + j*256;
        int r = idx/48, c4v = (idx%48)*4;
        int tok = g_keep[b*NKEEP + m0 + r];
        float4 v = *(float4*)&Ot[r*196 + c4v];
        *(float4*)&g_otokT[((size_t)b*NN + tok)*CC + c4v] = v;
    }
}

// ================= gather-transpose v1t[c][m] = vt[keep[m]][c] =================
__global__ void k_gT() {
    __shared__ float t[32][33];
    int b = blockIdx.z;
    int m0 = blockIdx.x * 32, c0 = blockIdx.y * 32;
    int tx = threadIdx.x, ty = threadIdx.y;
    #pragma unroll
    for (int j = ty; j < 32; j += 8) {
        int tok = g_keep[b*NKEEP + m0 + j];
        t[j][tx] = g_vt[((size_t)b*NN + tok)*CC + c0 + tx];
    }
    __syncthreads();
    #pragma unroll
    for (int j = ty; j < 32; j += 8)
        g_v1t[((size_t)b*CC + c0 + j)*NKEEP + m0 + tx] = t[tx][j];
}

// ================= front end (+ fused x transpose) =================
__global__ void k_front(const float* __restrict__ x,
    const float* __restrict__ in_w, const float* __restrict__ in_b,
    const float* __restrict__ ln_w, const float* __restrict__ ln_b,
    const float* __restrict__ ow1, const float* __restrict__ ob1,
    const float* __restrict__ ow2, const float* __restrict__ ob2,
    const float* __restrict__ mw1, const float* __restrict__ mb1,
    const float* __restrict__ mw2, const float* __restrict__ mb2)
{
    __shared__ float cond[CD][33];
    __shared__ float fb[C4][33];
    __shared__ float mu_s[32], rs_s[32];
    __shared__ float hb[C8][33];
    int b = blockIdx.y;
    int n0 = blockIdx.x * 32;
    int tid = threadIdx.x;

    for (int l = tid; l < CC*32; l += 256) {
        int c = l >> 5, px = l & 31;
        cond[c][px] = x[((b*CC + c) << 12) + n0 + px];
    }
    if (tid < 32) {
        int n = n0 + tid;
        int h = n >> 6, w = n & 63;
        cond[192][tid] = -1.0f + 2.0f * (float)w / 63.0f;
        cond[193][tid] = -1.0f + 2.0f * (float)h / 63.0f;
    }
    __syncthreads();

    for (int l = tid; l < 32*CC; l += 256) {
        int px = l / CC, c = l % CC;
        g_xt[((size_t)b*NN + n0 + px)*CC + c] = cond[c][px];
    }

    int px = tid & 31;
    for (int pass = 0; pass < 6; pass++) {
        int c = pass*8 + (tid >> 5);
        float acc = in_b[c];
        const float* wr = in_w + c*CD;
        #pragma unroll 2
        for (int k = 0; k < CD; k++) acc += wr[k] * cond[k][px];
        fb[c][px] = acc;
    }
    __syncthreads();

    if (tid < 32) {
        float s = 0.f, s2 = 0.f;
        for (int c = 0; c < C4; c++) { float v = fb[c][tid]; s += v; s2 += v*v; }
        float mu = s / (float)C4;
        float var = s2 / (float)C4 - mu*mu;
        mu_s[tid] = mu;
        rs_s[tid] = rsqrtf(var + 1e-6f);
    }
    __syncthreads();

    for (int l = tid; l < C4*32; l += 256) {
        int c = l >> 5, p = l & 31;
        float v = (fb[c][p] - mu_s[p]) * rs_s[p] * ln_w[c] + ln_b[c];
        v = v > 0.f ? v : 0.1f*v;
        fb[c][p] = v;
        g_f[(b*C4 + c)*NN + n0 + p] = v;
    }
    __syncthreads();

    for (int l = tid; l < C8*32; l += 256) {
        int j = l >> 5, p = l & 31;
        float acc = ob1[j];
        const float* wr = ow1 + j*C4;
        #pragma unroll 4
        for (int c = 0; c < C4; c++) acc += wr[c] * fb[c][p];
        hb[j][p] = acc > 0.f ? acc : 0.1f*acc;
    }
    __syncthreads();

    if (tid < 64) {
        int d = tid >> 5, p = tid & 31;
        float acc = ob2[d];
        const float* wr = ow2 + d*C8;
        #pragma unroll
        for (int j = 0; j < C8; j++) acc += wr[j] * hb[j][p];
        g_off[(b*2 + d)*NN + n0 + p] = tanhf(acc) * 8.0f;
    }
    if (tid >= 64 && tid < 96) {
        int p = tid - 64;
        float s = 0.f;
        for (int c = 0; c < C4; c++) s += fb[c][p];
        float t = s / (float)C4;
        float s1 = t * mw1[0] + mb1[0];
        s1 = s1 > 0.f ? s1 : 0.1f*s1;
        float l0 = s1 * mw2[0] + mb2[0];
        float l1 = s1 * mw2[1] + mb2[1];
        g_score[b*NN + n0 + p] = 1.0f / (1.0f + expf(l1 - l0));
    }
}

// ================= merged fmean + ca =================
__global__ void k_stats(const float* __restrict__ caw, const float* __restrict__ cab) {
    __shared__ float fm[C4];
    int b = blockIdx.x, tid = threadIdx.x;
    int w = tid >> 5, lane = tid & 31;
    for (int c = w; c < C4; c += 32) {
        const float* p = g_f + (b*C4 + c)*NN;
        float s = 0.f;
        for (int i = lane; i < NN; i += 32) s += p[i];
        #pragma unroll
        for (int o = 16; o; o >>= 1) s += __shfl_xor_sync(~0u, s, o);
        if (lane == 0) fm[c] = s / (float)NN;
    }
    __syncthreads();
    if (tid < CC) {
        float acc = cab[tid];
        #pragma unroll 4
        for (int c = 0; c < C4; c++) acc += caw[tid*C4 + c] * fm[c];
        g_ca[b*CC + tid] = 1.0f / (1.0f + __expf(-acc));
    }
}

// ================= sa: tiled 3x3 conv + sigmoid =================
__global__ void k_sa2(const float* __restrict__ saw, const float* __restrict__ sab) {
    __shared__ float wsh[C4*9];
    __shared__ float smf[6][64];
    int b = blockIdx.y, h0 = blockIdx.x*4;
    int tid = threadIdx.x;
    for (int l = tid; l < C4*9; l += 256) wsh[l] = saw[l];
    int lw = tid & 63, lh = tid >> 6;
    float acc = sab[0];
    const float* fb = g_f + b*C4*NN;
    for (int c = 0; c < C4; c++) {
        __syncthreads();
        for (int l = tid; l < 384; l += 256) {
            int r = l >> 6, ww = l & 63;
            int hh = h0 - 1 + r;
            smf[r][ww] = (hh >= 0 && hh < HH) ? fb[c*NN + hh*64 + ww] : 0.f;
        }
        __syncthreads();
        #pragma unroll
        for (int dh = 0; dh < 3; dh++) {
            float w0 = wsh[c*9+dh*3+0], w1 = wsh[c*9+dh*3+1], w2 = wsh[c*9+dh*3+2];
            const float* row = smf[lh + dh];
            float vm = (lw > 0)  ? row[lw-1] : 0.f;
            float vc = row[lw];
            float vp = (lw < 63) ? row[lw+1] : 0.f;
            acc += w0*vm + w1*vc + w2*vp;
        }
    }
    g_sa[b*NN + (h0+lh)*64 + lw] = 1.f/(1.f + __expf(-acc));
}

// ================= top-k by radix select (set semantics, deterministic) ========
__device__ __forceinline__ unsigned int ford(float f) {
    unsigned int u = __float_as_uint(f);
    return (u & 0x80000000u) ? ~u : (u | 0x80000000u);
}
__global__ void __launch_bounds__(1024) k_topk() {
    __shared__ ull keys[NN];
    __shared__ int hist[256];
    __shared__ int scan_[256];
    __shared__ ull sel_prefix;
    __shared__ int sel_k;
    __shared__ int wsum[32];
    int b = blockIdx.x, tid = threadIdx.x;
    int lane = tid & 31, wid = tid >> 5;

    for (int l = tid; l < NN; l += 1024) {
        unsigned int o = ford(g_score[b*NN + l]) ^ 0xFFFFFFFFu;  // ascending = descending score
        keys[l] = ((ull)o << 32) | (unsigned int)l;
    }
    if (tid == 0) { sel_prefix = 0; sel_k = NKEEP - 1; }
    __syncthreads();

    ull prefix = 0, mask = 0;
    for (int byte = 7; byte >= 0; byte--) {
        int sh = byte * 8;
        if (tid < 256) hist[tid] = 0;
        __syncthreads();
        for (int l = tid; l < NN; l += 1024) {
            ull k = keys[l];
            if ((k & mask) == prefix) atomicAdd(&hist[(int)((k >> sh) & 0xFF)], 1);
        }
        __syncthreads();
        if (tid < 256) scan_[tid] = hist[tid];
        __syncthreads();
        #pragma unroll
        for (int off = 1; off < 256; off <<= 1) {
            int v = 0;
            if (tid < 256 && tid >= off) v = scan_[tid - off];
            __syncthreads();
            if (tid < 256) scan_[tid] += v;
            __syncthreads();
        }
        int kcur = sel_k;
        __syncthreads();
        if (tid < 256) {
            int incl = scan_[tid], excl = incl - hist[tid];
            if (kcur >= excl && kcur < incl) {
                sel_prefix = prefix | ((ull)tid << sh);
                sel_k = kcur - excl;
            }
        }
        __syncthreads();
        prefix = sel_prefix;
        mask |= (0xFFull << sh);
        __syncthreads();
    }
    ull kstar = prefix;  // the NKEEP-th smallest key (keys unique)

    // deterministic positions: prefix-scan in token order (4 tokens per thread)
    int base = tid * 4;
    int kept[4], c = 0;
    #pragma unroll
    for (int j = 0; j < 4; j++) {
        kept[j] = (keys[base + j] <= kstar) ? 1 : 0;
        c += kept[j];
    }
    int incl = c;
    #pragma unroll
    for (int o = 1; o < 32; o <<= 1) {
        int v = __shfl_up_sync(~0u, incl, o);
        if (lane >= o) incl += v;
    }
    if (lane == 31) wsum[wid] = incl;
    __syncthreads();
    if (wid == 0) {
        int v = (lane < 32) ? wsum[lane] : 0;
        #pragma unroll
        for (int o = 1; o < 32; o <<= 1) {
            int u = __shfl_up_sync(~0u, v, o);
            if (lane >= o) v += u;
        }
        wsum[lane] = v;
    }
    __syncthreads();
    int offset = (wid > 0 ? wsum[wid - 1] : 0) + incl - c;
    #pragma unroll
    for (int j = 0; j < 4; j++) {
        int tok = base + j;
        if (kept[j]) {
            g_keep[b*NKEEP + offset] = tok;
            g_pos[b*NN + tok] = offset;
            offset++;
        } else {
            g_pos[b*NN + tok] = -1;
        }
    }
}

// ================= token-major depthwise 3x3 + gelu*ca + residual (fused fill) =====
__global__ void __launch_bounds__(192) k_dwT(const float* __restrict__ csw, const float* __restrict__ csb) {
    extern __shared__ float sdw[];
    float* tile = sdw;            // [100][192]
    float* wsm = sdw + 100*192;   // [192*9]
    int b = blockIdx.y;
    int t = blockIdx.x;
    int th0 = (t >> 3) * 8, tw0 = (t & 7) * 8;
    int tid = threadIdx.x;
    for (int l = tid; l < 192*9; l += 192) wsm[l] = csw[l];
    const float* inb = g_otokT + (size_t)b*NN*CC;
    const float* vtb = g_vt + (size_t)b*NN*CC;
    for (int l = tid; l < 100*48; l += 192) {
        int pos = l / 48, c4v = (l % 48)*4;
        int hh = th0 - 1 + pos/10, ww = tw0 - 1 + pos%10;
        float4 v = make_float4(0.f, 0.f, 0.f, 0.f);
        if (hh >= 0 && hh < 64 && ww >= 0 && ww < 64) {
            int n = hh*64 + ww;
            if (g_pos[b*NN + n] >= 0) {
                v = *(const float4*)(inb + (size_t)n*CC + c4v);
            } else {
                v = *(const float4*)(vtb + (size_t)n*CC + c4v);
                float s = g_sa[b*NN + n];
                v.x *= s; v.y *= s; v.z *= s; v.w *= s;
            }
        }
        *(float4*)&tile[pos*192 + c4v] = v;
    }
    __syncthreads();

    int c4 = (tid % 48) * 4;
    int pxb = tid / 48;
    float wreg[9][4];
    #pragma unroll
    for (int tap = 0; tap < 9; tap++)
        #pragma unroll
        for (int e = 0; e < 4; e++)
            wreg[tap][e] = wsm[(c4+e)*9 + tap];
    float bv[4], cav[4];
    #pragma unroll
    for (int e = 0; e < 4; e++) { bv[e] = csb[c4+e]; cav[e] = g_ca[b*CC + c4 + e]; }

    float* outb = g_out2T + (size_t)b*NN*CC;
    for (int j = 0; j < 16; j++) {
        int px = pxb*16 + j;
        int lh = px >> 3, lw2 = px & 7;
        float acc[4] = {bv[0], bv[1], bv[2], bv[3]};
        #pragma unroll
        for (int dh = 0; dh < 3; dh++)
            #pragma unroll
            for (int dw_ = 0; dw_ < 3; dw_++) {
                int pos = (lh+dh)*10 + (lw2+dw_);
                float4 v = *(const float4*)&tile[pos*192 + c4];
                int tap = dh*3 + dw_;
                acc[0] += wreg[tap][0]*v.x; acc[1] += wreg[tap][1]*v.y;
                acc[2] += wreg[tap][2]*v.z; acc[3] += wreg[tap][3]*v.w;
            }
        float4 cen = *(const float4*)&tile[((lh+1)*10 + (lw2+1))*192 + c4];
        float* cenp = (float*)&cen;
        float4 o;
        float* op = (float*)&o;
        #pragma unroll
        for (int e = 0; e < 4; e++) {
            float a = acc[e];
            float x3 = a*a*a;
            float gg = 0.5f*a*(1.0f + tanhf(0.7978845608028654f*(a + 0.044715f*x3)));
            op[e] = gg * cav[e] + cenp[e];
        }
        int n = (th0+lh)*64 + (tw0+lw2);
        *(float4*)(outb + (size_t)n*CC + c4) = o;
    }
}

// ================= host =================
extern "C" void kernel_launch(void* const* d_in, const int* in_sizes, int n_in,
                              void* d_out, int out_size) {
    const float* x     = (const float*)d_in[0];
    const float* in_w  = (const float*)d_in[1];
    const float* in_b  = (const float*)d_in[2];
    const float* ln_w  = (const float*)d_in[3];
    const float* ln_b  = (const float*)d_in[4];
    const float* ow1   = (const float*)d_in[5];
    const float* ob1   = (const float*)d_in[6];
    const float* ow2   = (const float*)d_in[7];
    const float* ob2   = (const float*)d_in[8];
    const float* caw   = (const float*)d_in[9];
    const float* cab   = (const float*)d_in[10];
    const float* saw   = (const float*)d_in[11];
    const float* sab   = (const float*)d_in[12];
    const float* mw1   = (const float*)d_in[13];
    const float* mb1   = (const float*)d_in[14];
    const float* mw2   = (const float*)d_in[15];
    const float* mb2   = (const float*)d_in[16];
    const float* v_w   = (const float*)d_in[17];
    const float* v_b   = (const float*)d_in[18];
    const float* q_w   = (const float*)d_in[19];
    const float* q_b   = (const float*)d_in[20];
    const float* k_w   = (const float*)d_in[21];
    const float* k_b   = (const float*)d_in[22];
    const float* cs_w  = (const float*)d_in[23];
    const float* cs_b  = (const float*)d_in[24];
    const float* out_w = (const float*)d_in[25];
    const float* out_b = (const float*)d_in[26];
    float* out = (float*)d_out;

    float *p_xt, *p_vt, *p_q1, *p_k1, *p_out2T;
    int *p_keep;
    cudaGetSymbolAddress((void**)&p_xt, g_xt);
    cudaGetSymbolAddress((void**)&p_vt, g_vt);
    cudaGetSymbolAddress((void**)&p_q1, g_q1);
    cudaGetSymbolAddress((void**)&p_k1, g_k1);
    cudaGetSymbolAddress((void**)&p_out2T, g_out2T);
    cudaGetSymbolAddress((void**)&p_keep, g_keep);

    const int SMEM_G = 8448 * 4;   // covers A/B buffers (7680 w) and TO staging (8448 w)
    cudaFuncSetAttribute((k_gemm<0,false>), cudaFuncAttributeMaxDynamicSharedMemorySize, SMEM_G);
    cudaFuncSetAttribute((k_gemm<1,false>), cudaFuncAttributeMaxDynamicSharedMemorySize, SMEM_G);
    cudaFuncSetAttribute((k_gemm<2,false>), cudaFuncAttributeMaxDynamicSharedMemorySize, SMEM_G);
    cudaFuncSetAttribute((k_gemm<0,true>),  cudaFuncAttributeMaxDynamicSharedMemorySize, SMEM_G);
    const int SMEM_F = F_TOT * 4;  // 105984
    cudaFuncSetAttribute(k_flash, cudaFuncAttributeMaxDynamicSharedMemorySize, SMEM_F);
    const int SMEM_DW = (100*192 + 192*9) * 4;
    cudaFuncSetAttribute(k_dwT, cudaFuncAttributeMaxDynamicSharedMemorySize, SMEM_DW);

    dim3 tb(32, 8);
    k_front<<<dim3(NN/32, BB), 256>>>(x, in_w, in_b, ln_w, ln_b,
                                      ow1, ob1, ow2, ob2, mw1, mb1, mw2, mb2);
    k_stats<<<BB, 1024>>>(caw, cab);
    k_sa2<<<dim3(HH/4, BB), 256>>>(saw, sab);
    k_topk<<<BB, 1024>>>();

    float scale = rsqrtf((float)CC);
    k_gemm<0,false><<<dim3(NN/128, 3, BB), 256, SMEM_G>>>(
        p_xt, (size_t)NN*CC, v_w, 0, v_b, nullptr, p_vt, (size_t)NN*CC, CC, CC, 1.0f);
    k_gemm<1,false><<<dim3(NKEEP/128, 3, BB), 256, SMEM_G>>>(
        p_xt, (size_t)NN*CC, q_w, 0, q_b, p_keep, p_q1, (size_t)NKEEP*CC, CC, CC, scale);
    k_gemm<2,false><<<dim3(NKEEP/128, 3, BB), 256, SMEM_G>>>(
        p_xt, (size_t)NN*CC, k_w, 0, k_b, p_keep, p_k1, (size_t)NKEEP*CC, CC, CC, 1.0f);
    k_gT<<<dim3(NKEEP/32, CC/32, BB), tb>>>();
    k_flash<<<dim3(NKEEP/128, BB), 256, SMEM_F>>>();
    k_dwT<<<dim3(64, BB), 192, SMEM_DW>>>(cs_w, cs_b);
    k_gemm<0,true><<<dim3(NN/128, 3, BB), 256, SMEM_G>>>(
        p_out2T, (size_t)NN*CC, out_w, 0, out_b, nullptr, out, 0, CC, CC, 1.0f);
}

// round 7
// speedup vs baseline: 4.4597x; 1.0086x over previous
#include <cuda_runtime.h>
#include <cuda_fp16.h>
#include <math.h>
#include <stdint.h>

#define BB 8
#define CC 192
#define HH 64
#define WW 64
#define NN 4096
#define C4 48
#define CD 194
#define C8 24
#define NKEEP 2048

typedef unsigned long long ull;

// ================= scratch =================
__device__ float g_f[BB*C4*NN];
__device__ float g_off[BB*2*NN];
__device__ float g_score[BB*NN];
__device__ int   g_keep[BB*NKEEP];
__device__ int   g_pos[BB*NN];
__device__ float g_ca[BB*CC];
__device__ float g_sa[BB*NN];
__device__ float g_xt[(size_t)BB*NN*CC];
__device__ float g_vt[(size_t)BB*NN*CC];
__device__ float g_q1[(size_t)BB*NKEEP*CC];
__device__ float g_k1[(size_t)BB*NKEEP*CC];
__device__ float g_v1t[(size_t)BB*CC*NKEEP];
__device__ float g_otokT[(size_t)BB*NN*CC];
__device__ float g_out2T[(size_t)BB*NN*CC];

// ================= fp16 mma / ldmatrix helpers =================
__device__ __forceinline__ uint32_t f22h2(float x, float y) {
    __half2 h = __floats2half2_rn(x, y);
    return *reinterpret_cast<uint32_t*>(&h);
}
__device__ __forceinline__ uint2 cvt4h(float4 v) {
    return make_uint2(f22h2(v.x, v.y), f22h2(v.z, v.w));
}
__device__ __forceinline__ void mma_f16(float* d, const uint32_t* a, uint32_t b0, uint32_t b1) {
    asm volatile("mma.sync.aligned.m16n8k16.row.col.f32.f16.f16.f32 "
        "{%0,%1,%2,%3}, {%4,%5,%6,%7}, {%8,%9}, {%0,%1,%2,%3};"
        : "+f"(d[0]), "+f"(d[1]), "+f"(d[2]), "+f"(d[3])
        : "r"(a[0]), "r"(a[1]), "r"(a[2]), "r"(a[3]), "r"(b0), "r"(b1));
}
__device__ __forceinline__ void ldsm_x4(uint32_t* r, uint32_t addr) {
    asm volatile("ldmatrix.sync.aligned.m8n8.x4.shared.b16 {%0,%1,%2,%3}, [%4];"
        : "=r"(r[0]), "=r"(r[1]), "=r"(r[2]), "=r"(r[3]) : "r"(addr));
}

// ================= GEMM fp16 + ldmatrix =================
// AMODE: 0 plain, 1 gather rows by gidx, 2 gather + inline flow-warp
// TO: transposed epilogue
#define KP 20
#define AS_SZ (128*KP)
#define BS_SZ (64*KP)
template<int AMODE, bool TO>
__global__ void __launch_bounds__(256, 2) k_gemm(
    const float* __restrict__ A, size_t bsA,
    const float* __restrict__ Bm, size_t bsB,
    const float* __restrict__ bias,
    const int* __restrict__ gidx,
    float* __restrict__ Out, size_t bsOut, int Ntot, int K, float scale)
{
    extern __shared__ uint32_t sm[];
    uint32_t* As = sm;
    uint32_t* Bs = sm + 2*AS_SZ;
    uint32_t sbase = (uint32_t)__cvta_generic_to_shared(sm);
    int tid = threadIdx.x;
    int lane = tid & 31, wid = tid >> 5;
    int wm = wid & 3, wn = wid >> 2;
    int g = lane >> 2, t4 = lane & 3;
    int la_row = lane & 15, la_kw = (lane >> 4) << 2;
    int lb_row = ((lane >> 4) & 1) * 8 + (lane & 7), lb_kw = ((lane >> 3) & 1) << 2;
    int b = blockIdx.z;
    int m0 = blockIdx.x * 128, n0 = blockIdx.y * 64;

    const float* Ab = A + (size_t)b * bsA;
    const float* Bb = Bm + (size_t)b * bsB;

    const float* aptr[4];
    const float* np[4][4];
    float4 wt4[4];
    int ar[4], ac[4];
    #pragma unroll
    for (int i = 0; i < 4; i++) {
        int idx = tid + i*256;
        ar[i] = idx >> 3; ac[i] = (idx & 7) << 2;
        int grow = (AMODE >= 1) ? gidx[b*NKEEP + m0 + ar[i]] : (m0 + ar[i]);
        aptr[i] = Ab + (size_t)grow * K + ac[i];
        if (AMODE == 2) {
            const float* offb = g_off + (size_t)(b*2)*NN;
            float sx = (float)(grow & 63) + offb[grow];
            float sy = (float)(grow >> 6) + offb[NN + grow];
            float x0f = floorf(sx), y0f = floorf(sy);
            float wx = sx - x0f, wy = sy - y0f;
            int x0 = (int)x0f, y0 = (int)y0f;
            float* wtp = (float*)&wt4[i];
            #pragma unroll
            for (int j = 0; j < 4; j++) {
                int xi = x0 + (j & 1), yi = y0 + (j >> 1);
                bool valid = (xi >= 0) && (xi <= 63) && (yi >= 0) && (yi <= 63);
                int xc = min(max(xi, 0), 63), yc = min(max(yi, 0), 63);
                float wt = ((j & 1) ? wx : 1.f - wx) * ((j >> 1) ? wy : 1.f - wy);
                wtp[j] = valid ? wt : 0.f;
                np[i][j] = Ab + (size_t)(yc*64 + xc) * K + ac[i];
            }
        }
    }
    const float* bptr[2];
    int br[2], bc[2];
    #pragma unroll
    for (int i = 0; i < 2; i++) {
        int idx = tid + i*256;
        br[i] = idx >> 3; bc[i] = (idx & 7) << 2;
        bptr[i] = Bb + (size_t)(n0 + br[i]) * K + bc[i];
    }

    float acc[2][4][4];
    #pragma unroll
    for (int mt = 0; mt < 2; mt++)
        #pragma unroll
        for (int nt = 0; nt < 4; nt++)
            #pragma unroll
            for (int e = 0; e < 4; e++) acc[mt][nt][e] = 0.f;

    float4 pa[4], pb[2];
    #pragma unroll
    for (int i = 0; i < 4; i++) pa[i] = *(const float4*)(aptr[i]);
    #pragma unroll
    for (int i = 0; i < 2; i++) pb[i] = *(const float4*)(bptr[i]);

    #pragma unroll
    for (int i = 0; i < 4; i++) {
        float4 v = pa[i];
        if (AMODE == 2) {
            const float* wtp = (const float*)&wt4[i];
            #pragma unroll
            for (int j = 0; j < 4; j++) {
                float4 nv = *(const float4*)(np[i][j]);
                v.x += wtp[j]*nv.x; v.y += wtp[j]*nv.y;
                v.z += wtp[j]*nv.z; v.w += wtp[j]*nv.w;
            }
        }
        *(uint2*)(As + ar[i]*KP + (ac[i] >> 1)) = cvt4h(v);
    }
    #pragma unroll
    for (int i = 0; i < 2; i++) *(uint2*)(Bs + br[i]*KP + (bc[i] >> 1)) = cvt4h(pb[i]);
    __syncthreads();

    int nkt = K >> 5;
    for (int kt = 0; kt < nkt; kt++) {
        int buf = kt & 1;
        int off = (kt + 1) << 5;
        if (kt + 1 < nkt) {
            #pragma unroll
            for (int i = 0; i < 4; i++) pa[i] = *(const float4*)(aptr[i] + off);
            #pragma unroll
            for (int i = 0; i < 2; i++) pb[i] = *(const float4*)(bptr[i] + off);
        }
        uint32_t sbA = sbase + (buf*AS_SZ)*4;
        uint32_t sbB = sbase + (2*AS_SZ + buf*BS_SZ)*4;
        #pragma unroll
        for (int ks = 0; ks < 2; ks++) {
            int k0 = ks*8;
            uint32_t af[2][4], bf[2][4];
            ldsm_x4(af[0], sbA + ((wm*32 +      la_row)*KP + k0 + la_kw)*4);
            ldsm_x4(af[1], sbA + ((wm*32 + 16 + la_row)*KP + k0 + la_kw)*4);
            ldsm_x4(bf[0], sbB + ((wn*32 +      lb_row)*KP + k0 + lb_kw)*4);
            ldsm_x4(bf[1], sbB + ((wn*32 + 16 + lb_row)*KP + k0 + lb_kw)*4);
            #pragma unroll
            for (int nt = 0; nt < 4; nt++) {
                uint32_t b0 = bf[nt>>1][(nt&1)*2], b1 = bf[nt>>1][(nt&1)*2+1];
                mma_f16(acc[0][nt], af[0], b0, b1);
                mma_f16(acc[1][nt], af[1], b0, b1);
            }
        }
        if (kt + 1 < nkt) {
            uint32_t* Asn = As + (buf^1)*AS_SZ;
            uint32_t* Bsn = Bs + (buf^1)*BS_SZ;
            #pragma unroll
            for (int i = 0; i < 4; i++) {
                float4 v = pa[i];
                if (AMODE == 2) {
                    const float* wtp = (const float*)&wt4[i];
                    #pragma unroll
                    for (int j = 0; j < 4; j++) {
                        float4 nv = *(const float4*)(np[i][j] + off);
                        v.x += wtp[j]*nv.x; v.y += wtp[j]*nv.y;
                        v.z += wtp[j]*nv.z; v.w += wtp[j]*nv.w;
                    }
                }
                *(uint2*)(Asn + ar[i]*KP + (ac[i] >> 1)) = cvt4h(v);
            }
            #pragma unroll
            for (int i = 0; i < 2; i++) *(uint2*)(Bsn + br[i]*KP + (bc[i] >> 1)) = cvt4h(pb[i]);
        }
        __syncthreads();
    }

    if (!TO) {
        float* Ob = Out + (size_t)b * bsOut;
        #pragma unroll
        for (int nt = 0; nt < 4; nt++) {
            int ncol = n0 + wn*32 + nt*8 + 2*t4;
            float b0v = bias ? bias[ncol]     : 0.f;
            float b1v = bias ? bias[ncol + 1] : 0.f;
            #pragma unroll
            for (int mt = 0; mt < 2; mt++) {
                int row0 = m0 + wm*32 + mt*16 + g;
                float2 o0 = make_float2((acc[mt][nt][0] + b0v) * scale, (acc[mt][nt][1] + b1v) * scale);
                float2 o1 = make_float2((acc[mt][nt][2] + b0v) * scale, (acc[mt][nt][3] + b1v) * scale);
                *(float2*)&Ob[(size_t)row0 * Ntot + ncol]     = o0;
                *(float2*)&Ob[(size_t)(row0+8) * Ntot + ncol] = o1;
            }
        }
    } else {
        float* st = (float*)sm;   // 64 x 132
        __syncthreads();
        #pragma unroll
        for (int nt = 0; nt < 4; nt++) {
            int nl = wn*32 + nt*8 + 2*t4;
            float b0v = bias ? bias[n0 + nl]     : 0.f;
            float b1v = bias ? bias[n0 + nl + 1] : 0.f;
            #pragma unroll
            for (int mt = 0; mt < 2; mt++) {
                int ml = wm*32 + mt*16 + g;
                st[nl*132 + ml]         = (acc[mt][nt][0] + b0v) * scale;
                st[(nl+1)*132 + ml]     = (acc[mt][nt][1] + b1v) * scale;
                st[nl*132 + ml + 8]     = (acc[mt][nt][2] + b0v) * scale;
                st[(nl+1)*132 + ml + 8] = (acc[mt][nt][3] + b1v) * scale;
            }
        }
        __syncthreads();
        for (int l = tid; l < 64*32; l += 256) {
            int r = l >> 5, c4v = (l & 31) << 2;
            float4 v = *(float4*)&st[r*132 + c4v];
            *(float4*)&Out[((size_t)b*CC + n0 + r)*NN + m0 + c4v] = v;
        }
    }
}

// ================= flash attention fp16 + ldmatrix =================
#define F_QS 0
#define F_KS 12800            // Qs 128 x 100
#define F_VS 16000            // Ks 32 x 100
#define F_PS 23680            // Vs 2 x (192 x 20)
#define F_SC 26240            // Ps 128 x 20
#define F_LB 26368
#define F_TOT 26496
#define NTILES (NKEEP/32)

__global__ void __launch_bounds__(256, 1) k_flash() {
    extern __shared__ uint32_t sm[];
    uint32_t* Qs = sm + F_QS;
    uint32_t* Ksm = sm + F_KS;
    uint32_t* Vsm = sm + F_VS;
    uint32_t* Ps = sm + F_PS;
    float* scaleb = (float*)(sm + F_SC);
    float* lb = (float*)(sm + F_LB);
    uint32_t sbase = (uint32_t)__cvta_generic_to_shared(sm);

    int tid = threadIdx.x, lane = tid & 31, w = tid >> 5;
    int g = lane >> 2, t4 = lane & 3;
    int la_row = lane & 15, la_kw = (lane >> 4) << 2;
    int lb_row = ((lane >> 4) & 1) * 8 + (lane & 7), lb_kw = ((lane >> 3) & 1) << 2;
    int b = blockIdx.y, m0 = blockIdx.x * 128;

    const float* Qg = g_q1 + ((size_t)b*NKEEP + m0)*CC;
    const float* Kg = g_k1 + (size_t)b*NKEEP*CC;
    const float* Vg = g_v1t + (size_t)b*CC*NKEEP;

    #pragma unroll
    for (int j = 0; j < 24; j++) {
        int idx = tid + j*256;
        int r = idx/48, c4v = (idx%48)*4;
        float4 v = *(const float4*)(Qg + (size_t)r*CC + c4v);
        *(uint2*)&Qs[r*100 + (c4v >> 1)] = cvt4h(v);
    }

    int rK[6], cK[6], cV[6], kV[6];
    #pragma unroll
    for (int j = 0; j < 6; j++) {
        int idx = tid + j*256;
        rK[j] = idx/48; cK[j] = (idx%48)*4;
        cV[j] = idx>>3; kV[j] = (idx&7)*4;
    }

    float4 pk[6], pv[6];
    #pragma unroll
    for (int j = 0; j < 6; j++) {
        pk[j] = *(const float4*)(Kg + (size_t)rK[j]*CC + cK[j]);
        pv[j] = *(const float4*)(Vg + (size_t)cV[j]*NKEEP + kV[j]);
    }
    #pragma unroll
    for (int j = 0; j < 6; j++) {
        *(uint2*)&Ksm[rK[j]*100 + (cK[j] >> 1)] = cvt4h(pk[j]);
        *(uint2*)&Vsm[cV[j]*20 + (kV[j] >> 1)] = cvt4h(pv[j]);
    }
    __syncthreads();

    int wm = w >> 1, wn = w & 1;
    float oat[3][8][4];
    #pragma unroll
    for (int mt = 0; mt < 3; mt++)
        #pragma unroll
        for (int nt = 0; nt < 8; nt++)
            #pragma unroll
            for (int e = 0; e < 4; e++) oat[mt][nt][e] = 0.f;
    float m_r0 = -1e30f, m_r1 = -1e30f, l_r0 = 0.f, l_r1 = 0.f;

    int qr0 = w * 16;
    #pragma unroll 1
    for (int kt = 0; kt < NTILES; kt++) {
        int buf = kt & 1;
        if (kt + 1 < NTILES) {
            int k0 = (kt + 1) * 32;
            #pragma unroll
            for (int j = 0; j < 6; j++) {
                pk[j] = *(const float4*)(Kg + (size_t)(k0 + rK[j])*CC + cK[j]);
                pv[j] = *(const float4*)(Vg + (size_t)cV[j]*NKEEP + k0 + kV[j]);
            }
        }
        float sacc[4][4];
        #pragma unroll
        for (int nt = 0; nt < 4; nt++)
            #pragma unroll
            for (int e = 0; e < 4; e++) sacc[nt][e] = 0.f;
        #pragma unroll
        for (int ks = 0; ks < 12; ks++) {
            int k0 = ks*8;
            uint32_t a[4], bf[2][4];
            ldsm_x4(a,     sbase + (F_QS + (qr0 + la_row)*100 + k0 + la_kw)*4);
            ldsm_x4(bf[0], sbase + (F_KS + (     lb_row)*100 + k0 + lb_kw)*4);
            ldsm_x4(bf[1], sbase + (F_KS + (16 + lb_row)*100 + k0 + lb_kw)*4);
            mma_f16(sacc[0], a, bf[0][0], bf[0][1]);
            mma_f16(sacc[1], a, bf[0][2], bf[0][3]);
            mma_f16(sacc[2], a, bf[1][0], bf[1][1]);
            mma_f16(sacc[3], a, bf[1][2], bf[1][3]);
        }
        float mx0 = -1e30f, mx1 = -1e30f;
        #pragma unroll
        for (int nt = 0; nt < 4; nt++) {
            mx0 = fmaxf(mx0, fmaxf(sacc[nt][0], sacc[nt][1]));
            mx1 = fmaxf(mx1, fmaxf(sacc[nt][2], sacc[nt][3]));
        }
        mx0 = fmaxf(mx0, __shfl_xor_sync(~0u, mx0, 1));
        mx0 = fmaxf(mx0, __shfl_xor_sync(~0u, mx0, 2));
        mx1 = fmaxf(mx1, __shfl_xor_sync(~0u, mx1, 1));
        mx1 = fmaxf(mx1, __shfl_xor_sync(~0u, mx1, 2));
        float mn0 = fmaxf(m_r0, mx0), mn1 = fmaxf(m_r1, mx1);
        float al0 = __expf(m_r0 - mn0), al1 = __expf(m_r1 - mn1);
        float s0 = 0.f, s1 = 0.f;
        #pragma unroll
        for (int nt = 0; nt < 4; nt++) {
            float e00 = __expf(sacc[nt][0] - mn0);
            float e01 = __expf(sacc[nt][1] - mn0);
            float e10 = __expf(sacc[nt][2] - mn1);
            float e11 = __expf(sacc[nt][3] - mn1);
            s0 += e00 + e01; s1 += e10 + e11;
            Ps[(qr0+g)*20   + nt*4 + t4] = f22h2(e00, e01);
            Ps[(qr0+g+8)*20 + nt*4 + t4] = f22h2(e10, e11);
        }
        s0 += __shfl_xor_sync(~0u, s0, 1); s0 += __shfl_xor_sync(~0u, s0, 2);
        s1 += __shfl_xor_sync(~0u, s1, 1); s1 += __shfl_xor_sync(~0u, s1, 2);
        l_r0 = l_r0 * al0 + s0;
        l_r1 = l_r1 * al1 + s1;
        m_r0 = mn0; m_r1 = mn1;
        if (t4 == 0) {
            scaleb[qr0+g]   = al0;
            scaleb[qr0+g+8] = al1;
            if (kt == NTILES-1) { lb[qr0+g] = l_r0; lb[qr0+g+8] = l_r1; }
        }
        __syncthreads();
        if (kt + 1 < NTILES) {
            #pragma unroll
            for (int j = 0; j < 6; j++)
                *(uint2*)&Ksm[rK[j]*100 + (cK[j] >> 1)] = cvt4h(pk[j]);
        }
        #pragma unroll
        for (int nt = 0; nt < 8; nt++) {
            int qc = wn*64 + nt*8 + 2*t4;
            float a0 = scaleb[qc], a1 = scaleb[qc+1];
            #pragma unroll
            for (int mt = 0; mt < 3; mt++) {
                oat[mt][nt][0] *= a0; oat[mt][nt][1] *= a1;
                oat[mt][nt][2] *= a0; oat[mt][nt][3] *= a1;
            }
        }
        #pragma unroll
        for (int ks = 0; ks < 2; ks++) {
            int k0 = ks*8;
            uint32_t pf[4][4];
            #pragma unroll
            for (int ntp = 0; ntp < 4; ntp++)
                ldsm_x4(pf[ntp], sbase + (F_PS + (wn*64 + ntp*16 + lb_row)*20 + k0 + lb_kw)*4);
            #pragma unroll
            for (int mt = 0; mt < 3; mt++) {
                uint32_t a[4];
                ldsm_x4(a, sbase + (F_VS + buf*3840 + (wm*48 + mt*16 + la_row)*20 + k0 + la_kw)*4);
                #pragma unroll
                for (int nt = 0; nt < 8; nt++)
                    mma_f16(oat[mt][nt], a, pf[nt>>1][(nt&1)*2], pf[nt>>1][(nt&1)*2+1]);
            }
        }
        if (kt + 1 < NTILES) {
            uint32_t* Vn = Vsm + (buf^1)*3840;
            #pragma unroll
            for (int j = 0; j < 6; j++)
                *(uint2*)&Vn[cV[j]*20 + (kV[j] >> 1)] = cvt4h(pv[j]);
        }
        __syncthreads();
    }

    // epilogue: normalize, transpose via smem, scatter to g_otokT
    float* Ot = (float*)sm;
    #pragma unroll
    for (int nt = 0; nt < 8; nt++) {
        int qc = wn*64 + nt*8 + 2*t4;
        float li0 = 1.f / lb[qc], li1 = 1.f / lb[qc+1];
        #pragma unroll
        for (int mt = 0; mt < 3; mt++) {
            int cr = wm*48 + mt*16;
            Ot[qc*196 + cr+g]       = oat[mt][nt][0] * li0;
            Ot[(qc+1)*196 + cr+g]   = oat[mt][nt][1] * li1;
            Ot[qc*196 + cr+g+8]     = oat[mt][nt][2] * li0;
            Ot[(qc+1)*196 + cr+g+8] = oat[mt][nt][3] * li1;
        }
    }
    __syncthreads();
    #pragma unroll
    for (int j = 0; j < 24; j++) {
        int idx = tid + j*256;
        int r = idx/48, c4v = (idx%48)*4;
        int tok = g_keep[b*NKEEP + m0 + r];
        float4 v = *(float4*)&Ot[r*196 + c4v];
        *(float4*)&g_otokT[((size_t)b*NN + tok)*CC + c4v] = v;
    }
}

// ================= gather-transpose v1t[c][m] = vt[keep[m]][c] =================
__global__ void k_gT() {
    __shared__ float t[32][33];
    int b = blockIdx.z;
    int m0 = blockIdx.x * 32, c0 = blockIdx.y * 32;
    int tx = threadIdx.x, ty = threadIdx.y;
    #pragma unroll
    for (int j = ty; j < 32; j += 8) {
        int tok = g_keep[b*NKEEP + m0 + j];
        t[j][tx] = g_vt[((size_t)b*NN + tok)*CC + c0 + tx];
    }
    __syncthreads();
    #pragma unroll
    for (int j = ty; j < 32; j += 8)
        g_v1t[((size_t)b*CC + c0 + j)*NKEEP + m0 + tx] = t[tx][j];
}

// ================= front end (+ fused x transpose) =================
__global__ void k_front(const float* __restrict__ x,
    const float* __restrict__ in_w, const float* __restrict__ in_b,
    const float* __restrict__ ln_w, const float* __restrict__ ln_b,
    const float* __restrict__ ow1, const float* __restrict__ ob1,
    const float* __restrict__ ow2, const float* __restrict__ ob2,
    const float* __restrict__ mw1, const float* __restrict__ mb1,
    const float* __restrict__ mw2, const float* __restrict__ mb2)
{
    __shared__ float cond[CD][33];
    __shared__ float fb[C4][33];
    __shared__ float mu_s[32], rs_s[32];
    __shared__ float hb[C8][33];
    int b = blockIdx.y;
    int n0 = blockIdx.x * 32;
    int tid = threadIdx.x;

    for (int l = tid; l < CC*32; l += 256) {
        int c = l >> 5, px = l & 31;
        cond[c][px] = x[((b*CC + c) << 12) + n0 + px];
    }
    if (tid < 32) {
        int n = n0 + tid;
        int h = n >> 6, w = n & 63;
        cond[192][tid] = -1.0f + 2.0f * (float)w / 63.0f;
        cond[193][tid] = -1.0f + 2.0f * (float)h / 63.0f;
    }
    __syncthreads();

    for (int l = tid; l < 32*CC; l += 256) {
        int px = l / CC, c = l % CC;
        g_xt[((size_t)b*NN + n0 + px)*CC + c] = cond[c][px];
    }

    int px = tid & 31;
    for (int pass = 0; pass < 6; pass++) {
        int c = pass*8 + (tid >> 5);
        float acc = in_b[c];
        const float* wr = in_w + c*CD;
        #pragma unroll 2
        for (int k = 0; k < CD; k++) acc += wr[k] * cond[k][px];
        fb[c][px] = acc;
    }
    __syncthreads();

    if (tid < 32) {
        float s = 0.f, s2 = 0.f;
        for (int c = 0; c < C4; c++) { float v = fb[c][tid]; s += v; s2 += v*v; }
        float mu = s / (float)C4;
        float var = s2 / (float)C4 - mu*mu;
        mu_s[tid] = mu;
        rs_s[tid] = rsqrtf(var + 1e-6f);
    }
    __syncthreads();

    for (int l = tid; l < C4*32; l += 256) {
        int c = l >> 5, p = l & 31;
        float v = (fb[c][p] - mu_s[p]) * rs_s[p] * ln_w[c] + ln_b[c];
        v = v > 0.f ? v : 0.1f*v;
        fb[c][p] = v;
        g_f[(b*C4 + c)*NN + n0 + p] = v;
    }
    __syncthreads();

    for (int l = tid; l < C8*32; l += 256) {
        int j = l >> 5, p = l & 31;
        float acc = ob1[j];
        const float* wr = ow1 + j*C4;
        #pragma unroll 4
        for (int c = 0; c < C4; c++) acc += wr[c] * fb[c][p];
        hb[j][p] = acc > 0.f ? acc : 0.1f*acc;
    }
    __syncthreads();

    if (tid < 64) {
        int d = tid >> 5, p = tid & 31;
        float acc = ob2[d];
        const float* wr = ow2 + d*C8;
        #pragma unroll
        for (int j = 0; j < C8; j++) acc += wr[j] * hb[j][p];
        g_off[(b*2 + d)*NN + n0 + p] = tanhf(acc) * 8.0f;
    }
    if (tid >= 64 && tid < 96) {
        int p = tid - 64;
        float s = 0.f;
        for (int c = 0; c < C4; c++) s += fb[c][p];
        float t = s / (float)C4;
        float s1 = t * mw1[0] + mb1[0];
        s1 = s1 > 0.f ? s1 : 0.1f*s1;
        float l0 = s1 * mw2[0] + mb2[0];
        float l1 = s1 * mw2[1] + mb2[1];
        g_score[b*NN + n0 + p] = 1.0f / (1.0f + expf(l1 - l0));
    }
}

// ================= merged fmean + ca =================
__global__ void k_stats(const float* __restrict__ caw, const float* __restrict__ cab) {
    __shared__ float fm[C4];
    int b = blockIdx.x, tid = threadIdx.x;
    int w = tid >> 5, lane = tid & 31;
    for (int c = w; c < C4; c += 32) {
        const float* p = g_f + (b*C4 + c)*NN;
        float s = 0.f;
        for (int i = lane; i < NN; i += 32) s += p[i];
        #pragma unroll
        for (int o = 16; o; o >>= 1) s += __shfl_xor_sync(~0u, s, o);
        if (lane == 0) fm[c] = s / (float)NN;
    }
    __syncthreads();
    if (tid < CC) {
        float acc = cab[tid];
        #pragma unroll 4
        for (int c = 0; c < C4; c++) acc += caw[tid*C4 + c] * fm[c];
        g_ca[b*CC + tid] = 1.0f / (1.0f + __expf(-acc));
    }
}

// ================= sa: tiled 3x3 conv + sigmoid =================
__global__ void k_sa2(const float* __restrict__ saw, const float* __restrict__ sab) {
    __shared__ float wsh[C4*9];
    __shared__ float smf[6][64];
    int b = blockIdx.y, h0 = blockIdx.x*4;
    int tid = threadIdx.x;
    for (int l = tid; l < C4*9; l += 256) wsh[l] = saw[l];
    int lw = tid & 63, lh = tid >> 6;
    float acc = sab[0];
    const float* fb = g_f + b*C4*NN;
    for (int c = 0; c < C4; c++) {
        __syncthreads();
        for (int l = tid; l < 384; l += 256) {
            int r = l >> 6, ww = l & 63;
            int hh = h0 - 1 + r;
            smf[r][ww] = (hh >= 0 && hh < HH) ? fb[c*NN + hh*64 + ww] : 0.f;
        }
        __syncthreads();
        #pragma unroll
        for (int dh = 0; dh < 3; dh++) {
            float w0 = wsh[c*9+dh*3+0], w1 = wsh[c*9+dh*3+1], w2 = wsh[c*9+dh*3+2];
            const float* row = smf[lh + dh];
            float vm = (lw > 0)  ? row[lw-1] : 0.f;
            float vc = row[lw];
            float vp = (lw < 63) ? row[lw+1] : 0.f;
            acc += w0*vm + w1*vc + w2*vp;
        }
    }
    g_sa[b*NN + (h0+lh)*64 + lw] = 1.f/(1.f + __expf(-acc));
}

// ================= top-k by radix select =================
__device__ __forceinline__ unsigned int ford(float f) {
    unsigned int u = __float_as_uint(f);
    return (u & 0x80000000u) ? ~u : (u | 0x80000000u);
}
__global__ void __launch_bounds__(1024) k_topk() {
    __shared__ ull keys[NN];
    __shared__ int hist[256];
    __shared__ int scan_[256];
    __shared__ ull sel_prefix;
    __shared__ int sel_k;
    __shared__ int wsum[32];
    int b = blockIdx.x, tid = threadIdx.x;
    int lane = tid & 31, wid = tid >> 5;

    for (int l = tid; l < NN; l += 1024) {
        unsigned int o = ford(g_score[b*NN + l]) ^ 0xFFFFFFFFu;
        keys[l] = ((ull)o << 32) | (unsigned int)l;
    }
    if (tid == 0) { sel_prefix = 0; sel_k = NKEEP - 1; }
    __syncthreads();

    ull prefix = 0, mask = 0;
    for (int byte = 7; byte >= 0; byte--) {
        int sh = byte * 8;
        if (tid < 256) hist[tid] = 0;
        __syncthreads();
        for (int l = tid; l < NN; l += 1024) {
            ull k = keys[l];
            if ((k & mask) == prefix) atomicAdd(&hist[(int)((k >> sh) & 0xFF)], 1);
        }
        __syncthreads();
        if (tid < 256) scan_[tid] = hist[tid];
        __syncthreads();
        #pragma unroll
        for (int off = 1; off < 256; off <<= 1) {
            int v = 0;
            if (tid < 256 && tid >= off) v = scan_[tid - off];
            __syncthreads();
            if (tid < 256) scan_[tid] += v;
            __syncthreads();
        }
        int kcur = sel_k;
        __syncthreads();
        if (tid < 256) {
            int incl = scan_[tid], excl = incl - hist[tid];
            if (kcur >= excl && kcur < incl) {
                sel_prefix = prefix | ((ull)tid << sh);
                sel_k = kcur - excl;
            }
        }
        __syncthreads();
        prefix = sel_prefix;
        mask |= (0xFFull << sh);
        __syncthreads();
    }
    ull kstar = prefix;

    int base = tid * 4;
    int kept[4], c = 0;
    #pragma unroll
    for (int j = 0; j < 4; j++) {
        kept[j] = (keys[base + j] <= kstar) ? 1 : 0;
        c += kept[j];
    }
    int incl = c;
    #pragma unroll
    for (int o = 1; o < 32; o <<= 1) {
        int v = __shfl_up_sync(~0u, incl, o);
        if (lane >= o) incl += v;
    }
    if (lane == 31) wsum[wid] = incl;
    __syncthreads();
    if (wid == 0) {
        int v = (lane < 32) ? wsum[lane] : 0;
        #pragma unroll
        for (int o = 1; o < 32; o <<= 1) {
            int u = __shfl_up_sync(~0u, v, o);
            if (lane >= o) v += u;
        }
        wsum[lane] = v;
    }
    __syncthreads();
    int offset = (wid > 0 ? wsum[wid - 1] : 0) + incl - c;
    #pragma unroll
    for (int j = 0; j < 4; j++) {
        int tok = base + j;
        if (kept[j]) {
            g_keep[b*NKEEP + offset] = tok;
            g_pos[b*NN + tok] = offset;
            offset++;
        } else {
            g_pos[b*NN + tok] = -1;
        }
    }
}

// ================= token-major depthwise 3x3 + gelu*ca + residual (fused fill) =====
__global__ void __launch_bounds__(192) k_dwT(const float* __restrict__ csw, const float* __restrict__ csb) {
    extern __shared__ float sdw[];
    float* tile = sdw;            // [100][192]
    float* wsm = sdw + 100*192;   // [192*9]
    int b = blockIdx.y;
    int t = blockIdx.x;
    int th0 = (t >> 3) * 8, tw0 = (t & 7) * 8;
    int tid = threadIdx.x;
    for (int l = tid; l < 192*9; l += 192) wsm[l] = csw[l];
    const float* inb = g_otokT + (size_t)b*NN*CC;
    const float* vtb = g_vt + (size_t)b*NN*CC;
    for (int l = tid; l < 100*48; l += 192) {
        int pos = l / 48, c4v = (l % 48)*4;
        int hh = th0 - 1 + pos/10, ww = tw0 - 1 + pos%10;
        float4 v = make_float4(0.f, 0.f, 0.f, 0.f);
        if (hh >= 0 && hh < 64 && ww >= 0 && ww < 64) {
            int n = hh*64 + ww;
            if (g_pos[b*NN + n] >= 0) {
                v = *(const float4*)(inb + (size_t)n*CC + c4v);
            } else {
                v = *(const float4*)(vtb + (size_t)n*CC + c4v);
                float s = g_sa[b*NN + n];
                v.x *= s; v.y *= s; v.z *= s; v.w *= s;
            }
        }
        *(float4*)&tile[pos*192 + c4v] = v;
    }
    __syncthreads();

    int c4 = (tid % 48) * 4;
    int pxb = tid / 48;
    float wreg[9][4];
    #pragma unroll
    for (int tap = 0; tap < 9; tap++)
        #pragma unroll
        for (int e = 0; e < 4; e++)
            wreg[tap][e] = wsm[(c4+e)*9 + tap];
    float bv[4], cav[4];
    #pragma unroll
    for (int e = 0; e < 4; e++) { bv[e] = csb[c4+e]; cav[e] = g_ca[b*CC + c4 + e]; }

    float* outb = g_out2T + (size_t)b*NN*CC;
    for (int j = 0; j < 16; j++) {
        int px = pxb*16 + j;
        int lh = px >> 3, lw2 = px & 7;
        float acc[4] = {bv[0], bv[1], bv[2], bv[3]};
        #pragma unroll
        for (int dh = 0; dh < 3; dh++)
            #pragma unroll
            for (int dw_ = 0; dw_ < 3; dw_++) {
                int pos = (lh+dh)*10 + (lw2+dw_);
                float4 v = *(const float4*)&tile[pos*192 + c4];
                int tap = dh*3 + dw_;
                acc[0] += wreg[tap][0]*v.x; acc[1] += wreg[tap][1]*v.y;
                acc[2] += wreg[tap][2]*v.z; acc[3] += wreg[tap][3]*v.w;
            }
        float4 cen = *(const float4*)&tile[((lh+1)*10 + (lw2+1))*192 + c4];
        float* cenp = (float*)&cen;
        float4 o;
        float* op = (float*)&o;
        #pragma unroll
        for (int e = 0; e < 4; e++) {
            float a = acc[e];
            float x3 = a*a*a;
            float gg = 0.5f*a*(1.0f + tanhf(0.7978845608028654f*(a + 0.044715f*x3)));
            op[e] = gg * cav[e] + cenp[e];
        }
        int n = (th0+lh)*64 + (tw0+lw2);
        *(float4*)(outb + (size_t)n*CC + c4) = o;
    }
}

// ================= host =================
extern "C" void kernel_launch(void* const* d_in, const int* in_sizes, int n_in,
                              void* d_out, int out_size) {
    const float* x     = (const float*)d_in[0];
    const float* in_w  = (const float*)d_in[1];
    const float* in_b  = (const float*)d_in[2];
    const float* ln_w  = (const float*)d_in[3];
    const float* ln_b  = (const float*)d_in[4];
    const float* ow1   = (const float*)d_in[5];
    const float* ob1   = (const float*)d_in[6];
    const float* ow2   = (const float*)d_in[7];
    const float* ob2   = (const float*)d_in[8];
    const float* caw   = (const float*)d_in[9];
    const float* cab   = (const float*)d_in[10];
    const float* saw   = (const float*)d_in[11];
    const float* sab   = (const float*)d_in[12];
    const float* mw1   = (const float*)d_in[13];
    const float* mb1   = (const float*)d_in[14];
    const float* mw2   = (const float*)d_in[15];
    const float* mb2   = (const float*)d_in[16];
    const float* v_w   = (const float*)d_in[17];
    const float* v_b   = (const float*)d_in[18];
    const float* q_w   = (const float*)d_in[19];
    const float* q_b   = (const float*)d_in[20];
    const float* k_w   = (const float*)d_in[21];
    const float* k_b   = (const float*)d_in[22];
    const float* cs_w  = (const float*)d_in[23];
    const float* cs_b  = (const float*)d_in[24];
    const float* out_w = (const float*)d_in[25];
    const float* out_b = (const float*)d_in[26];
    float* out = (float*)d_out;

    float *p_xt, *p_vt, *p_q1, *p_k1, *p_out2T;
    int *p_keep;
    cudaGetSymbolAddress((void**)&p_xt, g_xt);
    cudaGetSymbolAddress((void**)&p_vt, g_vt);
    cudaGetSymbolAddress((void**)&p_q1, g_q1);
    cudaGetSymbolAddress((void**)&p_k1, g_k1);
    cudaGetSymbolAddress((void**)&p_out2T, g_out2T);
    cudaGetSymbolAddress((void**)&p_keep, g_keep);

    const int SMEM_G = 8448 * 4;
    cudaFuncSetAttribute((k_gemm<0,false>), cudaFuncAttributeMaxDynamicSharedMemorySize, SMEM_G);
    cudaFuncSetAttribute((k_gemm<1,false>), cudaFuncAttributeMaxDynamicSharedMemorySize, SMEM_G);
    cudaFuncSetAttribute((k_gemm<2,false>), cudaFuncAttributeMaxDynamicSharedMemorySize, SMEM_G);
    cudaFuncSetAttribute((k_gemm<0,true>),  cudaFuncAttributeMaxDynamicSharedMemorySize, SMEM_G);
    const int SMEM_F = F_TOT * 4;
    cudaFuncSetAttribute(k_flash, cudaFuncAttributeMaxDynamicSharedMemorySize, SMEM_F);
    const int SMEM_DW = (100*192 + 192*9) * 4;
    cudaFuncSetAttribute(k_dwT, cudaFuncAttributeMaxDynamicSharedMemorySize, SMEM_DW);

    dim3 tb(32, 8);
    k_front<<<dim3(NN/32, BB), 256>>>(x, in_w, in_b, ln_w, ln_b,
                                      ow1, ob1, ow2, ob2, mw1, mb1, mw2, mb2);
    k_stats<<<BB, 1024>>>(caw, cab);
    k_sa2<<<dim3(HH/4, BB), 256>>>(saw, sab);
    k_topk<<<BB, 1024>>>();

    float scale = rsqrtf((float)CC);
    k_gemm<0,false><<<dim3(NN/128, 3, BB), 256, SMEM_G>>>(
        p_xt, (size_t)NN*CC, v_w, 0, v_b, nullptr, p_vt, (size_t)NN*CC, CC, CC, 1.0f);
    k_gemm<1,false><<<dim3(NKEEP/128, 3, BB), 256, SMEM_G>>>(
        p_xt, (size_t)NN*CC, q_w, 0, q_b, p_keep, p_q1, (size_t)NKEEP*CC, CC, CC, scale);
    k_gemm<2,false><<<dim3(NKEEP/128, 3, BB), 256, SMEM_G>>>(
        p_xt, (size_t)NN*CC, k_w, 0, k_b, p_keep, p_k1, (size_t)NKEEP*CC, CC, CC, 1.0f);
    k_gT<<<dim3(NKEEP/32, CC/32, BB), tb>>>();
    k_flash<<<dim3(NKEEP/128, BB), 256, SMEM_F>>>();
    k_dwT<<<dim3(64, BB), 192, SMEM_DW>>>(cs_w, cs_b);
    k_gemm<0,true><<<dim3(NN/128, 3, BB), 256, SMEM_G>>>(
        p_out2T, (size_t)NN*CC, out_w, 0, out_b, nullptr, out, 0, CC, CC, 1.0f);
}